// round 3
// baseline (speedup 1.0000x reference)
#include <cuda_runtime.h>
#include <math.h>

// ---------------- problem constants ----------------
namespace {
constexpr int D_   = 550;
constexpr int LDD  = 552;    // padded row stride (float4-aligned)
constexpr int F_   = 275;
constexpr int LDF  = 276;    // padded ident stride
constexpr int B_   = 4096;   // N*T = 8*512
constexpr int H_   = 128;
constexpr int OUT_ = 6325;   // F_*(3*8-1)
}

// ---------------- scratch (device globals; no allocs allowed) ----------------
__device__ float g_z  [B_*LDD];   // zero-init => pad cols stay 0
__device__ float g_zn [B_*LDD];
__device__ float g_LT [LDD*LDD];
__device__ float g_UpT[LDD*LDD];
__device__ float g_ApT[LDD*LDD];
__device__ float g_id [B_*LDF];
__device__ float g_t  [B_*H_];
__device__ float g_r  [B_*H_];
__device__ float g_lq [B_];
__device__ float g_slog[3];
__device__ float g_kn [F_*27];    // per-f ident knots: cw[9], ch[9], dd[9]

// ---------------- helpers ----------------
__device__ __forceinline__ float softplus_acc(float x) {   // accurate (precompute only)
    return (x > 20.f) ? x : log1pf(__expf(x));
}
__device__ __forceinline__ float softplus_fast(float x) {
    return (x > 15.f) ? x : __logf(1.f + __expf(x));
}

__device__ __forceinline__ float block_reduce_sum(float v) {
    __shared__ float sred[32];
    int tid = threadIdx.x;
    #pragma unroll
    for (int o = 16; o > 0; o >>= 1) v += __shfl_down_sync(0xffffffffu, v, o);
    if ((tid & 31) == 0) sred[tid >> 5] = v;
    __syncthreads();
    if (tid < 32) {
        int nw = (blockDim.x + 31) >> 5;
        v = (tid < nw) ? sred[tid] : 0.f;
        #pragma unroll
        for (int o = 16; o > 0; o >>= 1) v += __shfl_down_sync(0xffffffffu, v, o);
    }
    return v;  // valid in thread 0
}

// Fast inverse RQS, params in registers (conditional path).
__device__ __forceinline__ void rqs_fast(float x, const float* uw, const float* uh,
                                         const float* ud7, float& out, float& ld)
{
    const float TB = 3.f;
    bool inside = (x >= -TB) && (x <= TB);
    float xi = fminf(fmaxf(x, -TB), TB);

    float cw[9], ch[9];
    {
        float m = uw[0];
        #pragma unroll
        for (int k = 1; k < 8; k++) m = fmaxf(m, uw[k]);
        float e[8]; float s = 0.f;
        #pragma unroll
        for (int k = 0; k < 8; k++) { e[k] = __expf(uw[k] - m); s += e[k]; }
        float inv = __fdividef(1.f, s);
        float cum = 0.f;
        cw[0] = -TB;
        #pragma unroll
        for (int k = 0; k < 7; k++) { cum += 0.001f + 0.992f * e[k] * inv; cw[k+1] = 6.f * cum - 3.f; }
        cw[8] = TB;
    }
    {
        float m = uh[0];
        #pragma unroll
        for (int k = 1; k < 8; k++) m = fmaxf(m, uh[k]);
        float e[8]; float s = 0.f;
        #pragma unroll
        for (int k = 0; k < 8; k++) { e[k] = __expf(uh[k] - m); s += e[k]; }
        float inv = __fdividef(1.f, s);
        float cum = 0.f;
        ch[0] = -TB;
        #pragma unroll
        for (int k = 0; k < 7; k++) { cum += 0.001f + 0.992f * e[k] * inv; ch[k+1] = 6.f * cum - 3.f; }
        ch[8] = TB;
    }

    // bin search on height knots
    int cnt = 0;
    #pragma unroll
    for (int k = 0; k < 9; k++) {
        float lo = ch[k] + (k == 8 ? 1e-6f : 0.f);
        cnt += (xi >= lo) ? 1 : 0;
    }
    int idx = cnt - 1; idx = idx < 0 ? 0 : (idx > 7 ? 7 : idx);

    float icw = 0.f, iw = 1.f, ich = 0.f, ih = 1.f;
    float u0 = 0.f, u1 = 0.f;
    #pragma unroll
    for (int k = 0; k < 8; k++) {
        if (k == idx) {
            icw = cw[k]; iw = cw[k+1] - cw[k];
            ich = ch[k]; ih = ch[k+1] - ch[k];
        }
    }
    #pragma unroll
    for (int k = 0; k < 7; k++) {
        if (k == idx - 1) u0 = ud7[k];
        if (k == idx)     u1 = ud7[k];
    }
    // boundary derivative is exactly MIND + softplus(DCONST) = 1.0
    float d0 = (idx == 0) ? 1.f : 0.001f + softplus_fast(u0);
    float d1 = (idx == 7) ? 1.f : 0.001f + softplus_fast(u1);

    float delta = __fdividef(ih, iw);
    float t  = xi - ich;
    float s2 = d0 + d1 - 2.f * delta;
    float aa = t * s2 + ih * (delta - d0);
    float bb = ih * d0 - t * s2;
    float cc = -delta * t;
    float disc = bb * bb - 4.f * aa * cc;
    float sq = disc * __frsqrt_rn(fmaxf(disc, 1e-37f));
    float root = __fdividef(2.f * cc, -bb - sq);
    float o = root * iw + icw;
    float tm = root * (1.f - root);
    float den = delta + s2 * tm;
    float omr = 1.f - root;
    float dnum = delta * delta * (d1 * root * root + 2.f * delta * tm + d0 * omr * omr);
    float l = -__logf(__fdividef(dnum, den * den));

    out = inside ? o : x;
    ld  = inside ? l : 0.f;
}

// ---------------- small kernels ----------------
__global__ void zero_kernel(float* p, int n) {
    int i = blockIdx.x * blockDim.x + threadIdx.x;
    if (i < n) p[i] = 0.f;
}

__global__ void copy_pad_kernel(const float* __restrict__ x, float* __restrict__ z) {
    int i = blockIdx.x * blockDim.x + threadIdx.x;
    if (i >= B_ * D_) return;
    int b = i / D_, d = i % D_;
    z[b * LDD + d] = x[i];
}

__global__ void sumlog_kernel(const float* __restrict__ lu_ud, float* __restrict__ out) {
    int i = blockIdx.x;  // layer
    float s = 0.f;
    for (int d = threadIdx.x; d < D_; d += blockDim.x)
        s += __logf(softplus_acc(lu_ud[i * D_ + d]) + 0.001f);
    s = block_reduce_sum(s);
    if (threadIdx.x == 0) out[i] = s;
}

// Per-f knots for the unconditional (ident) spline: cw[9], ch[9], dd[9]
__global__ void ident_knots_kernel(const float* __restrict__ uw_u,
                                   const float* __restrict__ uh_u,
                                   const float* __restrict__ ud_u,
                                   float* __restrict__ kn)
{
    int f = blockIdx.x * blockDim.x + threadIdx.x;
    if (f >= F_) return;
    const float TB = 3.f;
    float* o = kn + f * 27;
    // widths
    {
        const float* u = uw_u + f * 8;
        float m = u[0];
        #pragma unroll
        for (int k = 1; k < 8; k++) m = fmaxf(m, u[k]);
        float e[8]; float s = 0.f;
        #pragma unroll
        for (int k = 0; k < 8; k++) { e[k] = __expf(u[k] - m); s += e[k]; }
        float inv = 1.f / s;
        float cum = 0.f;
        o[0] = -TB;
        #pragma unroll
        for (int k = 0; k < 7; k++) { cum += 0.001f + 0.992f * e[k] * inv; o[k+1] = 6.f * cum - 3.f; }
        o[8] = TB;
    }
    // heights
    {
        const float* u = uh_u + f * 8;
        float m = u[0];
        #pragma unroll
        for (int k = 1; k < 8; k++) m = fmaxf(m, u[k]);
        float e[8]; float s = 0.f;
        #pragma unroll
        for (int k = 0; k < 8; k++) { e[k] = __expf(u[k] - m); s += e[k]; }
        float inv = 1.f / s;
        float cum = 0.f;
        o[9] = -TB;
        #pragma unroll
        for (int k = 0; k < 7; k++) { cum += 0.001f + 0.992f * e[k] * inv; o[10+k] = 6.f * cum - 3.f; }
        o[17] = TB;
    }
    // derivatives (boundaries exactly 1.0)
    o[18] = 1.f; o[26] = 1.f;
    #pragma unroll
    for (int k = 0; k < 7; k++) o[19 + k] = 0.001f + softplus_acc(ud_u[f * 7 + k]);
}

// Table-driven ident spline eval. Block = 32 f x 8 b (256 thr).
__global__ void __launch_bounds__(256)
ident_eval_kernel(const float* __restrict__ zn, const float* __restrict__ kn,
                  float* __restrict__ ident, float* __restrict__ zout,
                  float* __restrict__ lq)
{
    __shared__ float sk[32][29];
    int tid = threadIdx.x;
    int f_local = tid & 31;
    int b_local = tid >> 5;
    int f0 = blockIdx.x * 32;
    int b  = blockIdx.y * 8 + b_local;

    for (int j = tid; j < 32 * 27; j += 256) {
        int fl = j / 27, e = j % 27;
        int f = f0 + fl;
        sk[fl][e] = (f < F_) ? kn[f * 27 + e] : 0.f;
    }
    __syncthreads();

    int f = f0 + f_local;
    float ldv = 0.f;
    if (f < F_) {
        const float TB = 3.f;
        const float* K = sk[f_local];
        float x = zn[b * LDD + 2 * f];
        bool inside = (x >= -TB) && (x <= TB);
        float xi = fminf(fmaxf(x, -TB), TB);

        int cnt = 0;
        #pragma unroll
        for (int k = 0; k < 9; k++) {
            float lo = K[9 + k] + (k == 8 ? 1e-6f : 0.f);
            cnt += (xi >= lo) ? 1 : 0;
        }
        int idx = cnt - 1; idx = idx < 0 ? 0 : (idx > 7 ? 7 : idx);

        float icw = K[idx],     iw = K[idx + 1] - icw;
        float ich = K[9 + idx], ih = K[10 + idx] - ich;
        float d0  = K[18 + idx], d1 = K[19 + idx];

        float delta = __fdividef(ih, iw);
        float t  = xi - ich;
        float s2 = d0 + d1 - 2.f * delta;
        float aa = t * s2 + ih * (delta - d0);
        float bb = ih * d0 - t * s2;
        float cc = -delta * t;
        float disc = bb * bb - 4.f * aa * cc;
        float sq = disc * __frsqrt_rn(fmaxf(disc, 1e-37f));
        float root = __fdividef(2.f * cc, -bb - sq);
        float o = root * iw + icw;
        float tm = root * (1.f - root);
        float den = delta + s2 * tm;
        float omr = 1.f - root;
        float dnum = delta * delta * (d1 * root * root + 2.f * delta * tm + d0 * omr * omr);
        float l = -__logf(__fdividef(dnum, den * den));

        float ov = inside ? o : x;
        ldv = inside ? l : 0.f;
        ident[b * LDF + f] = ov;
        zout[b * LDD + 2 * f] = ov;
    }
    // full-warp reduce (all 32 lanes share b)
    #pragma unroll
    for (int o = 16; o > 0; o >>= 1) ldv += __shfl_xor_sync(0xffffffffu, ldv, o);
    if (f_local == 0) atomicAdd(&lq[b], ldv);
}

// Materialize LT[m,d] = L[d,m] (unit diag) and UpT[perm[k], m] = Udense[m,k].
__global__ void build_lt_upt_kernel(const float* __restrict__ lower,
                                    const float* __restrict__ upper,
                                    const float* __restrict__ lu_ud,
                                    const int* __restrict__ perm,
                                    float* __restrict__ LT, float* __restrict__ UpT)
{
    int c = blockIdx.x * blockDim.x + threadIdx.x;
    int rr = blockIdx.y;
    if (c >= D_) return;
    if (blockIdx.z == 0) {
        int m = rr, d = c;
        float v = (m < d) ? lower[d * D_ + m] : ((m == d) ? 1.f : 0.f);
        LT[m * LDD + d] = v;
    } else {
        int k = rr, m = c;
        float v;
        if (m < k)       v = upper[m * D_ + k];
        else if (m == k) v = softplus_acc(lu_ud[k]) + 0.001f;
        else             v = 0.f;
        UpT[perm[k] * LDD + m] = v;
    }
}

// ---------------- fast SGEMM: C = act(A) @ B + bias (+Cadd) ----------------
// A: [M x lda] row-major; B: [K x ldb] row-major (output-dim contiguous).
template<int BM, int BN, int TM, int TN, bool HASB, bool RELUA, bool ADDC>
__global__ void __launch_bounds__(256)
sgemm_tn(const float* __restrict__ A, const float* __restrict__ Bm,
         const float* __restrict__ bias, const float* __restrict__ Cadd,
         float* __restrict__ C, int M, int N, int K, int lda, int ldb, int ldc)
{
    constexpr int BK = 16;
    constexpr int TX = BN / TN, TY = BM / TM;
    static_assert(TX * TY == 256, "thread tiling");
    __shared__ __align__(16) float As[BK][BM];
    __shared__ __align__(16) float Bs[BK][BN];
    int tid = threadIdx.x;
    int tx = tid % TX, ty = tid / TX;
    int m0 = blockIdx.y * BM, n0 = blockIdx.x * BN;

    float acc[TM][TN];
    #pragma unroll
    for (int i = 0; i < TM; i++)
        #pragma unroll
        for (int j = 0; j < TN; j++) acc[i][j] = 0.f;

    for (int k0 = 0; k0 < K; k0 += BK) {
        #pragma unroll
        for (int idx = tid; idx < BM * 4; idx += 256) {
            int m = idx >> 2, k4 = (idx & 3) << 2;
            int gm = m0 + m, gk = k0 + k4;
            float4 v = make_float4(0.f, 0.f, 0.f, 0.f);
            if (gm < M && gk < K)
                v = *reinterpret_cast<const float4*>(&A[gm * lda + gk]);
            if (RELUA) {
                v.x = fmaxf(v.x, 0.f); v.y = fmaxf(v.y, 0.f);
                v.z = fmaxf(v.z, 0.f); v.w = fmaxf(v.w, 0.f);
            }
            As[k4 + 0][m] = v.x; As[k4 + 1][m] = v.y;
            As[k4 + 2][m] = v.z; As[k4 + 3][m] = v.w;
        }
        #pragma unroll
        for (int idx = tid; idx < BN * 4; idx += 256) {
            int k = idx / (BN / 4), n4 = (idx % (BN / 4)) << 2;
            int gk = k0 + k, gn = n0 + n4;
            float4 v = make_float4(0.f, 0.f, 0.f, 0.f);
            if (gk < K && gn < N)
                v = *reinterpret_cast<const float4*>(&Bm[gk * ldb + gn]);
            *reinterpret_cast<float4*>(&Bs[k][n4]) = v;
        }
        __syncthreads();
        #pragma unroll
        for (int kk = 0; kk < BK; kk++) {
            float a[TM], b[TN];
            #pragma unroll
            for (int i = 0; i < TM / 4; i++)
                *reinterpret_cast<float4*>(&a[4 * i]) =
                    *reinterpret_cast<const float4*>(&As[kk][ty * TM + 4 * i]);
            #pragma unroll
            for (int j = 0; j < TN / 4; j++)
                *reinterpret_cast<float4*>(&b[4 * j]) =
                    *reinterpret_cast<const float4*>(&Bs[kk][tx * TN + 4 * j]);
            #pragma unroll
            for (int i = 0; i < TM; i++)
                #pragma unroll
                for (int j = 0; j < TN; j++)
                    acc[i][j] = fmaf(a[i], b[j], acc[i][j]);
        }
        __syncthreads();
    }
    #pragma unroll
    for (int i = 0; i < TM; i++) {
        int gm = m0 + ty * TM + i;
        if (gm < M) {
            #pragma unroll
            for (int j = 0; j < TN; j++) {
                int gn = n0 + tx * TN + j;
                if (gn < N) {
                    float v = acc[i][j] + (HASB ? bias[gn] : 0.f);
                    if (ADDC) v += Cadd[gm * ldc + gn];
                    C[gm * ldc + gn] = v;
                }
            }
        }
    }
}

// Fused: p[b,f,:] = t[b,:] @ Wo[:, f*23:(f+1)*23] + bo, then conditional RQS
// inverse on trans = zn[:, 2f+1].
__global__ void __launch_bounds__(128)
wo_spline_kernel(const float* __restrict__ tmat, const float* __restrict__ Wo,
                 const float* __restrict__ bo, const float* __restrict__ zn,
                 float* __restrict__ zout, float* __restrict__ lq)
{
    constexpr int BTB = 32, BTF = 8, KC = 16;
    __shared__ float ts[BTB][129];
    __shared__ float wos[KC][BTF * 28];
    __shared__ float bos[BTF * 24];

    int tid = threadIdx.x;
    int f_local = tid & 7;
    int b_local = tid >> 3;               // 0..15
    int b0 = blockIdx.y * BTB;
    int f0 = blockIdx.x * BTF;
    int f  = f0 + f_local;

    for (int idx = tid; idx < BTB * 128; idx += 128) {
        int r = idx >> 7, c = idx & 127;
        ts[r][c] = tmat[(b0 + r) * H_ + c];
    }
    for (int idx = tid; idx < BTF * 24; idx += 128) {
        int ff = idx / 24, oo = idx % 24;
        int col = (f0 + ff) * 23 + oo;
        bos[idx] = (oo < 23 && col < OUT_) ? bo[col] : 0.f;
    }

    float acc0[24], acc1[24];
    #pragma unroll
    for (int o = 0; o < 24; o++) { acc0[o] = 0.f; acc1[o] = 0.f; }

    for (int kc = 0; kc < H_; kc += KC) {
        __syncthreads();
        for (int idx = tid; idx < KC * BTF * 23; idx += 128) {
            int kk = idx / (BTF * 23), rem = idx % (BTF * 23);
            int ff = rem / 23, oo = rem % 23;
            int col = (f0 + ff) * 23 + oo;
            wos[kk][ff * 28 + oo] = (col < OUT_) ? Wo[(kc + kk) * OUT_ + col] : 0.f;
        }
        for (int idx = tid; idx < KC * BTF; idx += 128) {
            int kk = idx / BTF, ff = idx % BTF;
            wos[kk][ff * 28 + 23] = 0.f;
        }
        __syncthreads();
        #pragma unroll
        for (int kk = 0; kk < KC; kk++) {
            float tv0 = ts[b_local][kc + kk];
            float tv1 = ts[b_local + 16][kc + kk];
            const float4* wp = reinterpret_cast<const float4*>(&wos[kk][f_local * 28]);
            #pragma unroll
            for (int q = 0; q < 6; q++) {
                float4 w4 = wp[q];
                acc0[q*4+0] += tv0 * w4.x; acc0[q*4+1] += tv0 * w4.y;
                acc0[q*4+2] += tv0 * w4.z; acc0[q*4+3] += tv0 * w4.w;
                acc1[q*4+0] += tv1 * w4.x; acc1[q*4+1] += tv1 * w4.y;
                acc1[q*4+2] += tv1 * w4.z; acc1[q*4+3] += tv1 * w4.w;
            }
        }
    }

    const float scale = 0.08838834764831845f;  // 1/sqrt(128)
    float ld0 = 0.f, ld1 = 0.f;

    if (f < F_) {
        {   // row 0
            float uw[8], uh[8], ud7[7];
            #pragma unroll
            for (int o = 0; o < 8; o++) {
                uw[o] = (acc0[o]     + bos[f_local * 24 + o])     * scale;
                uh[o] = (acc0[8 + o] + bos[f_local * 24 + 8 + o]) * scale;
            }
            #pragma unroll
            for (int o = 0; o < 7; o++) ud7[o] = acc0[16 + o] + bos[f_local * 24 + 16 + o];
            int b = b0 + b_local;
            float x = zn[b * LDD + 2 * f + 1];
            float o, l;
            rqs_fast(x, uw, uh, ud7, o, l);
            zout[b * LDD + 2 * f + 1] = o;
            ld0 = l;
        }
        {   // row 1
            float uw[8], uh[8], ud7[7];
            #pragma unroll
            for (int o = 0; o < 8; o++) {
                uw[o] = (acc1[o]     + bos[f_local * 24 + o])     * scale;
                uh[o] = (acc1[8 + o] + bos[f_local * 24 + 8 + o]) * scale;
            }
            #pragma unroll
            for (int o = 0; o < 7; o++) ud7[o] = acc1[16 + o] + bos[f_local * 24 + 16 + o];
            int b = b0 + b_local + 16;
            float x = zn[b * LDD + 2 * f + 1];
            float o, l;
            rqs_fast(x, uw, uh, ud7, o, l);
            zout[b * LDD + 2 * f + 1] = o;
            ld1 = l;
        }
    }
    // reduce within 8-lane groups (lanes sharing the same b)
    #pragma unroll
    for (int o = 4; o > 0; o >>= 1) {
        ld0 += __shfl_xor_sync(0xffffffffu, ld0, o);
        ld1 += __shfl_xor_sync(0xffffffffu, ld1, o);
    }
    if (f_local == 0) {
        atomicAdd(&lq[b0 + b_local], ld0);
        atomicAdd(&lq[b0 + b_local + 16], ld1);
    }
}

__global__ void final_kernel(const float* __restrict__ z, const float* __restrict__ loc,
                             const float* __restrict__ lsc, const float* __restrict__ lq,
                             const float* __restrict__ slog, float* __restrict__ out)
{
    int b = blockIdx.x;
    float s = 0.f;
    for (int d = threadIdx.x; d < D_; d += blockDim.x) {
        float inv = __expf(-lsc[d]);
        float u = (z[b * LDD + d] - loc[d]) * inv;
        s += lsc[d] + 0.5f * u * u;
    }
    s = block_reduce_sum(s);
    if (threadIdx.x == 0) {
        const float c = 0.5f * 550.f * 1.8378770664093453f;
        out[b] = lq[b] + slog[0] + slog[1] + slog[2] - c - s;
    }
}

// ---------------- launch ----------------
extern "C" void kernel_launch(void* const* d_in, const int* in_sizes, int n_in,
                              void* d_out, int out_size)
{
    (void)in_sizes; (void)n_in; (void)out_size;
    const float* x      = (const float*)d_in[0];
    const float* loc    = (const float*)d_in[1];
    const float* lsc    = (const float*)d_in[2];
    const float* Wi     = (const float*)d_in[3];
    const float* bi     = (const float*)d_in[4];
    const float* Wb     = (const float*)d_in[5];
    const float* bb     = (const float*)d_in[6];
    const float* Wo     = (const float*)d_in[7];
    const float* bo     = (const float*)d_in[8];
    const float* uw_u   = (const float*)d_in[9];
    const float* uh_u   = (const float*)d_in[10];
    const float* ud_u   = (const float*)d_in[11];
    const float* lower  = (const float*)d_in[12];
    const float* upper  = (const float*)d_in[13];
    const float* lu_ud  = (const float*)d_in[14];
    const float* lu_b   = (const float*)d_in[15];
    const int*   perms  = (const int*)d_in[16];
    float* outp = (float*)d_out;

    float *z, *zn, *LT, *UpT, *ApT, *ident, *t, *r, *lq, *slog, *kn;
    cudaGetSymbolAddress((void**)&z,     g_z);
    cudaGetSymbolAddress((void**)&zn,    g_zn);
    cudaGetSymbolAddress((void**)&LT,    g_LT);
    cudaGetSymbolAddress((void**)&UpT,   g_UpT);
    cudaGetSymbolAddress((void**)&ApT,   g_ApT);
    cudaGetSymbolAddress((void**)&ident, g_id);
    cudaGetSymbolAddress((void**)&t,     g_t);
    cudaGetSymbolAddress((void**)&r,     g_r);
    cudaGetSymbolAddress((void**)&lq,    g_lq);
    cudaGetSymbolAddress((void**)&slog,  g_slog);
    cudaGetSymbolAddress((void**)&kn,    g_kn);

    zero_kernel<<<(B_ + 255) / 256, 256>>>(lq, B_);
    sumlog_kernel<<<3, 256>>>(lu_ud, slog);
    copy_pad_kernel<<<(B_ * D_ + 255) / 256, 256>>>(x, z);

    for (int i = 2; i >= 0; i--) {
        build_lt_upt_kernel<<<dim3((D_ + 255) / 256, D_, 2), 256>>>(
            lower + i * D_ * D_, upper + i * D_ * D_,
            lu_ud + i * D_, perms + i * D_, LT, UpT);
        ident_knots_kernel<<<(F_ + 255) / 256, 256>>>(
            uw_u + i * F_ * 8, uh_u + i * F_ * 8, ud_u + i * F_ * 7, kn);

        sgemm_tn<64, 64, 4, 4, false, false, false>
            <<<dim3((D_ + 63) / 64, (D_ + 63) / 64), 256>>>(
                UpT, LT, nullptr, nullptr, ApT, D_, D_, D_, LDD, LDD, LDD);

        // zn = z @ ApT + lu_b
        sgemm_tn<128, 128, 8, 8, true, false, false>
            <<<dim3((D_ + 127) / 128, B_ / 128), 256>>>(
                z, ApT, lu_b + i * D_, nullptr, zn, B_, D_, D_, LDD, LDD, LDD);

        ident_eval_kernel<<<dim3((F_ + 31) / 32, B_ / 8), 256>>>(
            zn, kn, ident, z, lq);

        // ResNet conditioner (vectorized SGEMMs)
        sgemm_tn<64, 64, 4, 4, true, false, false>
            <<<dim3(2, B_ / 64), 256>>>(ident, Wi + i * F_ * H_, bi + i * H_, nullptr,
                                        t, B_, H_, F_, LDF, H_, H_);
        sgemm_tn<64, 64, 4, 4, true, true, false>
            <<<dim3(2, B_ / 64), 256>>>(t, Wb + (i * 4 + 0) * H_ * H_, bb + (i * 4 + 0) * H_,
                                        nullptr, r, B_, H_, H_, H_, H_, H_);
        sgemm_tn<64, 64, 4, 4, true, true, true>
            <<<dim3(2, B_ / 64), 256>>>(r, Wb + (i * 4 + 1) * H_ * H_, bb + (i * 4 + 1) * H_,
                                        t, t, B_, H_, H_, H_, H_, H_);
        sgemm_tn<64, 64, 4, 4, true, true, false>
            <<<dim3(2, B_ / 64), 256>>>(t, Wb + (i * 4 + 2) * H_ * H_, bb + (i * 4 + 2) * H_,
                                        nullptr, r, B_, H_, H_, H_, H_, H_);
        sgemm_tn<64, 64, 4, 4, true, true, true>
            <<<dim3(2, B_ / 64), 256>>>(r, Wb + (i * 4 + 3) * H_ * H_, bb + (i * 4 + 3) * H_,
                                        t, t, B_, H_, H_, H_, H_, H_);

        wo_spline_kernel<<<dim3((F_ + 7) / 8, B_ / 32), 128>>>(
            t, Wo + i * H_ * OUT_, bo + i * OUT_, zn, z, lq);
    }

    final_kernel<<<B_, 256>>>(z, loc, lsc, lq, slog, outp);
}

// round 4
// speedup vs baseline: 1.5620x; 1.5620x over previous
#include <cuda_runtime.h>
#include <math.h>

// ---------------- problem constants ----------------
namespace {
constexpr int D_   = 550;
constexpr int LDD  = 552;    // padded row stride (float4-aligned)
constexpr int F_   = 275;
constexpr int LDF  = 276;    // padded ident stride
constexpr int B_   = 4096;   // N*T = 8*512
constexpr int H_   = 128;
constexpr int OUT_ = 6325;   // F_*(3*8-1)
}

// ---------------- scratch (device globals; no allocs allowed) ----------------
__device__ float g_z  [B_*LDD];   // zero-init => pad cols stay 0
__device__ float g_zn [B_*LDD];
__device__ float g_LT [LDD*LDD];
__device__ float g_UpT[LDD*LDD];
__device__ float g_ApT[LDD*LDD];
__device__ float g_id [B_*LDF];
__device__ float g_t  [B_*H_];
__device__ float g_r  [B_*H_];
__device__ float g_lq [B_];
__device__ float g_slog[3];
__device__ float g_kn [F_*27];    // per-f ident knots: cw[9], ch[9], dd[9]

// ---------------- helpers ----------------
__device__ __forceinline__ float softplus_acc(float x) {   // accurate (precompute only)
    return (x > 20.f) ? x : log1pf(__expf(x));
}
__device__ __forceinline__ float softplus_fast(float x) {
    return (x > 15.f) ? x : __logf(1.f + __expf(x));
}

__device__ __forceinline__ float block_reduce_sum(float v) {
    __shared__ float sred[32];
    int tid = threadIdx.x;
    #pragma unroll
    for (int o = 16; o > 0; o >>= 1) v += __shfl_down_sync(0xffffffffu, v, o);
    if ((tid & 31) == 0) sred[tid >> 5] = v;
    __syncthreads();
    if (tid < 32) {
        int nw = (blockDim.x + 31) >> 5;
        v = (tid < nw) ? sred[tid] : 0.f;
        #pragma unroll
        for (int o = 16; o > 0; o >>= 1) v += __shfl_down_sync(0xffffffffu, v, o);
    }
    return v;  // valid in thread 0
}

// Fast inverse RQS, params in registers (conditional path).
__device__ __forceinline__ void rqs_fast(float x, const float* uw, const float* uh,
                                         const float* ud7, float& out, float& ld)
{
    const float TB = 3.f;
    bool inside = (x >= -TB) && (x <= TB);
    float xi = fminf(fmaxf(x, -TB), TB);

    float cw[9], ch[9];
    {
        float m = uw[0];
        #pragma unroll
        for (int k = 1; k < 8; k++) m = fmaxf(m, uw[k]);
        float e[8]; float s = 0.f;
        #pragma unroll
        for (int k = 0; k < 8; k++) { e[k] = __expf(uw[k] - m); s += e[k]; }
        float inv = __fdividef(1.f, s);
        float cum = 0.f;
        cw[0] = -TB;
        #pragma unroll
        for (int k = 0; k < 7; k++) { cum += 0.001f + 0.992f * e[k] * inv; cw[k+1] = 6.f * cum - 3.f; }
        cw[8] = TB;
    }
    {
        float m = uh[0];
        #pragma unroll
        for (int k = 1; k < 8; k++) m = fmaxf(m, uh[k]);
        float e[8]; float s = 0.f;
        #pragma unroll
        for (int k = 0; k < 8; k++) { e[k] = __expf(uh[k] - m); s += e[k]; }
        float inv = __fdividef(1.f, s);
        float cum = 0.f;
        ch[0] = -TB;
        #pragma unroll
        for (int k = 0; k < 7; k++) { cum += 0.001f + 0.992f * e[k] * inv; ch[k+1] = 6.f * cum - 3.f; }
        ch[8] = TB;
    }

    // bin search on height knots
    int cnt = 0;
    #pragma unroll
    for (int k = 0; k < 9; k++) {
        float lo = ch[k] + (k == 8 ? 1e-6f : 0.f);
        cnt += (xi >= lo) ? 1 : 0;
    }
    int idx = cnt - 1; idx = idx < 0 ? 0 : (idx > 7 ? 7 : idx);

    float icw = 0.f, iw = 1.f, ich = 0.f, ih = 1.f;
    float u0 = 0.f, u1 = 0.f;
    #pragma unroll
    for (int k = 0; k < 8; k++) {
        if (k == idx) {
            icw = cw[k]; iw = cw[k+1] - cw[k];
            ich = ch[k]; ih = ch[k+1] - ch[k];
        }
    }
    #pragma unroll
    for (int k = 0; k < 7; k++) {
        if (k == idx - 1) u0 = ud7[k];
        if (k == idx)     u1 = ud7[k];
    }
    // boundary derivative is exactly MIND + softplus(DCONST) = 1.0
    float d0 = (idx == 0) ? 1.f : 0.001f + softplus_fast(u0);
    float d1 = (idx == 7) ? 1.f : 0.001f + softplus_fast(u1);

    float delta = __fdividef(ih, iw);
    float t  = xi - ich;
    float s2 = d0 + d1 - 2.f * delta;
    float aa = t * s2 + ih * (delta - d0);
    float bb = ih * d0 - t * s2;
    float cc = -delta * t;
    float disc = bb * bb - 4.f * aa * cc;
    float sq = disc * __frsqrt_rn(fmaxf(disc, 1e-37f));
    float root = __fdividef(2.f * cc, -bb - sq);
    float o = root * iw + icw;
    float tm = root * (1.f - root);
    float den = delta + s2 * tm;
    float omr = 1.f - root;
    float dnum = delta * delta * (d1 * root * root + 2.f * delta * tm + d0 * omr * omr);
    float l = -__logf(__fdividef(dnum, den * den));

    out = inside ? o : x;
    ld  = inside ? l : 0.f;
}

// ---------------- small kernels ----------------
__global__ void zero_kernel(float* p, int n) {
    int i = blockIdx.x * blockDim.x + threadIdx.x;
    if (i < n) p[i] = 0.f;
}

__global__ void copy_pad_kernel(const float* __restrict__ x, float* __restrict__ z) {
    int i = blockIdx.x * blockDim.x + threadIdx.x;
    if (i >= B_ * D_) return;
    int b = i / D_, d = i % D_;
    z[b * LDD + d] = x[i];
}

__global__ void sumlog_kernel(const float* __restrict__ lu_ud, float* __restrict__ out) {
    int i = blockIdx.x;  // layer
    float s = 0.f;
    for (int d = threadIdx.x; d < D_; d += blockDim.x)
        s += __logf(softplus_acc(lu_ud[i * D_ + d]) + 0.001f);
    s = block_reduce_sum(s);
    if (threadIdx.x == 0) out[i] = s;
}

// Per-f knots for the unconditional (ident) spline: cw[9], ch[9], dd[9]
__global__ void ident_knots_kernel(const float* __restrict__ uw_u,
                                   const float* __restrict__ uh_u,
                                   const float* __restrict__ ud_u,
                                   float* __restrict__ kn)
{
    int f = blockIdx.x * blockDim.x + threadIdx.x;
    if (f >= F_) return;
    const float TB = 3.f;
    float* o = kn + f * 27;
    {
        const float* u = uw_u + f * 8;
        float m = u[0];
        #pragma unroll
        for (int k = 1; k < 8; k++) m = fmaxf(m, u[k]);
        float e[8]; float s = 0.f;
        #pragma unroll
        for (int k = 0; k < 8; k++) { e[k] = __expf(u[k] - m); s += e[k]; }
        float inv = 1.f / s;
        float cum = 0.f;
        o[0] = -TB;
        #pragma unroll
        for (int k = 0; k < 7; k++) { cum += 0.001f + 0.992f * e[k] * inv; o[k+1] = 6.f * cum - 3.f; }
        o[8] = TB;
    }
    {
        const float* u = uh_u + f * 8;
        float m = u[0];
        #pragma unroll
        for (int k = 1; k < 8; k++) m = fmaxf(m, u[k]);
        float e[8]; float s = 0.f;
        #pragma unroll
        for (int k = 0; k < 8; k++) { e[k] = __expf(u[k] - m); s += e[k]; }
        float inv = 1.f / s;
        float cum = 0.f;
        o[9] = -TB;
        #pragma unroll
        for (int k = 0; k < 7; k++) { cum += 0.001f + 0.992f * e[k] * inv; o[10+k] = 6.f * cum - 3.f; }
        o[17] = TB;
    }
    o[18] = 1.f; o[26] = 1.f;
    #pragma unroll
    for (int k = 0; k < 7; k++) o[19 + k] = 0.001f + softplus_acc(ud_u[f * 7 + k]);
}

// Table-driven ident spline eval. Block = 32 f x 8 b (256 thr).
__global__ void __launch_bounds__(256)
ident_eval_kernel(const float* __restrict__ zn, const float* __restrict__ kn,
                  float* __restrict__ ident, float* __restrict__ zout,
                  float* __restrict__ lq)
{
    __shared__ float sk[32][29];
    int tid = threadIdx.x;
    int f_local = tid & 31;
    int b_local = tid >> 5;
    int f0 = blockIdx.x * 32;
    int b  = blockIdx.y * 8 + b_local;

    for (int j = tid; j < 32 * 27; j += 256) {
        int fl = j / 27, e = j % 27;
        int f = f0 + fl;
        sk[fl][e] = (f < F_) ? kn[f * 27 + e] : 0.f;
    }
    __syncthreads();

    int f = f0 + f_local;
    float ldv = 0.f;
    if (f < F_) {
        const float TB = 3.f;
        const float* K = sk[f_local];
        float x = zn[b * LDD + 2 * f];
        bool inside = (x >= -TB) && (x <= TB);
        float xi = fminf(fmaxf(x, -TB), TB);

        int cnt = 0;
        #pragma unroll
        for (int k = 0; k < 9; k++) {
            float lo = K[9 + k] + (k == 8 ? 1e-6f : 0.f);
            cnt += (xi >= lo) ? 1 : 0;
        }
        int idx = cnt - 1; idx = idx < 0 ? 0 : (idx > 7 ? 7 : idx);

        float icw = K[idx],     iw = K[idx + 1] - icw;
        float ich = K[9 + idx], ih = K[10 + idx] - ich;
        float d0  = K[18 + idx], d1 = K[19 + idx];

        float delta = __fdividef(ih, iw);
        float t  = xi - ich;
        float s2 = d0 + d1 - 2.f * delta;
        float aa = t * s2 + ih * (delta - d0);
        float bb = ih * d0 - t * s2;
        float cc = -delta * t;
        float disc = bb * bb - 4.f * aa * cc;
        float sq = disc * __frsqrt_rn(fmaxf(disc, 1e-37f));
        float root = __fdividef(2.f * cc, -bb - sq);
        float o = root * iw + icw;
        float tm = root * (1.f - root);
        float den = delta + s2 * tm;
        float omr = 1.f - root;
        float dnum = delta * delta * (d1 * root * root + 2.f * delta * tm + d0 * omr * omr);
        float l = -__logf(__fdividef(dnum, den * den));

        float ov = inside ? o : x;
        ldv = inside ? l : 0.f;
        ident[b * LDF + f] = ov;
        zout[b * LDD + 2 * f] = ov;
    }
    #pragma unroll
    for (int o = 16; o > 0; o >>= 1) ldv += __shfl_xor_sync(0xffffffffu, ldv, o);
    if (f_local == 0) atomicAdd(&lq[b], ldv);
}

// Materialize LT[m,d] = L[d,m] (unit diag) and UpT[perm[k], m] = Udense[m,k].
__global__ void build_lt_upt_kernel(const float* __restrict__ lower,
                                    const float* __restrict__ upper,
                                    const float* __restrict__ lu_ud,
                                    const int* __restrict__ perm,
                                    float* __restrict__ LT, float* __restrict__ UpT)
{
    int c = blockIdx.x * blockDim.x + threadIdx.x;
    int rr = blockIdx.y;
    if (c >= D_) return;
    if (blockIdx.z == 0) {
        int m = rr, d = c;
        float v = (m < d) ? lower[d * D_ + m] : ((m == d) ? 1.f : 0.f);
        LT[m * LDD + d] = v;
    } else {
        int k = rr, m = c;
        float v;
        if (m < k)       v = upper[m * D_ + k];
        else if (m == k) v = softplus_acc(lu_ud[k]) + 0.001f;
        else             v = 0.f;
        UpT[perm[k] * LDD + m] = v;
    }
}

// ---------------- vectorized SGEMM (big + ApT GEMMs) ----------------
template<int BM, int BN, int TM, int TN, bool HASB>
__global__ void __launch_bounds__(256)
sgemm_tn(const float* __restrict__ A, const float* __restrict__ Bm,
         const float* __restrict__ bias, float* __restrict__ C,
         int M, int N, int K, int lda, int ldb, int ldc)
{
    constexpr int BK = 16;
    constexpr int TX = BN / TN, TY = BM / TM;
    static_assert(TX * TY == 256, "thread tiling");
    __shared__ __align__(16) float As[BK][BM];
    __shared__ __align__(16) float Bs[BK][BN];
    int tid = threadIdx.x;
    int tx = tid % TX, ty = tid / TX;
    int m0 = blockIdx.y * BM, n0 = blockIdx.x * BN;

    float acc[TM][TN];
    #pragma unroll
    for (int i = 0; i < TM; i++)
        #pragma unroll
        for (int j = 0; j < TN; j++) acc[i][j] = 0.f;

    for (int k0 = 0; k0 < K; k0 += BK) {
        #pragma unroll
        for (int idx = tid; idx < BM * 4; idx += 256) {
            int m = idx >> 2, k4 = (idx & 3) << 2;
            int gm = m0 + m, gk = k0 + k4;
            float4 v = make_float4(0.f, 0.f, 0.f, 0.f);
            if (gm < M && gk < K)
                v = *reinterpret_cast<const float4*>(&A[gm * lda + gk]);
            As[k4 + 0][m] = v.x; As[k4 + 1][m] = v.y;
            As[k4 + 2][m] = v.z; As[k4 + 3][m] = v.w;
        }
        #pragma unroll
        for (int idx = tid; idx < BN * 4; idx += 256) {
            int k = idx / (BN / 4), n4 = (idx % (BN / 4)) << 2;
            int gk = k0 + k, gn = n0 + n4;
            float4 v = make_float4(0.f, 0.f, 0.f, 0.f);
            if (gk < K && gn < N)
                v = *reinterpret_cast<const float4*>(&Bm[gk * ldb + gn]);
            *reinterpret_cast<float4*>(&Bs[k][n4]) = v;
        }
        __syncthreads();
        #pragma unroll
        for (int kk = 0; kk < BK; kk++) {
            float a[TM], b[TN];
            #pragma unroll
            for (int i = 0; i < TM / 4; i++)
                *reinterpret_cast<float4*>(&a[4 * i]) =
                    *reinterpret_cast<const float4*>(&As[kk][ty * TM + 4 * i]);
            #pragma unroll
            for (int j = 0; j < TN / 4; j++)
                *reinterpret_cast<float4*>(&b[4 * j]) =
                    *reinterpret_cast<const float4*>(&Bs[kk][tx * TN + 4 * j]);
            #pragma unroll
            for (int i = 0; i < TM; i++)
                #pragma unroll
                for (int j = 0; j < TN; j++)
                    acc[i][j] = fmaf(a[i], b[j], acc[i][j]);
        }
        __syncthreads();
    }
    #pragma unroll
    for (int i = 0; i < TM; i++) {
        int gm = m0 + ty * TM + i;
        if (gm < M) {
            #pragma unroll
            for (int j = 0; j < TN; j++) {
                int gn = n0 + tx * TN + j;
                if (gn < N)
                    C[gm * ldc + gn] = acc[i][j] + (HASB ? bias[gn] : 0.f);
            }
        }
    }
}

// ---------------- resnet GEMM (R2 version, scalar loads) ----------------
template<int BM, int BN, int BK, int TM, int TN, bool RELUA, bool ADDC>
__global__ void __launch_bounds__((BM/TM)*(BN/TN))
gemm_k(const float* __restrict__ A, const float* __restrict__ B,
       const float* __restrict__ bias, const float* __restrict__ Cadd,
       float* __restrict__ C, int M, int N, int K, int lda, int ldb, int ldc)
{
    constexpr int TX = BN / TN, TY = BM / TM, NT = TX * TY;
    __shared__ float As[BK][BM];
    __shared__ float Bs[BK][BN];
    int tid = threadIdx.x;
    int tx = tid % TX, ty = tid / TX;
    int m0 = blockIdx.y * BM, n0 = blockIdx.x * BN;
    float acc[TM][TN];
    #pragma unroll
    for (int i = 0; i < TM; i++)
        #pragma unroll
        for (int j = 0; j < TN; j++) acc[i][j] = 0.f;

    for (int k0 = 0; k0 < K; k0 += BK) {
        #pragma unroll
        for (int idx = tid; idx < BM * BK; idx += NT) {
            int r = idx / BK, c = idx % BK;
            int gm = m0 + r, gk = k0 + c;
            float v = (gk < K) ? A[gm * lda + gk] : 0.f;
            if (RELUA) v = fmaxf(v, 0.f);
            As[c][r] = v;
        }
        #pragma unroll
        for (int idx = tid; idx < BK * BN; idx += NT) {
            int r = idx / BN, c = idx % BN;
            int gk = k0 + r, gn = n0 + c;
            Bs[r][c] = (gk < K && gn < N) ? B[gk * ldb + gn] : 0.f;
        }
        __syncthreads();
        #pragma unroll
        for (int kk = 0; kk < BK; kk++) {
            float ra[TM], rb[TN];
            #pragma unroll
            for (int i = 0; i < TM; i++) ra[i] = As[kk][ty * TM + i];
            #pragma unroll
            for (int j = 0; j < TN; j++) rb[j] = Bs[kk][tx * TN + j];
            #pragma unroll
            for (int i = 0; i < TM; i++)
                #pragma unroll
                for (int j = 0; j < TN; j++)
                    acc[i][j] += ra[i] * rb[j];
        }
        __syncthreads();
    }
    #pragma unroll
    for (int i = 0; i < TM; i++) {
        int gm = m0 + ty * TM + i;
        #pragma unroll
        for (int j = 0; j < TN; j++) {
            int gn = n0 + tx * TN + j;
            if (gn < N) {
                float v = acc[i][j] + bias[gn];
                if (ADDC) v += Cadd[gm * ldc + gn];
                C[gm * ldc + gn] = v;
            }
        }
    }
}

// Fused: p[b,f,:] = t[b,:] @ Wo[:, f*23:(f+1)*23] + bo, then conditional RQS
// inverse on trans = zn[:, 2f+1].
__global__ void __launch_bounds__(128)
wo_spline_kernel(const float* __restrict__ tmat, const float* __restrict__ Wo,
                 const float* __restrict__ bo, const float* __restrict__ zn,
                 float* __restrict__ zout, float* __restrict__ lq)
{
    constexpr int BTB = 32, BTF = 8, KC = 16;
    __shared__ float ts[BTB][129];
    __shared__ float wos[KC][BTF * 28];
    __shared__ float bos[BTF * 24];

    int tid = threadIdx.x;
    int f_local = tid & 7;
    int b_local = tid >> 3;               // 0..15
    int b0 = blockIdx.y * BTB;
    int f0 = blockIdx.x * BTF;
    int f  = f0 + f_local;

    for (int idx = tid; idx < BTB * 128; idx += 128) {
        int r = idx >> 7, c = idx & 127;
        ts[r][c] = tmat[(b0 + r) * H_ + c];
    }
    for (int idx = tid; idx < BTF * 24; idx += 128) {
        int ff = idx / 24, oo = idx % 24;
        int col = (f0 + ff) * 23 + oo;
        bos[idx] = (oo < 23 && col < OUT_) ? bo[col] : 0.f;
    }

    float acc0[24], acc1[24];
    #pragma unroll
    for (int o = 0; o < 24; o++) { acc0[o] = 0.f; acc1[o] = 0.f; }

    for (int kc = 0; kc < H_; kc += KC) {
        __syncthreads();
        for (int idx = tid; idx < KC * BTF * 23; idx += 128) {
            int kk = idx / (BTF * 23), rem = idx % (BTF * 23);
            int ff = rem / 23, oo = rem % 23;
            int col = (f0 + ff) * 23 + oo;
            wos[kk][ff * 28 + oo] = (col < OUT_) ? Wo[(kc + kk) * OUT_ + col] : 0.f;
        }
        for (int idx = tid; idx < KC * BTF; idx += 128) {
            int kk = idx / BTF, ff = idx % BTF;
            wos[kk][ff * 28 + 23] = 0.f;
        }
        __syncthreads();
        #pragma unroll
        for (int kk = 0; kk < KC; kk++) {
            float tv0 = ts[b_local][kc + kk];
            float tv1 = ts[b_local + 16][kc + kk];
            const float4* wp = reinterpret_cast<const float4*>(&wos[kk][f_local * 28]);
            #pragma unroll
            for (int q = 0; q < 6; q++) {
                float4 w4 = wp[q];
                acc0[q*4+0] += tv0 * w4.x; acc0[q*4+1] += tv0 * w4.y;
                acc0[q*4+2] += tv0 * w4.z; acc0[q*4+3] += tv0 * w4.w;
                acc1[q*4+0] += tv1 * w4.x; acc1[q*4+1] += tv1 * w4.y;
                acc1[q*4+2] += tv1 * w4.z; acc1[q*4+3] += tv1 * w4.w;
            }
        }
    }

    const float scale = 0.08838834764831845f;  // 1/sqrt(128)
    float ld0 = 0.f, ld1 = 0.f;

    if (f < F_) {
        {   // row 0
            float uw[8], uh[8], ud7[7];
            #pragma unroll
            for (int o = 0; o < 8; o++) {
                uw[o] = (acc0[o]     + bos[f_local * 24 + o])     * scale;
                uh[o] = (acc0[8 + o] + bos[f_local * 24 + 8 + o]) * scale;
            }
            #pragma unroll
            for (int o = 0; o < 7; o++) ud7[o] = acc0[16 + o] + bos[f_local * 24 + 16 + o];
            int b = b0 + b_local;
            float x = zn[b * LDD + 2 * f + 1];
            float o, l;
            rqs_fast(x, uw, uh, ud7, o, l);
            zout[b * LDD + 2 * f + 1] = o;
            ld0 = l;
        }
        {   // row 1
            float uw[8], uh[8], ud7[7];
            #pragma unroll
            for (int o = 0; o < 8; o++) {
                uw[o] = (acc1[o]     + bos[f_local * 24 + o])     * scale;
                uh[o] = (acc1[8 + o] + bos[f_local * 24 + 8 + o]) * scale;
            }
            #pragma unroll
            for (int o = 0; o < 7; o++) ud7[o] = acc1[16 + o] + bos[f_local * 24 + 16 + o];
            int b = b0 + b_local + 16;
            float x = zn[b * LDD + 2 * f + 1];
            float o, l;
            rqs_fast(x, uw, uh, ud7, o, l);
            zout[b * LDD + 2 * f + 1] = o;
            ld1 = l;
        }
    }
    #pragma unroll
    for (int o = 4; o > 0; o >>= 1) {
        ld0 += __shfl_xor_sync(0xffffffffu, ld0, o);
        ld1 += __shfl_xor_sync(0xffffffffu, ld1, o);
    }
    if (f_local == 0) {
        atomicAdd(&lq[b0 + b_local], ld0);
        atomicAdd(&lq[b0 + b_local + 16], ld1);
    }
}

__global__ void final_kernel(const float* __restrict__ z, const float* __restrict__ loc,
                             const float* __restrict__ lsc, const float* __restrict__ lq,
                             const float* __restrict__ slog, float* __restrict__ out)
{
    int b = blockIdx.x;
    float s = 0.f;
    for (int d = threadIdx.x; d < D_; d += blockDim.x) {
        float inv = __expf(-lsc[d]);
        float u = (z[b * LDD + d] - loc[d]) * inv;
        s += lsc[d] + 0.5f * u * u;
    }
    s = block_reduce_sum(s);
    if (threadIdx.x == 0) {
        const float c = 0.5f * 550.f * 1.8378770664093453f;
        out[b] = lq[b] + slog[0] + slog[1] + slog[2] - c - s;
    }
}

// ---------------- launch ----------------
extern "C" void kernel_launch(void* const* d_in, const int* in_sizes, int n_in,
                              void* d_out, int out_size)
{
    (void)in_sizes; (void)n_in; (void)out_size;
    const float* x      = (const float*)d_in[0];
    const float* loc    = (const float*)d_in[1];
    const float* lsc    = (const float*)d_in[2];
    const float* Wi     = (const float*)d_in[3];
    const float* bi     = (const float*)d_in[4];
    const float* Wb     = (const float*)d_in[5];
    const float* bb     = (const float*)d_in[6];
    const float* Wo     = (const float*)d_in[7];
    const float* bo     = (const float*)d_in[8];
    const float* uw_u   = (const float*)d_in[9];
    const float* uh_u   = (const float*)d_in[10];
    const float* ud_u   = (const float*)d_in[11];
    const float* lower  = (const float*)d_in[12];
    const float* upper  = (const float*)d_in[13];
    const float* lu_ud  = (const float*)d_in[14];
    const float* lu_b   = (const float*)d_in[15];
    const int*   perms  = (const int*)d_in[16];
    float* outp = (float*)d_out;

    float *z, *zn, *LT, *UpT, *ApT, *ident, *t, *r, *lq, *slog, *kn;
    cudaGetSymbolAddress((void**)&z,     g_z);
    cudaGetSymbolAddress((void**)&zn,    g_zn);
    cudaGetSymbolAddress((void**)&LT,    g_LT);
    cudaGetSymbolAddress((void**)&UpT,   g_UpT);
    cudaGetSymbolAddress((void**)&ApT,   g_ApT);
    cudaGetSymbolAddress((void**)&ident, g_id);
    cudaGetSymbolAddress((void**)&t,     g_t);
    cudaGetSymbolAddress((void**)&r,     g_r);
    cudaGetSymbolAddress((void**)&lq,    g_lq);
    cudaGetSymbolAddress((void**)&slog,  g_slog);
    cudaGetSymbolAddress((void**)&kn,    g_kn);

    // Per-layer body, minus the launch-order prelude of layer 2
    auto resnet_and_tail = [&](int i) {
        ident_knots_kernel<<<(F_ + 255) / 256, 256>>>(
            uw_u + i * F_ * 8, uh_u + i * F_ * 8, ud_u + i * F_ * 7, kn);
        ident_eval_kernel<<<dim3((F_ + 31) / 32, B_ / 8), 256>>>(
            zn, kn, ident, z, lq);
        gemm_k<64, 64, 16, 4, 4, false, false>
            <<<dim3(2, B_ / 64), 256>>>(ident, Wi + i * F_ * H_, bi + i * H_, nullptr,
                                        t, B_, H_, F_, LDF, H_, H_);
        gemm_k<64, 64, 16, 4, 4, true, false>
            <<<dim3(2, B_ / 64), 256>>>(t, Wb + (i * 4 + 0) * H_ * H_, bb + (i * 4 + 0) * H_,
                                        nullptr, r, B_, H_, H_, H_, H_, H_);
        gemm_k<64, 64, 16, 4, 4, true, true>
            <<<dim3(2, B_ / 64), 256>>>(r, Wb + (i * 4 + 1) * H_ * H_, bb + (i * 4 + 1) * H_,
                                        t, t, B_, H_, H_, H_, H_, H_);
        gemm_k<64, 64, 16, 4, 4, true, false>
            <<<dim3(2, B_ / 64), 256>>>(t, Wb + (i * 4 + 2) * H_ * H_, bb + (i * 4 + 2) * H_,
                                        nullptr, r, B_, H_, H_, H_, H_, H_);
        gemm_k<64, 64, 16, 4, 4, true, true>
            <<<dim3(2, B_ / 64), 256>>>(r, Wb + (i * 4 + 3) * H_ * H_, bb + (i * 4 + 3) * H_,
                                        t, t, B_, H_, H_, H_, H_, H_);
        wo_spline_kernel<<<dim3((F_ + 7) / 8, B_ / 32), 128>>>(
            t, Wo + i * H_ * OUT_, bo + i * OUT_, zn, z, lq);
    };

    // ---- layer 2 prelude, ordered so the BIG GEMM is launch index 3 (ncu) ----
    build_lt_upt_kernel<<<dim3((D_ + 255) / 256, D_, 2), 256>>>(          // 0
        lower + 2 * D_ * D_, upper + 2 * D_ * D_, lu_ud + 2 * D_, perms + 2 * D_, LT, UpT);
    sgemm_tn<64, 64, 4, 4, false>                                          // 1
        <<<dim3((D_ + 63) / 64, (D_ + 63) / 64), 256>>>(
            UpT, LT, nullptr, ApT, D_, D_, D_, LDD, LDD, LDD);
    copy_pad_kernel<<<(B_ * D_ + 255) / 256, 256>>>(x, z);                 // 2
    sgemm_tn<128, 128, 8, 8, true>                                         // 3 <- profiled
        <<<dim3((D_ + 127) / 128, B_ / 128), 256>>>(
            z, ApT, lu_b + 2 * D_, zn, B_, D_, D_, LDD, LDD, LDD);
    zero_kernel<<<(B_ + 255) / 256, 256>>>(lq, B_);                        // 4
    sumlog_kernel<<<3, 256>>>(lu_ud, slog);                                // 5
    resnet_and_tail(2);

    for (int i = 1; i >= 0; i--) {
        build_lt_upt_kernel<<<dim3((D_ + 255) / 256, D_, 2), 256>>>(
            lower + i * D_ * D_, upper + i * D_ * D_,
            lu_ud + i * D_, perms + i * D_, LT, UpT);
        sgemm_tn<64, 64, 4, 4, false>
            <<<dim3((D_ + 63) / 64, (D_ + 63) / 64), 256>>>(
                UpT, LT, nullptr, ApT, D_, D_, D_, LDD, LDD, LDD);
        sgemm_tn<128, 128, 8, 8, true>
            <<<dim3((D_ + 127) / 128, B_ / 128), 256>>>(
                z, ApT, lu_b + i * D_, zn, B_, D_, D_, LDD, LDD, LDD);
        resnet_and_tail(i);
    }

    final_kernel<<<B_, 256>>>(z, loc, lsc, lq, slog, outp);
}

// round 5
// speedup vs baseline: 1.7322x; 1.1089x over previous
#include <cuda_runtime.h>
#include <math.h>

// ---------------- problem constants ----------------
namespace {
constexpr int D_   = 550;
constexpr int LDP  = 560;    // padded lead dim: 35*16, all pads guaranteed zero
constexpr int MATR = 576;    // matrix buffer rows (covers 9*64 tile overreach)
constexpr int F_   = 275;
constexpr int LDF  = 276;    // padded ident stride
constexpr int B_   = 4096;   // N*T = 8*512
constexpr int H_   = 128;
constexpr int OUT_ = 6325;   // F_*(3*8-1)
}

// ---------------- scratch (device globals; no allocs allowed) ----------------
__device__ float g_z  [B_*LDP];   // zero-init => pad cols stay 0
__device__ float g_zn [B_*LDP];
__device__ float g_LT [MATR*LDP];
__device__ float g_UpT[MATR*LDP];
__device__ float g_ApT[MATR*LDP];
__device__ float g_id [B_*LDF];
__device__ float g_t  [B_*H_];
__device__ float g_r  [B_*H_];
__device__ float g_lq [B_];
__device__ float g_slog[3];
__device__ float g_kn [F_*27];    // per-f ident knots: cw[9], ch[9], dd[9]

// ---------------- helpers ----------------
__device__ __forceinline__ float softplus_acc(float x) {   // accurate (precompute only)
    return (x > 20.f) ? x : log1pf(__expf(x));
}
__device__ __forceinline__ float softplus_fast(float x) {
    return (x > 15.f) ? x : __logf(1.f + __expf(x));
}

__device__ __forceinline__ float block_reduce_sum(float v) {
    __shared__ float sred[32];
    int tid = threadIdx.x;
    #pragma unroll
    for (int o = 16; o > 0; o >>= 1) v += __shfl_down_sync(0xffffffffu, v, o);
    if ((tid & 31) == 0) sred[tid >> 5] = v;
    __syncthreads();
    if (tid < 32) {
        int nw = (blockDim.x + 31) >> 5;
        v = (tid < nw) ? sred[tid] : 0.f;
        #pragma unroll
        for (int o = 16; o > 0; o >>= 1) v += __shfl_down_sync(0xffffffffu, v, o);
    }
    return v;  // valid in thread 0
}

// Fast inverse RQS, params in registers (conditional path).
__device__ __forceinline__ void rqs_fast(float x, const float* uw, const float* uh,
                                         const float* ud7, float& out, float& ld)
{
    const float TB = 3.f;
    bool inside = (x >= -TB) && (x <= TB);
    float xi = fminf(fmaxf(x, -TB), TB);

    float cw[9], ch[9];
    {
        float m = uw[0];
        #pragma unroll
        for (int k = 1; k < 8; k++) m = fmaxf(m, uw[k]);
        float e[8]; float s = 0.f;
        #pragma unroll
        for (int k = 0; k < 8; k++) { e[k] = __expf(uw[k] - m); s += e[k]; }
        float inv = __fdividef(1.f, s);
        float cum = 0.f;
        cw[0] = -TB;
        #pragma unroll
        for (int k = 0; k < 7; k++) { cum += 0.001f + 0.992f * e[k] * inv; cw[k+1] = 6.f * cum - 3.f; }
        cw[8] = TB;
    }
    {
        float m = uh[0];
        #pragma unroll
        for (int k = 1; k < 8; k++) m = fmaxf(m, uh[k]);
        float e[8]; float s = 0.f;
        #pragma unroll
        for (int k = 0; k < 8; k++) { e[k] = __expf(uh[k] - m); s += e[k]; }
        float inv = __fdividef(1.f, s);
        float cum = 0.f;
        ch[0] = -TB;
        #pragma unroll
        for (int k = 0; k < 7; k++) { cum += 0.001f + 0.992f * e[k] * inv; ch[k+1] = 6.f * cum - 3.f; }
        ch[8] = TB;
    }

    // bin search on height knots
    int cnt = 0;
    #pragma unroll
    for (int k = 0; k < 9; k++) {
        float lo = ch[k] + (k == 8 ? 1e-6f : 0.f);
        cnt += (xi >= lo) ? 1 : 0;
    }
    int idx = cnt - 1; idx = idx < 0 ? 0 : (idx > 7 ? 7 : idx);

    float icw = 0.f, iw = 1.f, ich = 0.f, ih = 1.f;
    float u0 = 0.f, u1 = 0.f;
    #pragma unroll
    for (int k = 0; k < 8; k++) {
        if (k == idx) {
            icw = cw[k]; iw = cw[k+1] - cw[k];
            ich = ch[k]; ih = ch[k+1] - ch[k];
        }
    }
    #pragma unroll
    for (int k = 0; k < 7; k++) {
        if (k == idx - 1) u0 = ud7[k];
        if (k == idx)     u1 = ud7[k];
    }
    // boundary derivative is exactly MIND + softplus(DCONST) = 1.0
    float d0 = (idx == 0) ? 1.f : 0.001f + softplus_fast(u0);
    float d1 = (idx == 7) ? 1.f : 0.001f + softplus_fast(u1);

    float delta = __fdividef(ih, iw);
    float t  = xi - ich;
    float s2 = d0 + d1 - 2.f * delta;
    float aa = t * s2 + ih * (delta - d0);
    float bb = ih * d0 - t * s2;
    float cc = -delta * t;
    float disc = bb * bb - 4.f * aa * cc;
    float sq = disc * __frsqrt_rn(fmaxf(disc, 1e-37f));
    float root = __fdividef(2.f * cc, -bb - sq);
    float o = root * iw + icw;
    float tm = root * (1.f - root);
    float den = delta + s2 * tm;
    float omr = 1.f - root;
    float dnum = delta * delta * (d1 * root * root + 2.f * delta * tm + d0 * omr * omr);
    float l = -__logf(__fdividef(dnum, den * den));

    out = inside ? o : x;
    ld  = inside ? l : 0.f;
}

// ---------------- small kernels ----------------
__global__ void zero_kernel(float* p, int n) {
    int i = blockIdx.x * blockDim.x + threadIdx.x;
    if (i < n) p[i] = 0.f;
}

__global__ void copy_pad_kernel(const float* __restrict__ x, float* __restrict__ z) {
    int i = blockIdx.x * blockDim.x + threadIdx.x;
    if (i >= B_ * D_) return;
    int b = i / D_, d = i % D_;
    z[b * LDP + d] = x[i];
}

__global__ void sumlog_kernel(const float* __restrict__ lu_ud, float* __restrict__ out) {
    int i = blockIdx.x;  // layer
    float s = 0.f;
    for (int d = threadIdx.x; d < D_; d += blockDim.x)
        s += __logf(softplus_acc(lu_ud[i * D_ + d]) + 0.001f);
    s = block_reduce_sum(s);
    if (threadIdx.x == 0) out[i] = s;
}

// Per-f knots for the unconditional (ident) spline: cw[9], ch[9], dd[9]
__global__ void ident_knots_kernel(const float* __restrict__ uw_u,
                                   const float* __restrict__ uh_u,
                                   const float* __restrict__ ud_u,
                                   float* __restrict__ kn)
{
    int f = blockIdx.x * blockDim.x + threadIdx.x;
    if (f >= F_) return;
    const float TB = 3.f;
    float* o = kn + f * 27;
    {
        const float* u = uw_u + f * 8;
        float m = u[0];
        #pragma unroll
        for (int k = 1; k < 8; k++) m = fmaxf(m, u[k]);
        float e[8]; float s = 0.f;
        #pragma unroll
        for (int k = 0; k < 8; k++) { e[k] = __expf(u[k] - m); s += e[k]; }
        float inv = 1.f / s;
        float cum = 0.f;
        o[0] = -TB;
        #pragma unroll
        for (int k = 0; k < 7; k++) { cum += 0.001f + 0.992f * e[k] * inv; o[k+1] = 6.f * cum - 3.f; }
        o[8] = TB;
    }
    {
        const float* u = uh_u + f * 8;
        float m = u[0];
        #pragma unroll
        for (int k = 1; k < 8; k++) m = fmaxf(m, u[k]);
        float e[8]; float s = 0.f;
        #pragma unroll
        for (int k = 0; k < 8; k++) { e[k] = __expf(u[k] - m); s += e[k]; }
        float inv = 1.f / s;
        float cum = 0.f;
        o[9] = -TB;
        #pragma unroll
        for (int k = 0; k < 7; k++) { cum += 0.001f + 0.992f * e[k] * inv; o[10+k] = 6.f * cum - 3.f; }
        o[17] = TB;
    }
    o[18] = 1.f; o[26] = 1.f;
    #pragma unroll
    for (int k = 0; k < 7; k++) o[19 + k] = 0.001f + softplus_acc(ud_u[f * 7 + k]);
}

// Table-driven ident spline eval. Block = 32 f x 8 b (256 thr).
__global__ void __launch_bounds__(256)
ident_eval_kernel(const float* __restrict__ zn, const float* __restrict__ kn,
                  float* __restrict__ ident, float* __restrict__ zout,
                  float* __restrict__ lq)
{
    __shared__ float sk[32][29];
    int tid = threadIdx.x;
    int f_local = tid & 31;
    int b_local = tid >> 5;
    int f0 = blockIdx.x * 32;
    int b  = blockIdx.y * 8 + b_local;

    for (int j = tid; j < 32 * 27; j += 256) {
        int fl = j / 27, e = j % 27;
        int f = f0 + fl;
        sk[fl][e] = (f < F_) ? kn[f * 27 + e] : 0.f;
    }
    __syncthreads();

    int f = f0 + f_local;
    float ldv = 0.f;
    if (f < F_) {
        const float TB = 3.f;
        const float* K = sk[f_local];
        float x = zn[b * LDP + 2 * f];
        bool inside = (x >= -TB) && (x <= TB);
        float xi = fminf(fmaxf(x, -TB), TB);

        int cnt = 0;
        #pragma unroll
        for (int k = 0; k < 9; k++) {
            float lo = K[9 + k] + (k == 8 ? 1e-6f : 0.f);
            cnt += (xi >= lo) ? 1 : 0;
        }
        int idx = cnt - 1; idx = idx < 0 ? 0 : (idx > 7 ? 7 : idx);

        float icw = K[idx],     iw = K[idx + 1] - icw;
        float ich = K[9 + idx], ih = K[10 + idx] - ich;
        float d0  = K[18 + idx], d1 = K[19 + idx];

        float delta = __fdividef(ih, iw);
        float t  = xi - ich;
        float s2 = d0 + d1 - 2.f * delta;
        float aa = t * s2 + ih * (delta - d0);
        float bb = ih * d0 - t * s2;
        float cc = -delta * t;
        float disc = bb * bb - 4.f * aa * cc;
        float sq = disc * __frsqrt_rn(fmaxf(disc, 1e-37f));
        float root = __fdividef(2.f * cc, -bb - sq);
        float o = root * iw + icw;
        float tm = root * (1.f - root);
        float den = delta + s2 * tm;
        float omr = 1.f - root;
        float dnum = delta * delta * (d1 * root * root + 2.f * delta * tm + d0 * omr * omr);
        float l = -__logf(__fdividef(dnum, den * den));

        float ov = inside ? o : x;
        ldv = inside ? l : 0.f;
        ident[b * LDF + f] = ov;
        zout[b * LDP + 2 * f] = ov;
    }
    #pragma unroll
    for (int o = 16; o > 0; o >>= 1) ldv += __shfl_xor_sync(0xffffffffu, ldv, o);
    if (f_local == 0) atomicAdd(&lq[b], ldv);
}

// Materialize LT[m,d] = L[d,m] (unit diag) and UpT[perm[k], m] = Udense[m,k].
__global__ void build_lt_upt_kernel(const float* __restrict__ lower,
                                    const float* __restrict__ upper,
                                    const float* __restrict__ lu_ud,
                                    const int* __restrict__ perm,
                                    float* __restrict__ LT, float* __restrict__ UpT)
{
    int c = blockIdx.x * blockDim.x + threadIdx.x;
    int rr = blockIdx.y;
    if (c >= D_) return;
    if (blockIdx.z == 0) {
        int m = rr, d = c;
        float v = (m < d) ? lower[d * D_ + m] : ((m == d) ? 1.f : 0.f);
        LT[m * LDP + d] = v;
    } else {
        int k = rr, m = c;
        float v;
        if (m < k)       v = upper[m * D_ + k];
        else if (m == k) v = softplus_acc(lu_ud[k]) + 0.001f;
        else             v = 0.f;
        UpT[perm[k] * LDP + m] = v;
    }
}

// ---------------- padded SGEMM: C = A @ B + bias ----------------
// Requires: K % 16 == 0, rows of A/B beyond M/valid-K are readable and the
// products they generate only land in discarded (gn >= N) outputs.
// A: [M x lda] row-major; B: [K x ldb] row-major.
template<int BM, int BN, int TM, int TN, bool GUARDM, bool HASB>
__global__ void __launch_bounds__(256)
sgemm_pad(const float* __restrict__ A, const float* __restrict__ Bm,
          const float* __restrict__ bias, float* __restrict__ C,
          int M, int N, int K, int lda, int ldb, int ldc)
{
    constexpr int BK = 16;
    constexpr int TX = BN / TN, TY = BM / TM;
    static_assert(TX * TY == 256, "thread tiling");
    __shared__ __align__(16) float As[BK][BM];
    __shared__ __align__(16) float Bs[BK][BN];
    int tid = threadIdx.x;
    int tx = tid % TX, ty = tid / TX;
    int m0 = blockIdx.y * BM, n0 = blockIdx.x * BN;

    float acc[TM][TN];
    #pragma unroll
    for (int i = 0; i < TM; i++)
        #pragma unroll
        for (int j = 0; j < TN; j++) acc[i][j] = 0.f;

    for (int k0 = 0; k0 < K; k0 += BK) {
        // A tile: BM x 16, float4 along k, transposed store
        #pragma unroll
        for (int idx = tid; idx < BM * 4; idx += 256) {
            int m = idx >> 2, k4 = (idx & 3) << 2;
            int gm = m0 + m;
            float4 v = make_float4(0.f, 0.f, 0.f, 0.f);
            if (!GUARDM || gm < M)
                v = *reinterpret_cast<const float4*>(&A[gm * lda + k0 + k4]);
            As[k4 + 0][m] = v.x; As[k4 + 1][m] = v.y;
            As[k4 + 2][m] = v.z; As[k4 + 3][m] = v.w;
        }
        // B tile: 16 x BN, float4 along n (unchecked; see contract above)
        #pragma unroll
        for (int idx = tid; idx < BN * 4; idx += 256) {
            int k = idx / (BN / 4), n4 = (idx % (BN / 4)) << 2;
            float4 v = *reinterpret_cast<const float4*>(&Bm[(k0 + k) * ldb + n0 + n4]);
            *reinterpret_cast<float4*>(&Bs[k][n4]) = v;
        }
        __syncthreads();
        #pragma unroll
        for (int kk = 0; kk < BK; kk++) {
            float a[TM], b[TN];
            #pragma unroll
            for (int i = 0; i < TM / 4; i++)
                *reinterpret_cast<float4*>(&a[4 * i]) =
                    *reinterpret_cast<const float4*>(&As[kk][ty * TM + 4 * i]);
            #pragma unroll
            for (int j = 0; j < TN / 4; j++)
                *reinterpret_cast<float4*>(&b[4 * j]) =
                    *reinterpret_cast<const float4*>(&Bs[kk][tx * TN + 4 * j]);
            #pragma unroll
            for (int i = 0; i < TM; i++)
                #pragma unroll
                for (int j = 0; j < TN; j++)
                    acc[i][j] = fmaf(a[i], b[j], acc[i][j]);
        }
        __syncthreads();
    }
    #pragma unroll
    for (int i = 0; i < TM; i++) {
        int gm = m0 + ty * TM + i;
        if (!GUARDM || gm < M) {
            #pragma unroll
            for (int j = 0; j < TN; j++) {
                int gn = n0 + tx * TN + j;
                if (gn < N) {
                    float bv = HASB ? bias[gn] : 0.f;
                    C[gm * ldc + gn] = acc[i][j] + bv;
                }
            }
        }
    }
}

// ---------------- resnet GEMM (R2 version, scalar loads) ----------------
template<int BM, int BN, int BK, int TM, int TN, bool RELUA, bool ADDC>
__global__ void __launch_bounds__((BM/TM)*(BN/TN))
gemm_k(const float* __restrict__ A, const float* __restrict__ B,
       const float* __restrict__ bias, const float* __restrict__ Cadd,
       float* __restrict__ C, int M, int N, int K, int lda, int ldb, int ldc)
{
    constexpr int TX = BN / TN, TY = BM / TM, NT = TX * TY;
    __shared__ float As[BK][BM];
    __shared__ float Bs[BK][BN];
    int tid = threadIdx.x;
    int tx = tid % TX, ty = tid / TX;
    int m0 = blockIdx.y * BM, n0 = blockIdx.x * BN;
    float acc[TM][TN];
    #pragma unroll
    for (int i = 0; i < TM; i++)
        #pragma unroll
        for (int j = 0; j < TN; j++) acc[i][j] = 0.f;

    for (int k0 = 0; k0 < K; k0 += BK) {
        #pragma unroll
        for (int idx = tid; idx < BM * BK; idx += NT) {
            int r = idx / BK, c = idx % BK;
            int gm = m0 + r, gk = k0 + c;
            float v = (gk < K) ? A[gm * lda + gk] : 0.f;
            if (RELUA) v = fmaxf(v, 0.f);
            As[c][r] = v;
        }
        #pragma unroll
        for (int idx = tid; idx < BK * BN; idx += NT) {
            int r = idx / BN, c = idx % BN;
            int gk = k0 + r, gn = n0 + c;
            Bs[r][c] = (gk < K && gn < N) ? B[gk * ldb + gn] : 0.f;
        }
        __syncthreads();
        #pragma unroll
        for (int kk = 0; kk < BK; kk++) {
            float ra[TM], rb[TN];
            #pragma unroll
            for (int i = 0; i < TM; i++) ra[i] = As[kk][ty * TM + i];
            #pragma unroll
            for (int j = 0; j < TN; j++) rb[j] = Bs[kk][tx * TN + j];
            #pragma unroll
            for (int i = 0; i < TM; i++)
                #pragma unroll
                for (int j = 0; j < TN; j++)
                    acc[i][j] += ra[i] * rb[j];
        }
        __syncthreads();
    }
    #pragma unroll
    for (int i = 0; i < TM; i++) {
        int gm = m0 + ty * TM + i;
        #pragma unroll
        for (int j = 0; j < TN; j++) {
            int gn = n0 + tx * TN + j;
            if (gn < N) {
                float v = acc[i][j] + bias[gn];
                if (ADDC) v += Cadd[gm * ldc + gn];
                C[gm * ldc + gn] = v;
            }
        }
    }
}

// Fused: p[b,f,:] = t[b,:] @ Wo[:, f*23:(f+1)*23] + bo, then conditional RQS
// inverse on trans = zn[:, 2f+1].
__global__ void __launch_bounds__(128)
wo_spline_kernel(const float* __restrict__ tmat, const float* __restrict__ Wo,
                 const float* __restrict__ bo, const float* __restrict__ zn,
                 float* __restrict__ zout, float* __restrict__ lq)
{
    constexpr int BTB = 32, BTF = 8, KC = 16;
    __shared__ float ts[BTB][129];
    __shared__ float wos[KC][BTF * 28];
    __shared__ float bos[BTF * 24];

    int tid = threadIdx.x;
    int f_local = tid & 7;
    int b_local = tid >> 3;               // 0..15
    int b0 = blockIdx.y * BTB;
    int f0 = blockIdx.x * BTF;
    int f  = f0 + f_local;

    for (int idx = tid; idx < BTB * 128; idx += 128) {
        int r = idx >> 7, c = idx & 127;
        ts[r][c] = tmat[(b0 + r) * H_ + c];
    }
    for (int idx = tid; idx < BTF * 24; idx += 128) {
        int ff = idx / 24, oo = idx % 24;
        int col = (f0 + ff) * 23 + oo;
        bos[idx] = (oo < 23 && col < OUT_) ? bo[col] : 0.f;
    }

    float acc0[24], acc1[24];
    #pragma unroll
    for (int o = 0; o < 24; o++) { acc0[o] = 0.f; acc1[o] = 0.f; }

    for (int kc = 0; kc < H_; kc += KC) {
        __syncthreads();
        for (int idx = tid; idx < KC * BTF * 23; idx += 128) {
            int kk = idx / (BTF * 23), rem = idx % (BTF * 23);
            int ff = rem / 23, oo = rem % 23;
            int col = (f0 + ff) * 23 + oo;
            wos[kk][ff * 28 + oo] = (col < OUT_) ? Wo[(kc + kk) * OUT_ + col] : 0.f;
        }
        for (int idx = tid; idx < KC * BTF; idx += 128) {
            int kk = idx / BTF, ff = idx % BTF;
            wos[kk][ff * 28 + 23] = 0.f;
        }
        __syncthreads();
        #pragma unroll
        for (int kk = 0; kk < KC; kk++) {
            float tv0 = ts[b_local][kc + kk];
            float tv1 = ts[b_local + 16][kc + kk];
            const float4* wp = reinterpret_cast<const float4*>(&wos[kk][f_local * 28]);
            #pragma unroll
            for (int q = 0; q < 6; q++) {
                float4 w4 = wp[q];
                acc0[q*4+0] += tv0 * w4.x; acc0[q*4+1] += tv0 * w4.y;
                acc0[q*4+2] += tv0 * w4.z; acc0[q*4+3] += tv0 * w4.w;
                acc1[q*4+0] += tv1 * w4.x; acc1[q*4+1] += tv1 * w4.y;
                acc1[q*4+2] += tv1 * w4.z; acc1[q*4+3] += tv1 * w4.w;
            }
        }
    }

    const float scale = 0.08838834764831845f;  // 1/sqrt(128)
    float ld0 = 0.f, ld1 = 0.f;

    if (f < F_) {
        {   // row 0
            float uw[8], uh[8], ud7[7];
            #pragma unroll
            for (int o = 0; o < 8; o++) {
                uw[o] = (acc0[o]     + bos[f_local * 24 + o])     * scale;
                uh[o] = (acc0[8 + o] + bos[f_local * 24 + 8 + o]) * scale;
            }
            #pragma unroll
            for (int o = 0; o < 7; o++) ud7[o] = acc0[16 + o] + bos[f_local * 24 + 16 + o];
            int b = b0 + b_local;
            float x = zn[b * LDP + 2 * f + 1];
            float o, l;
            rqs_fast(x, uw, uh, ud7, o, l);
            zout[b * LDP + 2 * f + 1] = o;
            ld0 = l;
        }
        {   // row 1
            float uw[8], uh[8], ud7[7];
            #pragma unroll
            for (int o = 0; o < 8; o++) {
                uw[o] = (acc1[o]     + bos[f_local * 24 + o])     * scale;
                uh[o] = (acc1[8 + o] + bos[f_local * 24 + 8 + o]) * scale;
            }
            #pragma unroll
            for (int o = 0; o < 7; o++) ud7[o] = acc1[16 + o] + bos[f_local * 24 + 16 + o];
            int b = b0 + b_local + 16;
            float x = zn[b * LDP + 2 * f + 1];
            float o, l;
            rqs_fast(x, uw, uh, ud7, o, l);
            zout[b * LDP + 2 * f + 1] = o;
            ld1 = l;
        }
    }
    #pragma unroll
    for (int o = 4; o > 0; o >>= 1) {
        ld0 += __shfl_xor_sync(0xffffffffu, ld0, o);
        ld1 += __shfl_xor_sync(0xffffffffu, ld1, o);
    }
    if (f_local == 0) {
        atomicAdd(&lq[b0 + b_local], ld0);
        atomicAdd(&lq[b0 + b_local + 16], ld1);
    }
}

__global__ void final_kernel(const float* __restrict__ z, const float* __restrict__ loc,
                             const float* __restrict__ lsc, const float* __restrict__ lq,
                             const float* __restrict__ slog, float* __restrict__ out)
{
    int b = blockIdx.x;
    float s = 0.f;
    for (int d = threadIdx.x; d < D_; d += blockDim.x) {
        float inv = __expf(-lsc[d]);
        float u = (z[b * LDP + d] - loc[d]) * inv;
        s += lsc[d] + 0.5f * u * u;
    }
    s = block_reduce_sum(s);
    if (threadIdx.x == 0) {
        const float c = 0.5f * 550.f * 1.8378770664093453f;
        out[b] = lq[b] + slog[0] + slog[1] + slog[2] - c - s;
    }
}

// ---------------- launch ----------------
extern "C" void kernel_launch(void* const* d_in, const int* in_sizes, int n_in,
                              void* d_out, int out_size)
{
    (void)in_sizes; (void)n_in; (void)out_size;
    const float* x      = (const float*)d_in[0];
    const float* loc    = (const float*)d_in[1];
    const float* lsc    = (const float*)d_in[2];
    const float* Wi     = (const float*)d_in[3];
    const float* bi     = (const float*)d_in[4];
    const float* Wb     = (const float*)d_in[5];
    const float* bb     = (const float*)d_in[6];
    const float* Wo     = (const float*)d_in[7];
    const float* bo     = (const float*)d_in[8];
    const float* uw_u   = (const float*)d_in[9];
    const float* uh_u   = (const float*)d_in[10];
    const float* ud_u   = (const float*)d_in[11];
    const float* lower  = (const float*)d_in[12];
    const float* upper  = (const float*)d_in[13];
    const float* lu_ud  = (const float*)d_in[14];
    const float* lu_b   = (const float*)d_in[15];
    const int*   perms  = (const int*)d_in[16];
    float* outp = (float*)d_out;

    float *z, *zn, *LT, *UpT, *ApT, *ident, *t, *r, *lq, *slog, *kn;
    cudaGetSymbolAddress((void**)&z,     g_z);
    cudaGetSymbolAddress((void**)&zn,    g_zn);
    cudaGetSymbolAddress((void**)&LT,    g_LT);
    cudaGetSymbolAddress((void**)&UpT,   g_UpT);
    cudaGetSymbolAddress((void**)&ApT,   g_ApT);
    cudaGetSymbolAddress((void**)&ident, g_id);
    cudaGetSymbolAddress((void**)&t,     g_t);
    cudaGetSymbolAddress((void**)&r,     g_r);
    cudaGetSymbolAddress((void**)&lq,    g_lq);
    cudaGetSymbolAddress((void**)&slog,  g_slog);
    cudaGetSymbolAddress((void**)&kn,    g_kn);

    auto big_gemm = [&](const float* src, const float* bias) {
        // zn = src @ ApT + bias ; K padded to 560, no k-checks
        sgemm_pad<128, 64, 8, 4, false, true>
            <<<dim3((D_ + 63) / 64, B_ / 128), 256>>>(
                src, ApT, bias, zn, B_, D_, LDP, LDP, LDP, LDP);
    };
    auto apt_gemm = [&]() {
        sgemm_pad<64, 64, 4, 4, true, false>
            <<<dim3((D_ + 63) / 64, (D_ + 63) / 64), 256>>>(
                UpT, LT, nullptr, ApT, D_, D_, LDP, LDP, LDP, LDP);
    };

    // Per-layer body after the big GEMM
    auto resnet_and_tail = [&](int i) {
        ident_knots_kernel<<<(F_ + 255) / 256, 256>>>(
            uw_u + i * F_ * 8, uh_u + i * F_ * 8, ud_u + i * F_ * 7, kn);
        ident_eval_kernel<<<dim3((F_ + 31) / 32, B_ / 8), 256>>>(
            zn, kn, ident, z, lq);
        gemm_k<64, 64, 16, 4, 4, false, false>
            <<<dim3(2, B_ / 64), 256>>>(ident, Wi + i * F_ * H_, bi + i * H_, nullptr,
                                        t, B_, H_, F_, LDF, H_, H_);
        gemm_k<64, 64, 16, 4, 4, true, false>
            <<<dim3(2, B_ / 64), 256>>>(t, Wb + (i * 4 + 0) * H_ * H_, bb + (i * 4 + 0) * H_,
                                        nullptr, r, B_, H_, H_, H_, H_, H_);
        gemm_k<64, 64, 16, 4, 4, true, true>
            <<<dim3(2, B_ / 64), 256>>>(r, Wb + (i * 4 + 1) * H_ * H_, bb + (i * 4 + 1) * H_,
                                        t, t, B_, H_, H_, H_, H_, H_);
        gemm_k<64, 64, 16, 4, 4, true, false>
            <<<dim3(2, B_ / 64), 256>>>(t, Wb + (i * 4 + 2) * H_ * H_, bb + (i * 4 + 2) * H_,
                                        nullptr, r, B_, H_, H_, H_, H_, H_);
        gemm_k<64, 64, 16, 4, 4, true, true>
            <<<dim3(2, B_ / 64), 256>>>(r, Wb + (i * 4 + 3) * H_ * H_, bb + (i * 4 + 3) * H_,
                                        t, t, B_, H_, H_, H_, H_, H_);
        wo_spline_kernel<<<dim3((F_ + 7) / 8, B_ / 32), 128>>>(
            t, Wo + i * H_ * OUT_, bo + i * OUT_, zn, z, lq);
    };

    // ---- layer 2 prelude, ordered so the BIG GEMM is launch index 3 (ncu) ----
    build_lt_upt_kernel<<<dim3((D_ + 255) / 256, D_, 2), 256>>>(          // 0
        lower + 2 * D_ * D_, upper + 2 * D_ * D_, lu_ud + 2 * D_, perms + 2 * D_, LT, UpT);
    apt_gemm();                                                            // 1
    copy_pad_kernel<<<(B_ * D_ + 255) / 256, 256>>>(x, z);                 // 2
    big_gemm(z, lu_b + 2 * D_);                                            // 3 <- profiled
    zero_kernel<<<(B_ + 255) / 256, 256>>>(lq, B_);                        // 4
    sumlog_kernel<<<3, 256>>>(lu_ud, slog);                                // 5
    resnet_and_tail(2);

    for (int i = 1; i >= 0; i--) {
        build_lt_upt_kernel<<<dim3((D_ + 255) / 256, D_, 2), 256>>>(
            lower + i * D_ * D_, upper + i * D_ * D_,
            lu_ud + i * D_, perms + i * D_, LT, UpT);
        apt_gemm();
        big_gemm(z, lu_b + i * D_);
        resnet_and_tail(i);
    }

    final_kernel<<<B_, 256>>>(z, loc, lsc, lq, slog, outp);
}

// round 6
// speedup vs baseline: 1.8994x; 1.0965x over previous
#include <cuda_runtime.h>
#include <math.h>

// ---------------- problem constants ----------------
namespace {
constexpr int D_   = 550;
constexpr int LDP  = 560;    // padded lead dim: 35*16, all pads guaranteed zero
constexpr int MATR = 576;    // matrix buffer rows (covers 9*64 tile overreach)
constexpr int F_   = 275;
constexpr int LDF  = 276;    // padded ident stride
constexpr int B_   = 4096;   // N*T = 8*512
constexpr int H_   = 128;
constexpr int OUT_ = 6325;   // F_*(3*8-1)
}

// ---------------- scratch (device globals; no allocs allowed) ----------------
__device__ float g_z  [B_*LDP];   // zero-init => pad cols stay 0
__device__ float g_zn [B_*LDP];
__device__ float g_LT [MATR*LDP];
__device__ float g_UpT[MATR*LDP];
__device__ float g_ApT[MATR*LDP];
__device__ float g_id [B_*LDF];
__device__ float g_t  [B_*H_];
__device__ float g_r  [B_*H_];
__device__ float g_lq [B_];
__device__ float g_slog[3];
__device__ float g_kn [F_*27];    // per-f ident knots: cw[9], ch[9], dd[9]

// ---------------- helpers ----------------
__device__ __forceinline__ float softplus_acc(float x) {   // accurate (precompute only)
    return (x > 20.f) ? x : log1pf(__expf(x));
}
__device__ __forceinline__ float softplus_fast(float x) {
    return (x > 15.f) ? x : __logf(1.f + __expf(x));
}

__device__ __forceinline__ float block_reduce_sum(float v) {
    __shared__ float sred[32];
    int tid = threadIdx.x;
    #pragma unroll
    for (int o = 16; o > 0; o >>= 1) v += __shfl_down_sync(0xffffffffu, v, o);
    if ((tid & 31) == 0) sred[tid >> 5] = v;
    __syncthreads();
    if (tid < 32) {
        int nw = (blockDim.x + 31) >> 5;
        v = (tid < nw) ? sred[tid] : 0.f;
        #pragma unroll
        for (int o = 16; o > 0; o >>= 1) v += __shfl_down_sync(0xffffffffu, v, o);
    }
    return v;  // valid in thread 0
}

// Fast inverse RQS, params in registers (conditional path).
__device__ __forceinline__ void rqs_fast(float x, const float* uw, const float* uh,
                                         const float* ud7, float& out, float& ld)
{
    const float TB = 3.f;
    bool inside = (x >= -TB) && (x <= TB);
    float xi = fminf(fmaxf(x, -TB), TB);

    float cw[9], ch[9];
    {
        float m = uw[0];
        #pragma unroll
        for (int k = 1; k < 8; k++) m = fmaxf(m, uw[k]);
        float e[8]; float s = 0.f;
        #pragma unroll
        for (int k = 0; k < 8; k++) { e[k] = __expf(uw[k] - m); s += e[k]; }
        float inv = __fdividef(1.f, s);
        float cum = 0.f;
        cw[0] = -TB;
        #pragma unroll
        for (int k = 0; k < 7; k++) { cum += 0.001f + 0.992f * e[k] * inv; cw[k+1] = 6.f * cum - 3.f; }
        cw[8] = TB;
    }
    {
        float m = uh[0];
        #pragma unroll
        for (int k = 1; k < 8; k++) m = fmaxf(m, uh[k]);
        float e[8]; float s = 0.f;
        #pragma unroll
        for (int k = 0; k < 8; k++) { e[k] = __expf(uh[k] - m); s += e[k]; }
        float inv = __fdividef(1.f, s);
        float cum = 0.f;
        ch[0] = -TB;
        #pragma unroll
        for (int k = 0; k < 7; k++) { cum += 0.001f + 0.992f * e[k] * inv; ch[k+1] = 6.f * cum - 3.f; }
        ch[8] = TB;
    }

    // bin search on height knots
    int cnt = 0;
    #pragma unroll
    for (int k = 0; k < 9; k++) {
        float lo = ch[k] + (k == 8 ? 1e-6f : 0.f);
        cnt += (xi >= lo) ? 1 : 0;
    }
    int idx = cnt - 1; idx = idx < 0 ? 0 : (idx > 7 ? 7 : idx);

    float icw = 0.f, iw = 1.f, ich = 0.f, ih = 1.f;
    float u0 = 0.f, u1 = 0.f;
    #pragma unroll
    for (int k = 0; k < 8; k++) {
        if (k == idx) {
            icw = cw[k]; iw = cw[k+1] - cw[k];
            ich = ch[k]; ih = ch[k+1] - ch[k];
        }
    }
    #pragma unroll
    for (int k = 0; k < 7; k++) {
        if (k == idx - 1) u0 = ud7[k];
        if (k == idx)     u1 = ud7[k];
    }
    // boundary derivative is exactly MIND + softplus(DCONST) = 1.0
    float d0 = (idx == 0) ? 1.f : 0.001f + softplus_fast(u0);
    float d1 = (idx == 7) ? 1.f : 0.001f + softplus_fast(u1);

    float delta = __fdividef(ih, iw);
    float t  = xi - ich;
    float s2 = d0 + d1 - 2.f * delta;
    float aa = t * s2 + ih * (delta - d0);
    float bb = ih * d0 - t * s2;
    float cc = -delta * t;
    float disc = bb * bb - 4.f * aa * cc;
    float sq = disc * __frsqrt_rn(fmaxf(disc, 1e-37f));
    float root = __fdividef(2.f * cc, -bb - sq);
    float o = root * iw + icw;
    float tm = root * (1.f - root);
    float den = delta + s2 * tm;
    float omr = 1.f - root;
    float dnum = delta * delta * (d1 * root * root + 2.f * delta * tm + d0 * omr * omr);
    float l = -__logf(__fdividef(dnum, den * den));

    out = inside ? o : x;
    ld  = inside ? l : 0.f;
}

// ---------------- small kernels ----------------
__global__ void zero_kernel(float* p, int n) {
    int i = blockIdx.x * blockDim.x + threadIdx.x;
    if (i < n) p[i] = 0.f;
}

__global__ void copy_pad_kernel(const float* __restrict__ x, float* __restrict__ z) {
    int i = blockIdx.x * blockDim.x + threadIdx.x;
    if (i >= B_ * D_) return;
    int b = i / D_, d = i % D_;
    z[b * LDP + d] = x[i];
}

__global__ void sumlog_kernel(const float* __restrict__ lu_ud, float* __restrict__ out) {
    int i = blockIdx.x;  // layer
    float s = 0.f;
    for (int d = threadIdx.x; d < D_; d += blockDim.x)
        s += __logf(softplus_acc(lu_ud[i * D_ + d]) + 0.001f);
    s = block_reduce_sum(s);
    if (threadIdx.x == 0) out[i] = s;
}

// Per-f knots for the unconditional (ident) spline: cw[9], ch[9], dd[9]
__global__ void ident_knots_kernel(const float* __restrict__ uw_u,
                                   const float* __restrict__ uh_u,
                                   const float* __restrict__ ud_u,
                                   float* __restrict__ kn)
{
    int f = blockIdx.x * blockDim.x + threadIdx.x;
    if (f >= F_) return;
    const float TB = 3.f;
    float* o = kn + f * 27;
    {
        const float* u = uw_u + f * 8;
        float m = u[0];
        #pragma unroll
        for (int k = 1; k < 8; k++) m = fmaxf(m, u[k]);
        float e[8]; float s = 0.f;
        #pragma unroll
        for (int k = 0; k < 8; k++) { e[k] = __expf(u[k] - m); s += e[k]; }
        float inv = 1.f / s;
        float cum = 0.f;
        o[0] = -TB;
        #pragma unroll
        for (int k = 0; k < 7; k++) { cum += 0.001f + 0.992f * e[k] * inv; o[k+1] = 6.f * cum - 3.f; }
        o[8] = TB;
    }
    {
        const float* u = uh_u + f * 8;
        float m = u[0];
        #pragma unroll
        for (int k = 1; k < 8; k++) m = fmaxf(m, u[k]);
        float e[8]; float s = 0.f;
        #pragma unroll
        for (int k = 0; k < 8; k++) { e[k] = __expf(u[k] - m); s += e[k]; }
        float inv = 1.f / s;
        float cum = 0.f;
        o[9] = -TB;
        #pragma unroll
        for (int k = 0; k < 7; k++) { cum += 0.001f + 0.992f * e[k] * inv; o[10+k] = 6.f * cum - 3.f; }
        o[17] = TB;
    }
    o[18] = 1.f; o[26] = 1.f;
    #pragma unroll
    for (int k = 0; k < 7; k++) o[19 + k] = 0.001f + softplus_acc(ud_u[f * 7 + k]);
}

// Table-driven ident spline eval. Block = 32 f x 8 b (256 thr).
__global__ void __launch_bounds__(256)
ident_eval_kernel(const float* __restrict__ zn, const float* __restrict__ kn,
                  float* __restrict__ ident, float* __restrict__ zout,
                  float* __restrict__ lq)
{
    __shared__ float sk[32][29];
    int tid = threadIdx.x;
    int f_local = tid & 31;
    int b_local = tid >> 5;
    int f0 = blockIdx.x * 32;
    int b  = blockIdx.y * 8 + b_local;

    for (int j = tid; j < 32 * 27; j += 256) {
        int fl = j / 27, e = j % 27;
        int f = f0 + fl;
        sk[fl][e] = (f < F_) ? kn[f * 27 + e] : 0.f;
    }
    __syncthreads();

    int f = f0 + f_local;
    float ldv = 0.f;
    if (f < F_) {
        const float TB = 3.f;
        const float* K = sk[f_local];
        float x = zn[b * LDP + 2 * f];
        bool inside = (x >= -TB) && (x <= TB);
        float xi = fminf(fmaxf(x, -TB), TB);

        int cnt = 0;
        #pragma unroll
        for (int k = 0; k < 9; k++) {
            float lo = K[9 + k] + (k == 8 ? 1e-6f : 0.f);
            cnt += (xi >= lo) ? 1 : 0;
        }
        int idx = cnt - 1; idx = idx < 0 ? 0 : (idx > 7 ? 7 : idx);

        float icw = K[idx],     iw = K[idx + 1] - icw;
        float ich = K[9 + idx], ih = K[10 + idx] - ich;
        float d0  = K[18 + idx], d1 = K[19 + idx];

        float delta = __fdividef(ih, iw);
        float t  = xi - ich;
        float s2 = d0 + d1 - 2.f * delta;
        float aa = t * s2 + ih * (delta - d0);
        float bb = ih * d0 - t * s2;
        float cc = -delta * t;
        float disc = bb * bb - 4.f * aa * cc;
        float sq = disc * __frsqrt_rn(fmaxf(disc, 1e-37f));
        float root = __fdividef(2.f * cc, -bb - sq);
        float o = root * iw + icw;
        float tm = root * (1.f - root);
        float den = delta + s2 * tm;
        float omr = 1.f - root;
        float dnum = delta * delta * (d1 * root * root + 2.f * delta * tm + d0 * omr * omr);
        float l = -__logf(__fdividef(dnum, den * den));

        float ov = inside ? o : x;
        ldv = inside ? l : 0.f;
        ident[b * LDF + f] = ov;
        zout[b * LDP + 2 * f] = ov;
    }
    #pragma unroll
    for (int o = 16; o > 0; o >>= 1) ldv += __shfl_xor_sync(0xffffffffu, ldv, o);
    if (f_local == 0) atomicAdd(&lq[b], ldv);
}

// Materialize LT[m,d] = L[d,m] (unit diag) and UpT[perm[k], m] = Udense[m,k].
__global__ void build_lt_upt_kernel(const float* __restrict__ lower,
                                    const float* __restrict__ upper,
                                    const float* __restrict__ lu_ud,
                                    const int* __restrict__ perm,
                                    float* __restrict__ LT, float* __restrict__ UpT)
{
    int c = blockIdx.x * blockDim.x + threadIdx.x;
    int rr = blockIdx.y;
    if (c >= D_) return;
    if (blockIdx.z == 0) {
        int m = rr, d = c;
        float v = (m < d) ? lower[d * D_ + m] : ((m == d) ? 1.f : 0.f);
        LT[m * LDP + d] = v;
    } else {
        int k = rr, m = c;
        float v;
        if (m < k)       v = upper[m * D_ + k];
        else if (m == k) v = softplus_acc(lu_ud[k]) + 0.001f;
        else             v = 0.f;
        UpT[perm[k] * LDP + m] = v;
    }
}

// ---------------- padded SGEMM: C = A @ B + bias ----------------
// Requires: K % 16 == 0, rows of A/B beyond M/valid-K are readable and the
// products they generate only land in discarded (gn >= N) outputs.
// A: [M x lda] row-major; B: [K x ldb] row-major.
template<int BM, int BN, int TM, int TN, bool GUARDM, bool HASB>
__global__ void __launch_bounds__((BM/TM)*(BN/TN))
sgemm_pad(const float* __restrict__ A, const float* __restrict__ Bm,
          const float* __restrict__ bias, float* __restrict__ C,
          int M, int N, int K, int lda, int ldb, int ldc)
{
    constexpr int BK = 16;
    constexpr int TX = BN / TN, TY = BM / TM;
    constexpr int NT = TX * TY;
    __shared__ __align__(16) float As[BK][BM];
    __shared__ __align__(16) float Bs[BK][BN];
    int tid = threadIdx.x;
    int tx = tid % TX, ty = tid / TX;
    int m0 = blockIdx.y * BM, n0 = blockIdx.x * BN;

    float acc[TM][TN];
    #pragma unroll
    for (int i = 0; i < TM; i++)
        #pragma unroll
        for (int j = 0; j < TN; j++) acc[i][j] = 0.f;

    for (int k0 = 0; k0 < K; k0 += BK) {
        // A tile: BM x 16, float4 along k, transposed store
        #pragma unroll
        for (int idx = tid; idx < BM * 4; idx += NT) {
            int m = idx >> 2, k4 = (idx & 3) << 2;
            int gm = m0 + m;
            float4 v = make_float4(0.f, 0.f, 0.f, 0.f);
            if (!GUARDM || gm < M)
                v = *reinterpret_cast<const float4*>(&A[gm * lda + k0 + k4]);
            As[k4 + 0][m] = v.x; As[k4 + 1][m] = v.y;
            As[k4 + 2][m] = v.z; As[k4 + 3][m] = v.w;
        }
        // B tile: 16 x BN, float4 along n (unchecked; see contract above)
        #pragma unroll
        for (int idx = tid; idx < BN * 4; idx += NT) {
            int k = idx / (BN / 4), n4 = (idx % (BN / 4)) << 2;
            float4 v = *reinterpret_cast<const float4*>(&Bm[(k0 + k) * ldb + n0 + n4]);
            *reinterpret_cast<float4*>(&Bs[k][n4]) = v;
        }
        __syncthreads();
        #pragma unroll
        for (int kk = 0; kk < BK; kk++) {
            float a[TM], b[TN];
            #pragma unroll
            for (int i = 0; i < TM / 4; i++)
                *reinterpret_cast<float4*>(&a[4 * i]) =
                    *reinterpret_cast<const float4*>(&As[kk][ty * TM + 4 * i]);
            #pragma unroll
            for (int j = 0; j < TN / 4; j++)
                *reinterpret_cast<float4*>(&b[4 * j]) =
                    *reinterpret_cast<const float4*>(&Bs[kk][tx * TN + 4 * j]);
            #pragma unroll
            for (int i = 0; i < TM; i++)
                #pragma unroll
                for (int j = 0; j < TN; j++)
                    acc[i][j] = fmaf(a[i], b[j], acc[i][j]);
        }
        __syncthreads();
    }
    #pragma unroll
    for (int i = 0; i < TM; i++) {
        int gm = m0 + ty * TM + i;
        if (!GUARDM || gm < M) {
            #pragma unroll
            for (int j = 0; j < TN; j++) {
                int gn = n0 + tx * TN + j;
                if (gn < N) {
                    float bv = HASB ? bias[gn] : 0.f;
                    C[gm * ldc + gn] = acc[i][j] + bv;
                }
            }
        }
    }
}

// ---------------- resnet GEMM (R2 version, scalar loads) ----------------
template<int BM, int BN, int BK, int TM, int TN, bool RELUA, bool ADDC>
__global__ void __launch_bounds__((BM/TM)*(BN/TN))
gemm_k(const float* __restrict__ A, const float* __restrict__ B,
       const float* __restrict__ bias, const float* __restrict__ Cadd,
       float* __restrict__ C, int M, int N, int K, int lda, int ldb, int ldc)
{
    constexpr int TX = BN / TN, TY = BM / TM, NT = TX * TY;
    __shared__ float As[BK][BM];
    __shared__ float Bs[BK][BN];
    int tid = threadIdx.x;
    int tx = tid % TX, ty = tid / TX;
    int m0 = blockIdx.y * BM, n0 = blockIdx.x * BN;
    float acc[TM][TN];
    #pragma unroll
    for (int i = 0; i < TM; i++)
        #pragma unroll
        for (int j = 0; j < TN; j++) acc[i][j] = 0.f;

    for (int k0 = 0; k0 < K; k0 += BK) {
        #pragma unroll
        for (int idx = tid; idx < BM * BK; idx += NT) {
            int r = idx / BK, c = idx % BK;
            int gm = m0 + r, gk = k0 + c;
            float v = (gk < K) ? A[gm * lda + gk] : 0.f;
            if (RELUA) v = fmaxf(v, 0.f);
            As[c][r] = v;
        }
        #pragma unroll
        for (int idx = tid; idx < BK * BN; idx += NT) {
            int r = idx / BN, c = idx % BN;
            int gk = k0 + r, gn = n0 + c;
            Bs[r][c] = (gk < K && gn < N) ? B[gk * ldb + gn] : 0.f;
        }
        __syncthreads();
        #pragma unroll
        for (int kk = 0; kk < BK; kk++) {
            float ra[TM], rb[TN];
            #pragma unroll
            for (int i = 0; i < TM; i++) ra[i] = As[kk][ty * TM + i];
            #pragma unroll
            for (int j = 0; j < TN; j++) rb[j] = Bs[kk][tx * TN + j];
            #pragma unroll
            for (int i = 0; i < TM; i++)
                #pragma unroll
                for (int j = 0; j < TN; j++)
                    acc[i][j] += ra[i] * rb[j];
        }
        __syncthreads();
    }
    #pragma unroll
    for (int i = 0; i < TM; i++) {
        int gm = m0 + ty * TM + i;
        #pragma unroll
        for (int j = 0; j < TN; j++) {
            int gn = n0 + tx * TN + j;
            if (gn < N) {
                float v = acc[i][j] + bias[gn];
                if (ADDC) v += Cadd[gm * ldc + gn];
                C[gm * ldc + gn] = v;
            }
        }
    }
}

// Fused: p[b,f,:] = t[b,:] @ Wo[:, f*23:(f+1)*23] + bo, then conditional RQS
// inverse on trans = zn[:, 2f+1]. Block: 64 b x 8 f, 256 thr, 2 rows/thread.
__global__ void __launch_bounds__(256)
wo_spline_kernel(const float* __restrict__ tmat, const float* __restrict__ Wo,
                 const float* __restrict__ bo, const float* __restrict__ zn,
                 float* __restrict__ zout, float* __restrict__ lq)
{
    constexpr int BTB = 64, BTF = 8, KC = 16;
    __shared__ float ts[BTB][129];
    __shared__ float wos[KC][BTF * 28];
    __shared__ float bos[BTF * 24];

    int tid = threadIdx.x;
    int f_local = tid & 7;
    int b_local = tid >> 3;               // 0..31
    int b0 = blockIdx.y * BTB;
    int f0 = blockIdx.x * BTF;
    int f  = f0 + f_local;

    for (int idx = tid; idx < BTB * 128; idx += 256) {
        int r = idx >> 7, c = idx & 127;
        ts[r][c] = tmat[(b0 + r) * H_ + c];
    }
    for (int idx = tid; idx < BTF * 24; idx += 256) {
        int ff = idx / 24, oo = idx % 24;
        int col = (f0 + ff) * 23 + oo;
        bos[idx] = (oo < 23 && col < OUT_) ? bo[col] : 0.f;
    }

    float acc0[24], acc1[24];
    #pragma unroll
    for (int o = 0; o < 24; o++) { acc0[o] = 0.f; acc1[o] = 0.f; }

    for (int kc = 0; kc < H_; kc += KC) {
        __syncthreads();
        for (int idx = tid; idx < KC * BTF * 23; idx += 256) {
            int kk = idx / (BTF * 23), rem = idx % (BTF * 23);
            int ff = rem / 23, oo = rem % 23;
            int col = (f0 + ff) * 23 + oo;
            wos[kk][ff * 28 + oo] = (col < OUT_) ? Wo[(kc + kk) * OUT_ + col] : 0.f;
        }
        for (int idx = tid; idx < KC * BTF; idx += 256) {
            int kk = idx / BTF, ff = idx % BTF;
            wos[kk][ff * 28 + 23] = 0.f;
        }
        __syncthreads();
        #pragma unroll
        for (int kk = 0; kk < KC; kk++) {
            float tv0 = ts[b_local][kc + kk];
            float tv1 = ts[b_local + 32][kc + kk];
            const float4* wp = reinterpret_cast<const float4*>(&wos[kk][f_local * 28]);
            #pragma unroll
            for (int q = 0; q < 6; q++) {
                float4 w4 = wp[q];
                acc0[q*4+0] += tv0 * w4.x; acc0[q*4+1] += tv0 * w4.y;
                acc0[q*4+2] += tv0 * w4.z; acc0[q*4+3] += tv0 * w4.w;
                acc1[q*4+0] += tv1 * w4.x; acc1[q*4+1] += tv1 * w4.y;
                acc1[q*4+2] += tv1 * w4.z; acc1[q*4+3] += tv1 * w4.w;
            }
        }
    }

    const float scale = 0.08838834764831845f;  // 1/sqrt(128)
    float ld0 = 0.f, ld1 = 0.f;

    if (f < F_) {
        {   // row 0
            float uw[8], uh[8], ud7[7];
            #pragma unroll
            for (int o = 0; o < 8; o++) {
                uw[o] = (acc0[o]     + bos[f_local * 24 + o])     * scale;
                uh[o] = (acc0[8 + o] + bos[f_local * 24 + 8 + o]) * scale;
            }
            #pragma unroll
            for (int o = 0; o < 7; o++) ud7[o] = acc0[16 + o] + bos[f_local * 24 + 16 + o];
            int b = b0 + b_local;
            float x = zn[b * LDP + 2 * f + 1];
            float o, l;
            rqs_fast(x, uw, uh, ud7, o, l);
            zout[b * LDP + 2 * f + 1] = o;
            ld0 = l;
        }
        {   // row 1
            float uw[8], uh[8], ud7[7];
            #pragma unroll
            for (int o = 0; o < 8; o++) {
                uw[o] = (acc1[o]     + bos[f_local * 24 + o])     * scale;
                uh[o] = (acc1[8 + o] + bos[f_local * 24 + 8 + o]) * scale;
            }
            #pragma unroll
            for (int o = 0; o < 7; o++) ud7[o] = acc1[16 + o] + bos[f_local * 24 + 16 + o];
            int b = b0 + b_local + 32;
            float x = zn[b * LDP + 2 * f + 1];
            float o, l;
            rqs_fast(x, uw, uh, ud7, o, l);
            zout[b * LDP + 2 * f + 1] = o;
            ld1 = l;
        }
    }
    #pragma unroll
    for (int o = 4; o > 0; o >>= 1) {
        ld0 += __shfl_xor_sync(0xffffffffu, ld0, o);
        ld1 += __shfl_xor_sync(0xffffffffu, ld1, o);
    }
    if (f_local == 0) {
        atomicAdd(&lq[b0 + b_local], ld0);
        atomicAdd(&lq[b0 + b_local + 32], ld1);
    }
}

__global__ void final_kernel(const float* __restrict__ z, const float* __restrict__ loc,
                             const float* __restrict__ lsc, const float* __restrict__ lq,
                             const float* __restrict__ slog, float* __restrict__ out)
{
    int b = blockIdx.x;
    float s = 0.f;
    for (int d = threadIdx.x; d < D_; d += blockDim.x) {
        float inv = __expf(-lsc[d]);
        float u = (z[b * LDP + d] - loc[d]) * inv;
        s += lsc[d] + 0.5f * u * u;
    }
    s = block_reduce_sum(s);
    if (threadIdx.x == 0) {
        const float c = 0.5f * 550.f * 1.8378770664093453f;
        out[b] = lq[b] + slog[0] + slog[1] + slog[2] - c - s;
    }
}

// ---------------- launch ----------------
extern "C" void kernel_launch(void* const* d_in, const int* in_sizes, int n_in,
                              void* d_out, int out_size)
{
    (void)in_sizes; (void)n_in; (void)out_size;
    const float* x      = (const float*)d_in[0];
    const float* loc    = (const float*)d_in[1];
    const float* lsc    = (const float*)d_in[2];
    const float* Wi     = (const float*)d_in[3];
    const float* bi     = (const float*)d_in[4];
    const float* Wb     = (const float*)d_in[5];
    const float* bb     = (const float*)d_in[6];
    const float* Wo     = (const float*)d_in[7];
    const float* bo     = (const float*)d_in[8];
    const float* uw_u   = (const float*)d_in[9];
    const float* uh_u   = (const float*)d_in[10];
    const float* ud_u   = (const float*)d_in[11];
    const float* lower  = (const float*)d_in[12];
    const float* upper  = (const float*)d_in[13];
    const float* lu_ud  = (const float*)d_in[14];
    const float* lu_b   = (const float*)d_in[15];
    const int*   perms  = (const int*)d_in[16];
    float* outp = (float*)d_out;

    float *z, *zn, *LT, *UpT, *ApT, *ident, *t, *r, *lq, *slog, *kn;
    cudaGetSymbolAddress((void**)&z,     g_z);
    cudaGetSymbolAddress((void**)&zn,    g_zn);
    cudaGetSymbolAddress((void**)&LT,    g_LT);
    cudaGetSymbolAddress((void**)&UpT,   g_UpT);
    cudaGetSymbolAddress((void**)&ApT,   g_ApT);
    cudaGetSymbolAddress((void**)&ident, g_id);
    cudaGetSymbolAddress((void**)&t,     g_t);
    cudaGetSymbolAddress((void**)&r,     g_r);
    cudaGetSymbolAddress((void**)&lq,    g_lq);
    cudaGetSymbolAddress((void**)&slog,  g_slog);
    cudaGetSymbolAddress((void**)&kn,    g_kn);

    auto big_gemm = [&](const float* src, const float* bias) {
        // zn = src @ ApT + bias ; K padded to 560, no k-checks
        // BM=64 -> 128-thread blocks, grid 576 (~4 blocks/SM)
        sgemm_pad<64, 64, 8, 4, false, true>
            <<<dim3((D_ + 63) / 64, B_ / 64), 128>>>(
                src, ApT, bias, zn, B_, D_, LDP, LDP, LDP, LDP);
    };
    auto apt_gemm = [&]() {
        sgemm_pad<64, 64, 4, 4, true, false>
            <<<dim3((D_ + 63) / 64, (D_ + 63) / 64), 256>>>(
                UpT, LT, nullptr, ApT, D_, D_, LDP, LDP, LDP, LDP);
    };

    // Per-layer body after the big GEMM
    auto resnet_and_tail = [&](int i) {
        ident_knots_kernel<<<(F_ + 255) / 256, 256>>>(
            uw_u + i * F_ * 8, uh_u + i * F_ * 8, ud_u + i * F_ * 7, kn);
        ident_eval_kernel<<<dim3((F_ + 31) / 32, B_ / 8), 256>>>(
            zn, kn, ident, z, lq);
        gemm_k<64, 64, 16, 4, 4, false, false>
            <<<dim3(2, B_ / 64), 256>>>(ident, Wi + i * F_ * H_, bi + i * H_, nullptr,
                                        t, B_, H_, F_, LDF, H_, H_);
        gemm_k<64, 64, 16, 4, 4, true, false>
            <<<dim3(2, B_ / 64), 256>>>(t, Wb + (i * 4 + 0) * H_ * H_, bb + (i * 4 + 0) * H_,
                                        nullptr, r, B_, H_, H_, H_, H_, H_);
        gemm_k<64, 64, 16, 4, 4, true, true>
            <<<dim3(2, B_ / 64), 256>>>(r, Wb + (i * 4 + 1) * H_ * H_, bb + (i * 4 + 1) * H_,
                                        t, t, B_, H_, H_, H_, H_, H_);
        gemm_k<64, 64, 16, 4, 4, true, false>
            <<<dim3(2, B_ / 64), 256>>>(t, Wb + (i * 4 + 2) * H_ * H_, bb + (i * 4 + 2) * H_,
                                        nullptr, r, B_, H_, H_, H_, H_, H_);
        gemm_k<64, 64, 16, 4, 4, true, true>
            <<<dim3(2, B_ / 64), 256>>>(r, Wb + (i * 4 + 3) * H_ * H_, bb + (i * 4 + 3) * H_,
                                        t, t, B_, H_, H_, H_, H_, H_);
        wo_spline_kernel<<<dim3((F_ + 7) / 8, B_ / 64), 256>>>(
            t, Wo + i * H_ * OUT_, bo + i * OUT_, zn, z, lq);
    };

    // ---- layer 2 prelude, ordered so the BIG GEMM is launch index 3 (ncu) ----
    build_lt_upt_kernel<<<dim3((D_ + 255) / 256, D_, 2), 256>>>(          // 0
        lower + 2 * D_ * D_, upper + 2 * D_ * D_, lu_ud + 2 * D_, perms + 2 * D_, LT, UpT);
    apt_gemm();                                                            // 1
    copy_pad_kernel<<<(B_ * D_ + 255) / 256, 256>>>(x, z);                 // 2
    big_gemm(z, lu_b + 2 * D_);                                            // 3 <- profiled
    zero_kernel<<<(B_ + 255) / 256, 256>>>(lq, B_);                        // 4
    sumlog_kernel<<<3, 256>>>(lu_ud, slog);                                // 5
    resnet_and_tail(2);

    for (int i = 1; i >= 0; i--) {
        build_lt_upt_kernel<<<dim3((D_ + 255) / 256, D_, 2), 256>>>(
            lower + i * D_ * D_, upper + i * D_ * D_,
            lu_ud + i * D_, perms + i * D_, LT, UpT);
        apt_gemm();
        big_gemm(z, lu_b + i * D_);
        resnet_and_tail(i);
    }

    final_kernel<<<B_, 256>>>(z, loc, lsc, lq, slog, outp);
}

// round 7
// speedup vs baseline: 3.6058x; 1.8984x over previous
#include <cuda_runtime.h>
#include <math.h>

// ---------------- problem constants ----------------
namespace {
constexpr int D_   = 550;
constexpr int LDP  = 560;    // padded lead dim: 35*16, all pads guaranteed zero
constexpr int MATR = 576;    // matrix buffer rows (covers 9*64 tile overreach)
constexpr int F_   = 275;
constexpr int LDF  = 276;    // padded ident stride
constexpr int B_   = 4096;   // N*T = 8*512
constexpr int H_   = 128;
constexpr int OUT_ = 6325;   // F_*(3*8-1)
constexpr int LDW  = 6720;   // padded Wo cols: 280 features * 24
}

// ---------------- scratch (device globals; no allocs allowed) ----------------
__device__ float g_z  [B_*LDP];   // zero-init => pad cols stay 0
__device__ float g_zn [B_*LDP];
__device__ float g_LT [MATR*LDP];
__device__ float g_UpT[MATR*LDP];
__device__ float g_ApT[MATR*LDP];
__device__ float g_id [B_*LDF];
__device__ float g_t  [B_*H_];
__device__ float g_r  [B_*H_];
__device__ float g_lq [B_];
__device__ float g_slog[3];
__device__ float g_kn [F_*27];    // per-f ident knots
__device__ float g_Wop[H_*LDW];   // per-layer padded Wo (24 cols per feature)

// ---------------- helpers ----------------
__device__ __forceinline__ float softplus_acc(float x) {
    return (x > 20.f) ? x : log1pf(__expf(x));
}
__device__ __forceinline__ float softplus_fast(float x) {
    return (x > 15.f) ? x : __logf(1.f + __expf(x));
}

__device__ __forceinline__ unsigned f2tf32(float x) {
    unsigned r; asm("cvt.rna.tf32.f32 %0, %1;" : "=r"(r) : "f"(x)); return r;
}

__device__ __forceinline__ void mma_tf32(float* c,
    unsigned a0, unsigned a1, unsigned a2, unsigned a3,
    unsigned b0, unsigned b1)
{
    asm volatile(
        "mma.sync.aligned.m16n8k8.row.col.f32.tf32.tf32.f32 "
        "{%0,%1,%2,%3}, {%4,%5,%6,%7}, {%8,%9}, {%0,%1,%2,%3};\n"
        : "+f"(c[0]), "+f"(c[1]), "+f"(c[2]), "+f"(c[3])
        : "r"(a0), "r"(a1), "r"(a2), "r"(a3), "r"(b0), "r"(b1));
}

__device__ __forceinline__ float block_reduce_sum(float v) {
    __shared__ float sred[32];
    int tid = threadIdx.x;
    #pragma unroll
    for (int o = 16; o > 0; o >>= 1) v += __shfl_down_sync(0xffffffffu, v, o);
    if ((tid & 31) == 0) sred[tid >> 5] = v;
    __syncthreads();
    if (tid < 32) {
        int nw = (blockDim.x + 31) >> 5;
        v = (tid < nw) ? sred[tid] : 0.f;
        #pragma unroll
        for (int o = 16; o > 0; o >>= 1) v += __shfl_down_sync(0xffffffffu, v, o);
    }
    return v;
}

// Fast inverse RQS, params in registers (conditional path).
__device__ __forceinline__ void rqs_fast(float x, const float* uw, const float* uh,
                                         const float* ud7, float& out, float& ld)
{
    const float TB = 3.f;
    bool inside = (x >= -TB) && (x <= TB);
    float xi = fminf(fmaxf(x, -TB), TB);

    float cw[9], ch[9];
    {
        float m = uw[0];
        #pragma unroll
        for (int k = 1; k < 8; k++) m = fmaxf(m, uw[k]);
        float e[8]; float s = 0.f;
        #pragma unroll
        for (int k = 0; k < 8; k++) { e[k] = __expf(uw[k] - m); s += e[k]; }
        float inv = __fdividef(1.f, s);
        float cum = 0.f;
        cw[0] = -TB;
        #pragma unroll
        for (int k = 0; k < 7; k++) { cum += 0.001f + 0.992f * e[k] * inv; cw[k+1] = 6.f * cum - 3.f; }
        cw[8] = TB;
    }
    {
        float m = uh[0];
        #pragma unroll
        for (int k = 1; k < 8; k++) m = fmaxf(m, uh[k]);
        float e[8]; float s = 0.f;
        #pragma unroll
        for (int k = 0; k < 8; k++) { e[k] = __expf(uh[k] - m); s += e[k]; }
        float inv = __fdividef(1.f, s);
        float cum = 0.f;
        ch[0] = -TB;
        #pragma unroll
        for (int k = 0; k < 7; k++) { cum += 0.001f + 0.992f * e[k] * inv; ch[k+1] = 6.f * cum - 3.f; }
        ch[8] = TB;
    }

    int cnt = 0;
    #pragma unroll
    for (int k = 0; k < 9; k++) {
        float lo = ch[k] + (k == 8 ? 1e-6f : 0.f);
        cnt += (xi >= lo) ? 1 : 0;
    }
    int idx = cnt - 1; idx = idx < 0 ? 0 : (idx > 7 ? 7 : idx);

    float icw = 0.f, iw = 1.f, ich = 0.f, ih = 1.f;
    float u0 = 0.f, u1 = 0.f;
    #pragma unroll
    for (int k = 0; k < 8; k++) {
        if (k == idx) {
            icw = cw[k]; iw = cw[k+1] - cw[k];
            ich = ch[k]; ih = ch[k+1] - ch[k];
        }
    }
    #pragma unroll
    for (int k = 0; k < 7; k++) {
        if (k == idx - 1) u0 = ud7[k];
        if (k == idx)     u1 = ud7[k];
    }
    float d0 = (idx == 0) ? 1.f : 0.001f + softplus_fast(u0);
    float d1 = (idx == 7) ? 1.f : 0.001f + softplus_fast(u1);

    float delta = __fdividef(ih, iw);
    float t  = xi - ich;
    float s2 = d0 + d1 - 2.f * delta;
    float aa = t * s2 + ih * (delta - d0);
    float bb = ih * d0 - t * s2;
    float cc = -delta * t;
    float disc = bb * bb - 4.f * aa * cc;
    float sq = disc * __frsqrt_rn(fmaxf(disc, 1e-37f));
    float root = __fdividef(2.f * cc, -bb - sq);
    float o = root * iw + icw;
    float tm = root * (1.f - root);
    float den = delta + s2 * tm;
    float omr = 1.f - root;
    float dnum = delta * delta * (d1 * root * root + 2.f * delta * tm + d0 * omr * omr);
    float l = -__logf(__fdividef(dnum, den * den));

    out = inside ? o : x;
    ld  = inside ? l : 0.f;
}

// ---------------- small kernels ----------------
__global__ void zero_kernel(float* p, int n) {
    int i = blockIdx.x * blockDim.x + threadIdx.x;
    if (i < n) p[i] = 0.f;
}

__global__ void copy_pad_kernel(const float* __restrict__ x, float* __restrict__ z) {
    int i = blockIdx.x * blockDim.x + threadIdx.x;
    if (i >= B_ * D_) return;
    int b = i / D_, d = i % D_;
    z[b * LDP + d] = x[i];
}

__global__ void sumlog_kernel(const float* __restrict__ lu_ud, float* __restrict__ out) {
    int i = blockIdx.x;
    float s = 0.f;
    for (int d = threadIdx.x; d < D_; d += blockDim.x)
        s += __logf(softplus_acc(lu_ud[i * D_ + d]) + 0.001f);
    s = block_reduce_sum(s);
    if (threadIdx.x == 0) out[i] = s;
}

// Pad Wo[k, f*23+o] -> Wop[k, f*24+o] (o=23 pad = 0; features >= F_ stay 0)
__global__ void prep_wop_kernel(const float* __restrict__ Wo, float* __restrict__ Wop) {
    int idx = blockIdx.x * blockDim.x + threadIdx.x;
    if (idx >= H_ * LDW) return;
    int k = idx / LDW, c = idx % LDW;
    int f = c / 24, o = c % 24;
    float v = 0.f;
    if (o < 23 && f < F_) v = Wo[k * OUT_ + f * 23 + o];
    Wop[idx] = v;
}

// Per-f knots for the unconditional (ident) spline
__global__ void ident_knots_kernel(const float* __restrict__ uw_u,
                                   const float* __restrict__ uh_u,
                                   const float* __restrict__ ud_u,
                                   float* __restrict__ kn)
{
    int f = blockIdx.x * blockDim.x + threadIdx.x;
    if (f >= F_) return;
    const float TB = 3.f;
    float* o = kn + f * 27;
    {
        const float* u = uw_u + f * 8;
        float m = u[0];
        #pragma unroll
        for (int k = 1; k < 8; k++) m = fmaxf(m, u[k]);
        float e[8]; float s = 0.f;
        #pragma unroll
        for (int k = 0; k < 8; k++) { e[k] = __expf(u[k] - m); s += e[k]; }
        float inv = 1.f / s;
        float cum = 0.f;
        o[0] = -TB;
        #pragma unroll
        for (int k = 0; k < 7; k++) { cum += 0.001f + 0.992f * e[k] * inv; o[k+1] = 6.f * cum - 3.f; }
        o[8] = TB;
    }
    {
        const float* u = uh_u + f * 8;
        float m = u[0];
        #pragma unroll
        for (int k = 1; k < 8; k++) m = fmaxf(m, u[k]);
        float e[8]; float s = 0.f;
        #pragma unroll
        for (int k = 0; k < 8; k++) { e[k] = __expf(u[k] - m); s += e[k]; }
        float inv = 1.f / s;
        float cum = 0.f;
        o[9] = -TB;
        #pragma unroll
        for (int k = 0; k < 7; k++) { cum += 0.001f + 0.992f * e[k] * inv; o[10+k] = 6.f * cum - 3.f; }
        o[17] = TB;
    }
    o[18] = 1.f; o[26] = 1.f;
    #pragma unroll
    for (int k = 0; k < 7; k++) o[19 + k] = 0.001f + softplus_acc(ud_u[f * 7 + k]);
}

// Table-driven ident spline eval. Block = 32 f x 8 b (256 thr).
__global__ void __launch_bounds__(256)
ident_eval_kernel(const float* __restrict__ zn, const float* __restrict__ kn,
                  float* __restrict__ ident, float* __restrict__ zout,
                  float* __restrict__ lq)
{
    __shared__ float sk[32][29];
    int tid = threadIdx.x;
    int f_local = tid & 31;
    int b_local = tid >> 5;
    int f0 = blockIdx.x * 32;
    int b  = blockIdx.y * 8 + b_local;

    for (int j = tid; j < 32 * 27; j += 256) {
        int fl = j / 27, e = j % 27;
        int f = f0 + fl;
        sk[fl][e] = (f < F_) ? kn[f * 27 + e] : 0.f;
    }
    __syncthreads();

    int f = f0 + f_local;
    float ldv = 0.f;
    if (f < F_) {
        const float TB = 3.f;
        const float* K = sk[f_local];
        float x = zn[b * LDP + 2 * f];
        bool inside = (x >= -TB) && (x <= TB);
        float xi = fminf(fmaxf(x, -TB), TB);

        int cnt = 0;
        #pragma unroll
        for (int k = 0; k < 9; k++) {
            float lo = K[9 + k] + (k == 8 ? 1e-6f : 0.f);
            cnt += (xi >= lo) ? 1 : 0;
        }
        int idx = cnt - 1; idx = idx < 0 ? 0 : (idx > 7 ? 7 : idx);

        float icw = K[idx],     iw = K[idx + 1] - icw;
        float ich = K[9 + idx], ih = K[10 + idx] - ich;
        float d0  = K[18 + idx], d1 = K[19 + idx];

        float delta = __fdividef(ih, iw);
        float t  = xi - ich;
        float s2 = d0 + d1 - 2.f * delta;
        float aa = t * s2 + ih * (delta - d0);
        float bb = ih * d0 - t * s2;
        float cc = -delta * t;
        float disc = bb * bb - 4.f * aa * cc;
        float sq = disc * __frsqrt_rn(fmaxf(disc, 1e-37f));
        float root = __fdividef(2.f * cc, -bb - sq);
        float o = root * iw + icw;
        float tm = root * (1.f - root);
        float den = delta + s2 * tm;
        float omr = 1.f - root;
        float dnum = delta * delta * (d1 * root * root + 2.f * delta * tm + d0 * omr * omr);
        float l = -__logf(__fdividef(dnum, den * den));

        float ov = inside ? o : x;
        ldv = inside ? l : 0.f;
        ident[b * LDF + f] = ov;
        zout[b * LDP + 2 * f] = ov;
    }
    #pragma unroll
    for (int o = 16; o > 0; o >>= 1) ldv += __shfl_xor_sync(0xffffffffu, ldv, o);
    if (f_local == 0) atomicAdd(&lq[b], ldv);
}

// Materialize LT[m,d] = L[d,m] (unit diag) and UpT[perm[k], m] = Udense[m,k].
__global__ void build_lt_upt_kernel(const float* __restrict__ lower,
                                    const float* __restrict__ upper,
                                    const float* __restrict__ lu_ud,
                                    const int* __restrict__ perm,
                                    float* __restrict__ LT, float* __restrict__ UpT)
{
    int c = blockIdx.x * blockDim.x + threadIdx.x;
    int rr = blockIdx.y;
    if (c >= D_) return;
    if (blockIdx.z == 0) {
        int m = rr, d = c;
        float v = (m < d) ? lower[d * D_ + m] : ((m == d) ? 1.f : 0.f);
        LT[m * LDP + d] = v;
    } else {
        int k = rr, m = c;
        float v;
        if (m < k)       v = upper[m * D_ + k];
        else if (m == k) v = softplus_acc(lu_ud[k]) + 0.001f;
        else             v = 0.f;
        UpT[perm[k] * LDP + m] = v;
    }
}

// ---------------- padded SGEMM: C = A @ B + bias ----------------
template<int BM, int BN, int TM, int TN, bool GUARDM, bool HASB>
__global__ void __launch_bounds__((BM/TM)*(BN/TN))
sgemm_pad(const float* __restrict__ A, const float* __restrict__ Bm,
          const float* __restrict__ bias, float* __restrict__ C,
          int M, int N, int K, int lda, int ldb, int ldc)
{
    constexpr int BK = 16;
    constexpr int TX = BN / TN, TY = BM / TM;
    constexpr int NT = TX * TY;
    __shared__ __align__(16) float As[BK][BM];
    __shared__ __align__(16) float Bs[BK][BN];
    int tid = threadIdx.x;
    int tx = tid % TX, ty = tid / TX;
    int m0 = blockIdx.y * BM, n0 = blockIdx.x * BN;

    float acc[TM][TN];
    #pragma unroll
    for (int i = 0; i < TM; i++)
        #pragma unroll
        for (int j = 0; j < TN; j++) acc[i][j] = 0.f;

    for (int k0 = 0; k0 < K; k0 += BK) {
        #pragma unroll
        for (int idx = tid; idx < BM * 4; idx += NT) {
            int m = idx >> 2, k4 = (idx & 3) << 2;
            int gm = m0 + m;
            float4 v = make_float4(0.f, 0.f, 0.f, 0.f);
            if (!GUARDM || gm < M)
                v = *reinterpret_cast<const float4*>(&A[gm * lda + k0 + k4]);
            As[k4 + 0][m] = v.x; As[k4 + 1][m] = v.y;
            As[k4 + 2][m] = v.z; As[k4 + 3][m] = v.w;
        }
        #pragma unroll
        for (int idx = tid; idx < BN * 4; idx += NT) {
            int k = idx / (BN / 4), n4 = (idx % (BN / 4)) << 2;
            float4 v = *reinterpret_cast<const float4*>(&Bm[(k0 + k) * ldb + n0 + n4]);
            *reinterpret_cast<float4*>(&Bs[k][n4]) = v;
        }
        __syncthreads();
        #pragma unroll
        for (int kk = 0; kk < BK; kk++) {
            float a[TM], b[TN];
            #pragma unroll
            for (int i = 0; i < TM / 4; i++)
                *reinterpret_cast<float4*>(&a[4 * i]) =
                    *reinterpret_cast<const float4*>(&As[kk][ty * TM + 4 * i]);
            #pragma unroll
            for (int j = 0; j < TN / 4; j++)
                *reinterpret_cast<float4*>(&b[4 * j]) =
                    *reinterpret_cast<const float4*>(&Bs[kk][tx * TN + 4 * j]);
            #pragma unroll
            for (int i = 0; i < TM; i++)
                #pragma unroll
                for (int j = 0; j < TN; j++)
                    acc[i][j] = fmaf(a[i], b[j], acc[i][j]);
        }
        __syncthreads();
    }
    #pragma unroll
    for (int i = 0; i < TM; i++) {
        int gm = m0 + ty * TM + i;
        if (!GUARDM || gm < M) {
            #pragma unroll
            for (int j = 0; j < TN; j++) {
                int gn = n0 + tx * TN + j;
                if (gn < N) {
                    float bv = HASB ? bias[gn] : 0.f;
                    C[gm * ldc + gn] = acc[i][j] + bv;
                }
            }
        }
    }
}

// ---------------- resnet GEMM (scalar loads; do not touch) ----------------
template<int BM, int BN, int BK, int TM, int TN, bool RELUA, bool ADDC>
__global__ void __launch_bounds__((BM/TM)*(BN/TN))
gemm_k(const float* __restrict__ A, const float* __restrict__ B,
       const float* __restrict__ bias, const float* __restrict__ Cadd,
       float* __restrict__ C, int M, int N, int K, int lda, int ldb, int ldc)
{
    constexpr int TX = BN / TN, TY = BM / TM, NT = TX * TY;
    __shared__ float As[BK][BM];
    __shared__ float Bs[BK][BN];
    int tid = threadIdx.x;
    int tx = tid % TX, ty = tid / TX;
    int m0 = blockIdx.y * BM, n0 = blockIdx.x * BN;
    float acc[TM][TN];
    #pragma unroll
    for (int i = 0; i < TM; i++)
        #pragma unroll
        for (int j = 0; j < TN; j++) acc[i][j] = 0.f;

    for (int k0 = 0; k0 < K; k0 += BK) {
        #pragma unroll
        for (int idx = tid; idx < BM * BK; idx += NT) {
            int r = idx / BK, c = idx % BK;
            int gm = m0 + r, gk = k0 + c;
            float v = (gk < K) ? A[gm * lda + gk] : 0.f;
            if (RELUA) v = fmaxf(v, 0.f);
            As[c][r] = v;
        }
        #pragma unroll
        for (int idx = tid; idx < BK * BN; idx += NT) {
            int r = idx / BN, c = idx % BN;
            int gk = k0 + r, gn = n0 + c;
            Bs[r][c] = (gk < K && gn < N) ? B[gk * ldb + gn] : 0.f;
        }
        __syncthreads();
        #pragma unroll
        for (int kk = 0; kk < BK; kk++) {
            float ra[TM], rb[TN];
            #pragma unroll
            for (int i = 0; i < TM; i++) ra[i] = As[kk][ty * TM + i];
            #pragma unroll
            for (int j = 0; j < TN; j++) rb[j] = Bs[kk][tx * TN + j];
            #pragma unroll
            for (int i = 0; i < TM; i++)
                #pragma unroll
                for (int j = 0; j < TN; j++)
                    acc[i][j] += ra[i] * rb[j];
        }
        __syncthreads();
    }
    #pragma unroll
    for (int i = 0; i < TM; i++) {
        int gm = m0 + ty * TM + i;
        #pragma unroll
        for (int j = 0; j < TN; j++) {
            int gn = n0 + tx * TN + j;
            if (gn < N) {
                float v = acc[i][j] + bias[gn];
                if (ADDC) v += Cadd[gm * ldc + gn];
                C[gm * ldc + gn] = v;
            }
        }
    }
}

// ---------------- tf32 tensor-core fused Wo GEMM + conditional spline ----------
// Block: 64 batch rows x 192 cols (8 features x 24). 256 thr = 8 warps.
// Warp (w&3) -> m-tile base (w&3)*16 ; (w>>2) -> n-group base (w>>2)*96 (12 n-frags).
// Dynamic smem: phase1 { As[64][36], Bs[32][200] } aliased with Cs[64][200].
__global__ void __launch_bounds__(256)
wo_spline_tc(const float* __restrict__ tmat, const float* __restrict__ Wop,
             const float* __restrict__ bo, const float* __restrict__ zn,
             float* __restrict__ zout, float* __restrict__ lq)
{
    extern __shared__ float sm[];
    float (*As)[36]  = reinterpret_cast<float(*)[36]>(sm);            // 64x36
    float (*Bs)[200] = reinterpret_cast<float(*)[200]>(sm + 64 * 36); // 32x200
    float (*Cs)[200] = reinterpret_cast<float(*)[200]>(sm);           // 64x200 (aliases)
    __shared__ float bos[192];

    int tid  = threadIdx.x;
    int warp = tid >> 5, lane = tid & 31;
    int mw = (warp & 3) * 16;
    int nw = (warp >> 2) * 96;
    int b0 = blockIdx.y * 64;
    int f0 = blockIdx.x * 8;
    int n0 = blockIdx.x * 192;

    for (int i = tid; i < 192; i += 256) {
        int ff = i / 24, oo = i % 24;
        int col = (f0 + ff) * 23 + oo;
        bos[i] = (oo < 23 && col < OUT_) ? bo[col] : 0.f;
    }

    float c[12][4];
    #pragma unroll
    for (int i = 0; i < 12; i++) { c[i][0] = c[i][1] = c[i][2] = c[i][3] = 0.f; }

    int g = lane >> 2, t4 = lane & 3;

    for (int kc = 0; kc < H_; kc += 32) {
        __syncthreads();
        // A tile 64x32 (tf32-converted)
        #pragma unroll
        for (int i = 0; i < 2; i++) {
            int idx = tid + i * 256;           // 512 float4 slots
            int r = idx >> 3, c4 = (idx & 7) << 2;
            float4 v = *reinterpret_cast<const float4*>(&tmat[(b0 + r) * H_ + kc + c4]);
            As[r][c4 + 0] = __uint_as_float(f2tf32(v.x));
            As[r][c4 + 1] = __uint_as_float(f2tf32(v.y));
            As[r][c4 + 2] = __uint_as_float(f2tf32(v.z));
            As[r][c4 + 3] = __uint_as_float(f2tf32(v.w));
        }
        // B tile 32x192 (tf32-converted)
        #pragma unroll
        for (int i = 0; i < 6; i++) {
            int idx = tid + i * 256;           // 1536 float4 slots
            int r = idx / 48, c4 = (idx % 48) << 2;
            float4 v = *reinterpret_cast<const float4*>(&Wop[(kc + r) * LDW + n0 + c4]);
            Bs[r][c4 + 0] = __uint_as_float(f2tf32(v.x));
            Bs[r][c4 + 1] = __uint_as_float(f2tf32(v.y));
            Bs[r][c4 + 2] = __uint_as_float(f2tf32(v.z));
            Bs[r][c4 + 3] = __uint_as_float(f2tf32(v.w));
        }
        __syncthreads();
        #pragma unroll
        for (int k8 = 0; k8 < 32; k8 += 8) {
            unsigned a0 = __float_as_uint(As[mw + g][k8 + t4]);
            unsigned a1 = __float_as_uint(As[mw + g + 8][k8 + t4]);
            unsigned a2 = __float_as_uint(As[mw + g][k8 + t4 + 4]);
            unsigned a3 = __float_as_uint(As[mw + g + 8][k8 + t4 + 4]);
            #pragma unroll
            for (int nt = 0; nt < 12; nt++) {
                unsigned b0r = __float_as_uint(Bs[k8 + t4][nw + nt * 8 + g]);
                unsigned b1r = __float_as_uint(Bs[k8 + t4 + 4][nw + nt * 8 + g]);
                mma_tf32(c[nt], a0, a1, a2, a3, b0r, b1r);
            }
        }
    }
    __syncthreads();
    // Store C frags to smem with per-feature 25-stride remap (bank-collision-free)
    {
        int t2 = (lane & 3) * 2;
        int r0 = mw + g, r1 = r0 + 8;
        #pragma unroll
        for (int nt = 0; nt < 12; nt++) {
            int col0 = nw + nt * 8 + t2;
            int fa = col0 / 24, oa = col0 % 24;
            Cs[r0][fa * 25 + oa] = c[nt][0];
            Cs[r1][fa * 25 + oa] = c[nt][2];
            int col1 = col0 + 1;
            int fb = col1 / 24, ob = col1 % 24;
            Cs[r0][fb * 25 + ob] = c[nt][1];
            Cs[r1][fb * 25 + ob] = c[nt][3];
        }
    }
    __syncthreads();

    // Spline phase: thread owns rows b_local, b_local+32 for feature f_local
    int f_local = tid & 7;
    int b_local = tid >> 3;   // 0..31
    int f = f0 + f_local;
    const float scale = 0.08838834764831845f;  // 1/sqrt(128)
    float ld0 = 0.f, ld1 = 0.f;

    if (f < F_) {
        const float* Bo = bos + f_local * 24;
        {
            const float* P = Cs[b_local] + f_local * 25;
            float uw[8], uh[8], ud7[7];
            #pragma unroll
            for (int o = 0; o < 8; o++) {
                uw[o] = (P[o] + Bo[o]) * scale;
                uh[o] = (P[8 + o] + Bo[8 + o]) * scale;
            }
            #pragma unroll
            for (int o = 0; o < 7; o++) ud7[o] = P[16 + o] + Bo[16 + o];
            int b = b0 + b_local;
            float x = zn[b * LDP + 2 * f + 1];
            float o, l;
            rqs_fast(x, uw, uh, ud7, o, l);
            zout[b * LDP + 2 * f + 1] = o;
            ld0 = l;
        }
        {
            const float* P = Cs[b_local + 32] + f_local * 25;
            float uw[8], uh[8], ud7[7];
            #pragma unroll
            for (int o = 0; o < 8; o++) {
                uw[o] = (P[o] + Bo[o]) * scale;
                uh[o] = (P[8 + o] + Bo[8 + o]) * scale;
            }
            #pragma unroll
            for (int o = 0; o < 7; o++) ud7[o] = P[16 + o] + Bo[16 + o];
            int b = b0 + b_local + 32;
            float x = zn[b * LDP + 2 * f + 1];
            float o, l;
            rqs_fast(x, uw, uh, ud7, o, l);
            zout[b * LDP + 2 * f + 1] = o;
            ld1 = l;
        }
    }
    #pragma unroll
    for (int o = 4; o > 0; o >>= 1) {
        ld0 += __shfl_xor_sync(0xffffffffu, ld0, o);
        ld1 += __shfl_xor_sync(0xffffffffu, ld1, o);
    }
    if (f_local == 0) {
        atomicAdd(&lq[b0 + b_local], ld0);
        atomicAdd(&lq[b0 + b_local + 32], ld1);
    }
}

__global__ void final_kernel(const float* __restrict__ z, const float* __restrict__ loc,
                             const float* __restrict__ lsc, const float* __restrict__ lq,
                             const float* __restrict__ slog, float* __restrict__ out)
{
    int b = blockIdx.x;
    float s = 0.f;
    for (int d = threadIdx.x; d < D_; d += blockDim.x) {
        float inv = __expf(-lsc[d]);
        float u = (z[b * LDP + d] - loc[d]) * inv;
        s += lsc[d] + 0.5f * u * u;
    }
    s = block_reduce_sum(s);
    if (threadIdx.x == 0) {
        const float c = 0.5f * 550.f * 1.8378770664093453f;
        out[b] = lq[b] + slog[0] + slog[1] + slog[2] - c - s;
    }
}

// ---------------- launch ----------------
extern "C" void kernel_launch(void* const* d_in, const int* in_sizes, int n_in,
                              void* d_out, int out_size)
{
    (void)in_sizes; (void)n_in; (void)out_size;
    const float* x      = (const float*)d_in[0];
    const float* loc    = (const float*)d_in[1];
    const float* lsc    = (const float*)d_in[2];
    const float* Wi     = (const float*)d_in[3];
    const float* bi     = (const float*)d_in[4];
    const float* Wb     = (const float*)d_in[5];
    const float* bb     = (const float*)d_in[6];
    const float* Wo     = (const float*)d_in[7];
    const float* bo     = (const float*)d_in[8];
    const float* uw_u   = (const float*)d_in[9];
    const float* uh_u   = (const float*)d_in[10];
    const float* ud_u   = (const float*)d_in[11];
    const float* lower  = (const float*)d_in[12];
    const float* upper  = (const float*)d_in[13];
    const float* lu_ud  = (const float*)d_in[14];
    const float* lu_b   = (const float*)d_in[15];
    const int*   perms  = (const int*)d_in[16];
    float* outp = (float*)d_out;

    float *z, *zn, *LT, *UpT, *ApT, *ident, *t, *r, *lq, *slog, *kn, *wop;
    cudaGetSymbolAddress((void**)&z,     g_z);
    cudaGetSymbolAddress((void**)&zn,    g_zn);
    cudaGetSymbolAddress((void**)&LT,    g_LT);
    cudaGetSymbolAddress((void**)&UpT,   g_UpT);
    cudaGetSymbolAddress((void**)&ApT,   g_ApT);
    cudaGetSymbolAddress((void**)&ident, g_id);
    cudaGetSymbolAddress((void**)&t,     g_t);
    cudaGetSymbolAddress((void**)&r,     g_r);
    cudaGetSymbolAddress((void**)&lq,    g_lq);
    cudaGetSymbolAddress((void**)&slog,  g_slog);
    cudaGetSymbolAddress((void**)&kn,    g_kn);
    cudaGetSymbolAddress((void**)&wop,   g_Wop);

    static bool attr_set = false;
    if (!attr_set) {
        cudaFuncSetAttribute(wo_spline_tc,
                             cudaFuncAttributeMaxDynamicSharedMemorySize, 64 * 200 * 4);
        attr_set = true;
    }

    auto big_gemm = [&](const float* src, const float* bias) {
        sgemm_pad<64, 64, 8, 4, false, true>
            <<<dim3((D_ + 63) / 64, B_ / 64), 128>>>(
                src, ApT, bias, zn, B_, D_, LDP, LDP, LDP, LDP);
    };
    auto apt_gemm = [&]() {
        sgemm_pad<64, 64, 4, 4, true, false>
            <<<dim3((D_ + 63) / 64, (D_ + 63) / 64), 256>>>(
                UpT, LT, nullptr, ApT, D_, D_, LDP, LDP, LDP, LDP);
    };

    auto resnet_and_tail = [&](int i) {
        ident_knots_kernel<<<(F_ + 255) / 256, 256>>>(
            uw_u + i * F_ * 8, uh_u + i * F_ * 8, ud_u + i * F_ * 7, kn);
        ident_eval_kernel<<<dim3((F_ + 31) / 32, B_ / 8), 256>>>(
            zn, kn, ident, z, lq);
        prep_wop_kernel<<<(H_ * LDW + 255) / 256, 256>>>(Wo + i * H_ * OUT_, wop);
        gemm_k<64, 64, 16, 4, 4, false, false>
            <<<dim3(2, B_ / 64), 256>>>(ident, Wi + i * F_ * H_, bi + i * H_, nullptr,
                                        t, B_, H_, F_, LDF, H_, H_);
        gemm_k<64, 64, 16, 4, 4, true, false>
            <<<dim3(2, B_ / 64), 256>>>(t, Wb + (i * 4 + 0) * H_ * H_, bb + (i * 4 + 0) * H_,
                                        nullptr, r, B_, H_, H_, H_, H_, H_);
        gemm_k<64, 64, 16, 4, 4, true, true>
            <<<dim3(2, B_ / 64), 256>>>(r, Wb + (i * 4 + 1) * H_ * H_, bb + (i * 4 + 1) * H_,
                                        t, t, B_, H_, H_, H_, H_, H_);
        gemm_k<64, 64, 16, 4, 4, true, false>
            <<<dim3(2, B_ / 64), 256>>>(t, Wb + (i * 4 + 2) * H_ * H_, bb + (i * 4 + 2) * H_,
                                        nullptr, r, B_, H_, H_, H_, H_, H_);
        gemm_k<64, 64, 16, 4, 4, true, true>
            <<<dim3(2, B_ / 64), 256>>>(r, Wb + (i * 4 + 3) * H_ * H_, bb + (i * 4 + 3) * H_,
                                        t, t, B_, H_, H_, H_, H_, H_);
        wo_spline_tc<<<dim3((F_ + 7) / 8, B_ / 64), 256, 64 * 200 * 4>>>(
            t, wop, bo + i * OUT_, zn, z, lq);
    };

    // ---- layer 2 prelude, ordered so the BIG GEMM is launch index 3 (ncu) ----
    build_lt_upt_kernel<<<dim3((D_ + 255) / 256, D_, 2), 256>>>(          // 0
        lower + 2 * D_ * D_, upper + 2 * D_ * D_, lu_ud + 2 * D_, perms + 2 * D_, LT, UpT);
    apt_gemm();                                                            // 1
    copy_pad_kernel<<<(B_ * D_ + 255) / 256, 256>>>(x, z);                 // 2
    big_gemm(z, lu_b + 2 * D_);                                            // 3 <- profiled
    zero_kernel<<<(B_ + 255) / 256, 256>>>(lq, B_);                        // 4
    sumlog_kernel<<<3, 256>>>(lu_ud, slog);                                // 5
    resnet_and_tail(2);

    for (int i = 1; i >= 0; i--) {
        build_lt_upt_kernel<<<dim3((D_ + 255) / 256, D_, 2), 256>>>(
            lower + i * D_ * D_, upper + i * D_ * D_,
            lu_ud + i * D_, perms + i * D_, LT, UpT);
        apt_gemm();
        big_gemm(z, lu_b + i * D_);
        resnet_and_tail(i);
    }

    final_kernel<<<B_, 256>>>(z, loc, lsc, lq, slog, outp);
}

// round 8
// speedup vs baseline: 4.0716x; 1.1292x over previous
#include <cuda_runtime.h>
#include <math.h>

// ---------------- problem constants ----------------
namespace {
constexpr int D_   = 550;
constexpr int LDP  = 560;    // padded lead dim: 35*16, all pads guaranteed zero
constexpr int MATR = 576;    // matrix buffer rows (covers tile overreach)
constexpr int F_   = 275;
constexpr int LDF  = 276;    // padded ident stride
constexpr int B_   = 4096;   // N*T = 8*512
constexpr int H_   = 128;
constexpr int OUT_ = 6325;   // F_*(3*8-1)
constexpr int LDW  = 6720;   // padded Wo cols: 280 features * 24
}

// ---------------- scratch (device globals; no allocs allowed) ----------------
__device__ float g_z  [B_*LDP];   // zero-init => pad cols stay 0
__device__ float g_zn [B_*LDP];
__device__ float g_LT [MATR*LDP];
__device__ float g_UpT[MATR*LDP];
__device__ float g_ApT[MATR*LDP];
__device__ float g_id [B_*LDF];
__device__ float g_t  [B_*H_];
__device__ float g_r  [B_*H_];
__device__ float g_lq [B_];
__device__ float g_slog[3];
__device__ float g_kn [F_*27];    // per-f ident knots
__device__ float g_Wop[H_*LDW];   // per-layer padded Wo (24 cols per feature)

// ---------------- helpers ----------------
__device__ __forceinline__ float softplus_acc(float x) {
    return (x > 20.f) ? x : log1pf(__expf(x));
}
__device__ __forceinline__ float softplus_fast(float x) {
    return (x > 15.f) ? x : __logf(1.f + __expf(x));
}

__device__ __forceinline__ unsigned f2tf32(float x) {
    unsigned r; asm("cvt.rna.tf32.f32 %0, %1;" : "=r"(r) : "f"(x)); return r;
}

__device__ __forceinline__ void mma_tf32(float* c,
    unsigned a0, unsigned a1, unsigned a2, unsigned a3,
    unsigned b0, unsigned b1)
{
    asm volatile(
        "mma.sync.aligned.m16n8k8.row.col.f32.tf32.tf32.f32 "
        "{%0,%1,%2,%3}, {%4,%5,%6,%7}, {%8,%9}, {%0,%1,%2,%3};\n"
        : "+f"(c[0]), "+f"(c[1]), "+f"(c[2]), "+f"(c[3])
        : "r"(a0), "r"(a1), "r"(a2), "r"(a3), "r"(b0), "r"(b1));
}

__device__ __forceinline__ float block_reduce_sum(float v) {
    __shared__ float sred[32];
    int tid = threadIdx.x;
    #pragma unroll
    for (int o = 16; o > 0; o >>= 1) v += __shfl_down_sync(0xffffffffu, v, o);
    if ((tid & 31) == 0) sred[tid >> 5] = v;
    __syncthreads();
    if (tid < 32) {
        int nw = (blockDim.x + 31) >> 5;
        v = (tid < nw) ? sred[tid] : 0.f;
        #pragma unroll
        for (int o = 16; o > 0; o >>= 1) v += __shfl_down_sync(0xffffffffu, v, o);
    }
    return v;
}

// Fast inverse RQS, params in registers (conditional path).
__device__ __forceinline__ void rqs_fast(float x, const float* uw, const float* uh,
                                         const float* ud7, float& out, float& ld)
{
    const float TB = 3.f;
    bool inside = (x >= -TB) && (x <= TB);
    float xi = fminf(fmaxf(x, -TB), TB);

    float cw[9], ch[9];
    {
        float m = uw[0];
        #pragma unroll
        for (int k = 1; k < 8; k++) m = fmaxf(m, uw[k]);
        float e[8]; float s = 0.f;
        #pragma unroll
        for (int k = 0; k < 8; k++) { e[k] = __expf(uw[k] - m); s += e[k]; }
        float inv = __fdividef(1.f, s);
        float cum = 0.f;
        cw[0] = -TB;
        #pragma unroll
        for (int k = 0; k < 7; k++) { cum += 0.001f + 0.992f * e[k] * inv; cw[k+1] = 6.f * cum - 3.f; }
        cw[8] = TB;
    }
    {
        float m = uh[0];
        #pragma unroll
        for (int k = 1; k < 8; k++) m = fmaxf(m, uh[k]);
        float e[8]; float s = 0.f;
        #pragma unroll
        for (int k = 0; k < 8; k++) { e[k] = __expf(uh[k] - m); s += e[k]; }
        float inv = __fdividef(1.f, s);
        float cum = 0.f;
        ch[0] = -TB;
        #pragma unroll
        for (int k = 0; k < 7; k++) { cum += 0.001f + 0.992f * e[k] * inv; ch[k+1] = 6.f * cum - 3.f; }
        ch[8] = TB;
    }

    int cnt = 0;
    #pragma unroll
    for (int k = 0; k < 9; k++) {
        float lo = ch[k] + (k == 8 ? 1e-6f : 0.f);
        cnt += (xi >= lo) ? 1 : 0;
    }
    int idx = cnt - 1; idx = idx < 0 ? 0 : (idx > 7 ? 7 : idx);

    float icw = 0.f, iw = 1.f, ich = 0.f, ih = 1.f;
    float u0 = 0.f, u1 = 0.f;
    #pragma unroll
    for (int k = 0; k < 8; k++) {
        if (k == idx) {
            icw = cw[k]; iw = cw[k+1] - cw[k];
            ich = ch[k]; ih = ch[k+1] - ch[k];
        }
    }
    #pragma unroll
    for (int k = 0; k < 7; k++) {
        if (k == idx - 1) u0 = ud7[k];
        if (k == idx)     u1 = ud7[k];
    }
    float d0 = (idx == 0) ? 1.f : 0.001f + softplus_fast(u0);
    float d1 = (idx == 7) ? 1.f : 0.001f + softplus_fast(u1);

    float delta = __fdividef(ih, iw);
    float t  = xi - ich;
    float s2 = d0 + d1 - 2.f * delta;
    float aa = t * s2 + ih * (delta - d0);
    float bb = ih * d0 - t * s2;
    float cc = -delta * t;
    float disc = bb * bb - 4.f * aa * cc;
    float sq = disc * __frsqrt_rn(fmaxf(disc, 1e-37f));
    float root = __fdividef(2.f * cc, -bb - sq);
    float o = root * iw + icw;
    float tm = root * (1.f - root);
    float den = delta + s2 * tm;
    float omr = 1.f - root;
    float dnum = delta * delta * (d1 * root * root + 2.f * delta * tm + d0 * omr * omr);
    float l = -__logf(__fdividef(dnum, den * den));

    out = inside ? o : x;
    ld  = inside ? l : 0.f;
}

// ---------------- small kernels ----------------
__global__ void zero_kernel(float* p, int n) {
    int i = blockIdx.x * blockDim.x + threadIdx.x;
    if (i < n) p[i] = 0.f;
}

__global__ void copy_pad_kernel(const float* __restrict__ x, float* __restrict__ z) {
    int i = blockIdx.x * blockDim.x + threadIdx.x;
    if (i >= B_ * D_) return;
    int b = i / D_, d = i % D_;
    z[b * LDP + d] = x[i];
}

__global__ void sumlog_kernel(const float* __restrict__ lu_ud, float* __restrict__ out) {
    int i = blockIdx.x;
    float s = 0.f;
    for (int d = threadIdx.x; d < D_; d += blockDim.x)
        s += __logf(softplus_acc(lu_ud[i * D_ + d]) + 0.001f);
    s = block_reduce_sum(s);
    if (threadIdx.x == 0) out[i] = s;
}

// Pad Wo[k, f*23+o] -> Wop[k, f*24+o]
__global__ void prep_wop_kernel(const float* __restrict__ Wo, float* __restrict__ Wop) {
    int idx = blockIdx.x * blockDim.x + threadIdx.x;
    if (idx >= H_ * LDW) return;
    int k = idx / LDW, c = idx % LDW;
    int f = c / 24, o = c % 24;
    float v = 0.f;
    if (o < 23 && f < F_) v = Wo[k * OUT_ + f * 23 + o];
    Wop[idx] = v;
}

// Per-f knots for the unconditional (ident) spline
__global__ void ident_knots_kernel(const float* __restrict__ uw_u,
                                   const float* __restrict__ uh_u,
                                   const float* __restrict__ ud_u,
                                   float* __restrict__ kn)
{
    int f = blockIdx.x * blockDim.x + threadIdx.x;
    if (f >= F_) return;
    const float TB = 3.f;
    float* o = kn + f * 27;
    {
        const float* u = uw_u + f * 8;
        float m = u[0];
        #pragma unroll
        for (int k = 1; k < 8; k++) m = fmaxf(m, u[k]);
        float e[8]; float s = 0.f;
        #pragma unroll
        for (int k = 0; k < 8; k++) { e[k] = __expf(u[k] - m); s += e[k]; }
        float inv = 1.f / s;
        float cum = 0.f;
        o[0] = -TB;
        #pragma unroll
        for (int k = 0; k < 7; k++) { cum += 0.001f + 0.992f * e[k] * inv; o[k+1] = 6.f * cum - 3.f; }
        o[8] = TB;
    }
    {
        const float* u = uh_u + f * 8;
        float m = u[0];
        #pragma unroll
        for (int k = 1; k < 8; k++) m = fmaxf(m, u[k]);
        float e[8]; float s = 0.f;
        #pragma unroll
        for (int k = 0; k < 8; k++) { e[k] = __expf(u[k] - m); s += e[k]; }
        float inv = 1.f / s;
        float cum = 0.f;
        o[9] = -TB;
        #pragma unroll
        for (int k = 0; k < 7; k++) { cum += 0.001f + 0.992f * e[k] * inv; o[10+k] = 6.f * cum - 3.f; }
        o[17] = TB;
    }
    o[18] = 1.f; o[26] = 1.f;
    #pragma unroll
    for (int k = 0; k < 7; k++) o[19 + k] = 0.001f + softplus_acc(ud_u[f * 7 + k]);
}

// Table-driven ident spline eval. Block = 32 f x 8 b (256 thr).
__global__ void __launch_bounds__(256)
ident_eval_kernel(const float* __restrict__ zn, const float* __restrict__ kn,
                  float* __restrict__ ident, float* __restrict__ zout,
                  float* __restrict__ lq)
{
    __shared__ float sk[32][29];
    int tid = threadIdx.x;
    int f_local = tid & 31;
    int b_local = tid >> 5;
    int f0 = blockIdx.x * 32;
    int b  = blockIdx.y * 8 + b_local;

    for (int j = tid; j < 32 * 27; j += 256) {
        int fl = j / 27, e = j % 27;
        int f = f0 + fl;
        sk[fl][e] = (f < F_) ? kn[f * 27 + e] : 0.f;
    }
    __syncthreads();

    int f = f0 + f_local;
    float ldv = 0.f;
    if (f < F_) {
        const float TB = 3.f;
        const float* K = sk[f_local];
        float x = zn[b * LDP + 2 * f];
        bool inside = (x >= -TB) && (x <= TB);
        float xi = fminf(fmaxf(x, -TB), TB);

        int cnt = 0;
        #pragma unroll
        for (int k = 0; k < 9; k++) {
            float lo = K[9 + k] + (k == 8 ? 1e-6f : 0.f);
            cnt += (xi >= lo) ? 1 : 0;
        }
        int idx = cnt - 1; idx = idx < 0 ? 0 : (idx > 7 ? 7 : idx);

        float icw = K[idx],     iw = K[idx + 1] - icw;
        float ich = K[9 + idx], ih = K[10 + idx] - ich;
        float d0  = K[18 + idx], d1 = K[19 + idx];

        float delta = __fdividef(ih, iw);
        float t  = xi - ich;
        float s2 = d0 + d1 - 2.f * delta;
        float aa = t * s2 + ih * (delta - d0);
        float bb = ih * d0 - t * s2;
        float cc = -delta * t;
        float disc = bb * bb - 4.f * aa * cc;
        float sq = disc * __frsqrt_rn(fmaxf(disc, 1e-37f));
        float root = __fdividef(2.f * cc, -bb - sq);
        float o = root * iw + icw;
        float tm = root * (1.f - root);
        float den = delta + s2 * tm;
        float omr = 1.f - root;
        float dnum = delta * delta * (d1 * root * root + 2.f * delta * tm + d0 * omr * omr);
        float l = -__logf(__fdividef(dnum, den * den));

        float ov = inside ? o : x;
        ldv = inside ? l : 0.f;
        ident[b * LDF + f] = ov;
        zout[b * LDP + 2 * f] = ov;
    }
    #pragma unroll
    for (int o = 16; o > 0; o >>= 1) ldv += __shfl_xor_sync(0xffffffffu, ldv, o);
    if (f_local == 0) atomicAdd(&lq[b], ldv);
}

// Materialize LT[m,d] = L[d,m] (unit diag) and UpT[perm[k], m] = Udense[m,k].
__global__ void build_lt_upt_kernel(const float* __restrict__ lower,
                                    const float* __restrict__ upper,
                                    const float* __restrict__ lu_ud,
                                    const int* __restrict__ perm,
                                    float* __restrict__ LT, float* __restrict__ UpT)
{
    int c = blockIdx.x * blockDim.x + threadIdx.x;
    int rr = blockIdx.y;
    if (c >= D_) return;
    if (blockIdx.z == 0) {
        int m = rr, d = c;
        float v = (m < d) ? lower[d * D_ + m] : ((m == d) ? 1.f : 0.f);
        LT[m * LDP + d] = v;
    } else {
        int k = rr, m = c;
        float v;
        if (m < k)       v = upper[m * D_ + k];
        else if (m == k) v = softplus_acc(lu_ud[k]) + 0.001f;
        else             v = 0.f;
        UpT[perm[k] * LDP + m] = v;
    }
}

// ---------------- padded SGEMM (ApT build only) ----------------
template<int BM, int BN, int TM, int TN, bool GUARDM, bool HASB>
__global__ void __launch_bounds__((BM/TM)*(BN/TN))
sgemm_pad(const float* __restrict__ A, const float* __restrict__ Bm,
          const float* __restrict__ bias, float* __restrict__ C,
          int M, int N, int K, int lda, int ldb, int ldc)
{
    constexpr int BK = 16;
    constexpr int TX = BN / TN, TY = BM / TM;
    constexpr int NT = TX * TY;
    __shared__ __align__(16) float As[BK][BM];
    __shared__ __align__(16) float Bs[BK][BN];
    int tid = threadIdx.x;
    int tx = tid % TX, ty = tid / TX;
    int m0 = blockIdx.y * BM, n0 = blockIdx.x * BN;

    float acc[TM][TN];
    #pragma unroll
    for (int i = 0; i < TM; i++)
        #pragma unroll
        for (int j = 0; j < TN; j++) acc[i][j] = 0.f;

    for (int k0 = 0; k0 < K; k0 += BK) {
        #pragma unroll
        for (int idx = tid; idx < BM * 4; idx += NT) {
            int m = idx >> 2, k4 = (idx & 3) << 2;
            int gm = m0 + m;
            float4 v = make_float4(0.f, 0.f, 0.f, 0.f);
            if (!GUARDM || gm < M)
                v = *reinterpret_cast<const float4*>(&A[gm * lda + k0 + k4]);
            As[k4 + 0][m] = v.x; As[k4 + 1][m] = v.y;
            As[k4 + 2][m] = v.z; As[k4 + 3][m] = v.w;
        }
        #pragma unroll
        for (int idx = tid; idx < BN * 4; idx += NT) {
            int k = idx / (BN / 4), n4 = (idx % (BN / 4)) << 2;
            float4 v = *reinterpret_cast<const float4*>(&Bm[(k0 + k) * ldb + n0 + n4]);
            *reinterpret_cast<float4*>(&Bs[k][n4]) = v;
        }
        __syncthreads();
        #pragma unroll
        for (int kk = 0; kk < BK; kk++) {
            float a[TM], b[TN];
            #pragma unroll
            for (int i = 0; i < TM / 4; i++)
                *reinterpret_cast<float4*>(&a[4 * i]) =
                    *reinterpret_cast<const float4*>(&As[kk][ty * TM + 4 * i]);
            #pragma unroll
            for (int j = 0; j < TN / 4; j++)
                *reinterpret_cast<float4*>(&b[4 * j]) =
                    *reinterpret_cast<const float4*>(&Bs[kk][tx * TN + 4 * j]);
            #pragma unroll
            for (int i = 0; i < TM; i++)
                #pragma unroll
                for (int j = 0; j < TN; j++)
                    acc[i][j] = fmaf(a[i], b[j], acc[i][j]);
        }
        __syncthreads();
    }
    #pragma unroll
    for (int i = 0; i < TM; i++) {
        int gm = m0 + ty * TM + i;
        if (!GUARDM || gm < M) {
            #pragma unroll
            for (int j = 0; j < TN; j++) {
                int gn = n0 + tx * TN + j;
                if (gn < N) {
                    float bv = HASB ? bias[gn] : 0.f;
                    C[gm * ldc + gn] = acc[i][j] + bv;
                }
            }
        }
    }
}

// ---------------- tf32 tensor-core big GEMM: zn = src @ ApT + bias ----------
// Block: 128 m x 64 n, 256 thr = 8 warps (4m x 2n), warp tile 32x32.
// K = LDP = 560 = 35 chunks of 16; pads are zero so no k-guards.
// Garbage columns (>=550) only produce discarded outputs.
__global__ void __launch_bounds__(256)
lu_gemm_tc(const float* __restrict__ src, const float* __restrict__ ApT,
           const float* __restrict__ bias, float* __restrict__ C)
{
    __shared__ __align__(16) float As[128][20];
    __shared__ __align__(16) float Bs[16][72];

    int tid  = threadIdx.x;
    int warp = tid >> 5, lane = tid & 31;
    int mwarp = (warp & 3) * 32;
    int nwarp = (warp >> 2) * 32;
    int m0 = blockIdx.y * 128;
    int n0 = blockIdx.x * 64;
    int g = lane >> 2, t4 = lane & 3;

    float c[2][4][4];
    #pragma unroll
    for (int i = 0; i < 2; i++)
        #pragma unroll
        for (int j = 0; j < 4; j++)
            c[i][j][0] = c[i][j][1] = c[i][j][2] = c[i][j][3] = 0.f;

    for (int kc = 0; kc < LDP; kc += 16) {
        __syncthreads();
        // A tile 128x16 (tf32)
        #pragma unroll
        for (int i = 0; i < 2; i++) {
            int idx = tid + i * 256;          // 512 float4 slots
            int r = idx >> 2, c4 = (idx & 3) << 2;
            float4 v = *reinterpret_cast<const float4*>(&src[(m0 + r) * LDP + kc + c4]);
            v.x = __uint_as_float(f2tf32(v.x));
            v.y = __uint_as_float(f2tf32(v.y));
            v.z = __uint_as_float(f2tf32(v.z));
            v.w = __uint_as_float(f2tf32(v.w));
            *reinterpret_cast<float4*>(&As[r][c4]) = v;
        }
        // B tile 16x64 (tf32) — rows kc..kc+15 of ApT, cols n0..n0+63
        {
            int r = tid >> 4, c4 = (tid & 15) << 2;   // 256 float4 slots
            float4 v = *reinterpret_cast<const float4*>(&ApT[(kc + r) * LDP + n0 + c4]);
            v.x = __uint_as_float(f2tf32(v.x));
            v.y = __uint_as_float(f2tf32(v.y));
            v.z = __uint_as_float(f2tf32(v.z));
            v.w = __uint_as_float(f2tf32(v.w));
            *reinterpret_cast<float4*>(&Bs[r][c4]) = v;
        }
        __syncthreads();
        #pragma unroll
        for (int k8 = 0; k8 < 16; k8 += 8) {
            #pragma unroll
            for (int mf = 0; mf < 2; mf++) {
                int mb = mwarp + mf * 16;
                unsigned a0 = __float_as_uint(As[mb + g][k8 + t4]);
                unsigned a1 = __float_as_uint(As[mb + g + 8][k8 + t4]);
                unsigned a2 = __float_as_uint(As[mb + g][k8 + t4 + 4]);
                unsigned a3 = __float_as_uint(As[mb + g + 8][k8 + t4 + 4]);
                #pragma unroll
                for (int nf = 0; nf < 4; nf++) {
                    unsigned b0r = __float_as_uint(Bs[k8 + t4][nwarp + nf * 8 + g]);
                    unsigned b1r = __float_as_uint(Bs[k8 + t4 + 4][nwarp + nf * 8 + g]);
                    mma_tf32(c[mf][nf], a0, a1, a2, a3, b0r, b1r);
                }
            }
        }
    }

    // Epilogue: write valid columns with bias
    #pragma unroll
    for (int mf = 0; mf < 2; mf++) {
        int r0 = m0 + mwarp + mf * 16 + g;
        int r1 = r0 + 8;
        #pragma unroll
        for (int nf = 0; nf < 4; nf++) {
            int cA = n0 + nwarp + nf * 8 + t4 * 2;
            int cB = cA + 1;
            if (cA < D_) {
                C[r0 * LDP + cA] = c[mf][nf][0] + bias[cA];
                C[r1 * LDP + cA] = c[mf][nf][2] + bias[cA];
            }
            if (cB < D_) {
                C[r0 * LDP + cB] = c[mf][nf][1] + bias[cB];
                C[r1 * LDP + cB] = c[mf][nf][3] + bias[cB];
            }
        }
    }
}

// ---------------- resnet GEMM (scalar loads; do not touch) ----------------
template<int BM, int BN, int BK, int TM, int TN, bool RELUA, bool ADDC>
__global__ void __launch_bounds__((BM/TM)*(BN/TN))
gemm_k(const float* __restrict__ A, const float* __restrict__ B,
       const float* __restrict__ bias, const float* __restrict__ Cadd,
       float* __restrict__ C, int M, int N, int K, int lda, int ldb, int ldc)
{
    constexpr int TX = BN / TN, TY = BM / TM, NT = TX * TY;
    __shared__ float As[BK][BM];
    __shared__ float Bs[BK][BN];
    int tid = threadIdx.x;
    int tx = tid % TX, ty = tid / TX;
    int m0 = blockIdx.y * BM, n0 = blockIdx.x * BN;
    float acc[TM][TN];
    #pragma unroll
    for (int i = 0; i < TM; i++)
        #pragma unroll
        for (int j = 0; j < TN; j++) acc[i][j] = 0.f;

    for (int k0 = 0; k0 < K; k0 += BK) {
        #pragma unroll
        for (int idx = tid; idx < BM * BK; idx += NT) {
            int r = idx / BK, c = idx % BK;
            int gm = m0 + r, gk = k0 + c;
            float v = (gk < K) ? A[gm * lda + gk] : 0.f;
            if (RELUA) v = fmaxf(v, 0.f);
            As[c][r] = v;
        }
        #pragma unroll
        for (int idx = tid; idx < BK * BN; idx += NT) {
            int r = idx / BN, c = idx % BN;
            int gk = k0 + r, gn = n0 + c;
            Bs[r][c] = (gk < K && gn < N) ? B[gk * ldb + gn] : 0.f;
        }
        __syncthreads();
        #pragma unroll
        for (int kk = 0; kk < BK; kk++) {
            float ra[TM], rb[TN];
            #pragma unroll
            for (int i = 0; i < TM; i++) ra[i] = As[kk][ty * TM + i];
            #pragma unroll
            for (int j = 0; j < TN; j++) rb[j] = Bs[kk][tx * TN + j];
            #pragma unroll
            for (int i = 0; i < TM; i++)
                #pragma unroll
                for (int j = 0; j < TN; j++)
                    acc[i][j] += ra[i] * rb[j];
        }
        __syncthreads();
    }
    #pragma unroll
    for (int i = 0; i < TM; i++) {
        int gm = m0 + ty * TM + i;
        #pragma unroll
        for (int j = 0; j < TN; j++) {
            int gn = n0 + tx * TN + j;
            if (gn < N) {
                float v = acc[i][j] + bias[gn];
                if (ADDC) v += Cadd[gm * ldc + gn];
                C[gm * ldc + gn] = v;
            }
        }
    }
}

// ---------------- tf32 tensor-core fused Wo GEMM + conditional spline ----------
__global__ void __launch_bounds__(256)
wo_spline_tc(const float* __restrict__ tmat, const float* __restrict__ Wop,
             const float* __restrict__ bo, const float* __restrict__ zn,
             float* __restrict__ zout, float* __restrict__ lq)
{
    extern __shared__ float sm[];
    float (*As)[36]  = reinterpret_cast<float(*)[36]>(sm);            // 64x36
    float (*Bs)[200] = reinterpret_cast<float(*)[200]>(sm + 64 * 36); // 32x200
    float (*Cs)[200] = reinterpret_cast<float(*)[200]>(sm);           // 64x200 (aliases)
    __shared__ float bos[192];

    int tid  = threadIdx.x;
    int warp = tid >> 5, lane = tid & 31;
    int mw = (warp & 3) * 16;
    int nw = (warp >> 2) * 96;
    int b0 = blockIdx.y * 64;
    int f0 = blockIdx.x * 8;
    int n0 = blockIdx.x * 192;

    for (int i = tid; i < 192; i += 256) {
        int ff = i / 24, oo = i % 24;
        int col = (f0 + ff) * 23 + oo;
        bos[i] = (oo < 23 && col < OUT_) ? bo[col] : 0.f;
    }

    float c[12][4];
    #pragma unroll
    for (int i = 0; i < 12; i++) { c[i][0] = c[i][1] = c[i][2] = c[i][3] = 0.f; }

    int g = lane >> 2, t4 = lane & 3;

    for (int kc = 0; kc < H_; kc += 32) {
        __syncthreads();
        #pragma unroll
        for (int i = 0; i < 2; i++) {
            int idx = tid + i * 256;
            int r = idx >> 3, c4 = (idx & 7) << 2;
            float4 v = *reinterpret_cast<const float4*>(&tmat[(b0 + r) * H_ + kc + c4]);
            As[r][c4 + 0] = __uint_as_float(f2tf32(v.x));
            As[r][c4 + 1] = __uint_as_float(f2tf32(v.y));
            As[r][c4 + 2] = __uint_as_float(f2tf32(v.z));
            As[r][c4 + 3] = __uint_as_float(f2tf32(v.w));
        }
        #pragma unroll
        for (int i = 0; i < 6; i++) {
            int idx = tid + i * 256;
            int r = idx / 48, c4 = (idx % 48) << 2;
            float4 v = *reinterpret_cast<const float4*>(&Wop[(kc + r) * LDW + n0 + c4]);
            Bs[r][c4 + 0] = __uint_as_float(f2tf32(v.x));
            Bs[r][c4 + 1] = __uint_as_float(f2tf32(v.y));
            Bs[r][c4 + 2] = __uint_as_float(f2tf32(v.z));
            Bs[r][c4 + 3] = __uint_as_float(f2tf32(v.w));
        }
        __syncthreads();
        #pragma unroll
        for (int k8 = 0; k8 < 32; k8 += 8) {
            unsigned a0 = __float_as_uint(As[mw + g][k8 + t4]);
            unsigned a1 = __float_as_uint(As[mw + g + 8][k8 + t4]);
            unsigned a2 = __float_as_uint(As[mw + g][k8 + t4 + 4]);
            unsigned a3 = __float_as_uint(As[mw + g + 8][k8 + t4 + 4]);
            #pragma unroll
            for (int nt = 0; nt < 12; nt++) {
                unsigned b0r = __float_as_uint(Bs[k8 + t4][nw + nt * 8 + g]);
                unsigned b1r = __float_as_uint(Bs[k8 + t4 + 4][nw + nt * 8 + g]);
                mma_tf32(c[nt], a0, a1, a2, a3, b0r, b1r);
            }
        }
    }
    __syncthreads();
    {
        int t2 = (lane & 3) * 2;
        int r0 = mw + g, r1 = r0 + 8;
        #pragma unroll
        for (int nt = 0; nt < 12; nt++) {
            int col0 = nw + nt * 8 + t2;
            int fa = col0 / 24, oa = col0 % 24;
            Cs[r0][fa * 25 + oa] = c[nt][0];
            Cs[r1][fa * 25 + oa] = c[nt][2];
            int col1 = col0 + 1;
            int fb = col1 / 24, ob = col1 % 24;
            Cs[r0][fb * 25 + ob] = c[nt][1];
            Cs[r1][fb * 25 + ob] = c[nt][3];
        }
    }
    __syncthreads();

    int f_local = tid & 7;
    int b_local = tid >> 3;
    int f = f0 + f_local;
    const float scale = 0.08838834764831845f;
    float ld0 = 0.f, ld1 = 0.f;

    if (f < F_) {
        const float* Bo = bos + f_local * 24;
        {
            const float* P = Cs[b_local] + f_local * 25;
            float uw[8], uh[8], ud7[7];
            #pragma unroll
            for (int o = 0; o < 8; o++) {
                uw[o] = (P[o] + Bo[o]) * scale;
                uh[o] = (P[8 + o] + Bo[8 + o]) * scale;
            }
            #pragma unroll
            for (int o = 0; o < 7; o++) ud7[o] = P[16 + o] + Bo[16 + o];
            int b = b0 + b_local;
            float x = zn[b * LDP + 2 * f + 1];
            float o, l;
            rqs_fast(x, uw, uh, ud7, o, l);
            zout[b * LDP + 2 * f + 1] = o;
            ld0 = l;
        }
        {
            const float* P = Cs[b_local + 32] + f_local * 25;
            float uw[8], uh[8], ud7[7];
            #pragma unroll
            for (int o = 0; o < 8; o++) {
                uw[o] = (P[o] + Bo[o]) * scale;
                uh[o] = (P[8 + o] + Bo[8 + o]) * scale;
            }
            #pragma unroll
            for (int o = 0; o < 7; o++) ud7[o] = P[16 + o] + Bo[16 + o];
            int b = b0 + b_local + 32;
            float x = zn[b * LDP + 2 * f + 1];
            float o, l;
            rqs_fast(x, uw, uh, ud7, o, l);
            zout[b * LDP + 2 * f + 1] = o;
            ld1 = l;
        }
    }
    #pragma unroll
    for (int o = 4; o > 0; o >>= 1) {
        ld0 += __shfl_xor_sync(0xffffffffu, ld0, o);
        ld1 += __shfl_xor_sync(0xffffffffu, ld1, o);
    }
    if (f_local == 0) {
        atomicAdd(&lq[b0 + b_local], ld0);
        atomicAdd(&lq[b0 + b_local + 32], ld1);
    }
}

__global__ void final_kernel(const float* __restrict__ z, const float* __restrict__ loc,
                             const float* __restrict__ lsc, const float* __restrict__ lq,
                             const float* __restrict__ slog, float* __restrict__ out)
{
    int b = blockIdx.x;
    float s = 0.f;
    for (int d = threadIdx.x; d < D_; d += blockDim.x) {
        float inv = __expf(-lsc[d]);
        float u = (z[b * LDP + d] - loc[d]) * inv;
        s += lsc[d] + 0.5f * u * u;
    }
    s = block_reduce_sum(s);
    if (threadIdx.x == 0) {
        const float c = 0.5f * 550.f * 1.8378770664093453f;
        out[b] = lq[b] + slog[0] + slog[1] + slog[2] - c - s;
    }
}

// ---------------- launch ----------------
extern "C" void kernel_launch(void* const* d_in, const int* in_sizes, int n_in,
                              void* d_out, int out_size)
{
    (void)in_sizes; (void)n_in; (void)out_size;
    const float* x      = (const float*)d_in[0];
    const float* loc    = (const float*)d_in[1];
    const float* lsc    = (const float*)d_in[2];
    const float* Wi     = (const float*)d_in[3];
    const float* bi     = (const float*)d_in[4];
    const float* Wb     = (const float*)d_in[5];
    const float* bb     = (const float*)d_in[6];
    const float* Wo     = (const float*)d_in[7];
    const float* bo     = (const float*)d_in[8];
    const float* uw_u   = (const float*)d_in[9];
    const float* uh_u   = (const float*)d_in[10];
    const float* ud_u   = (const float*)d_in[11];
    const float* lower  = (const float*)d_in[12];
    const float* upper  = (const float*)d_in[13];
    const float* lu_ud  = (const float*)d_in[14];
    const float* lu_b   = (const float*)d_in[15];
    const int*   perms  = (const int*)d_in[16];
    float* outp = (float*)d_out;

    float *z, *zn, *LT, *UpT, *ApT, *ident, *t, *r, *lq, *slog, *kn, *wop;
    cudaGetSymbolAddress((void**)&z,     g_z);
    cudaGetSymbolAddress((void**)&zn,    g_zn);
    cudaGetSymbolAddress((void**)&LT,    g_LT);
    cudaGetSymbolAddress((void**)&UpT,   g_UpT);
    cudaGetSymbolAddress((void**)&ApT,   g_ApT);
    cudaGetSymbolAddress((void**)&ident, g_id);
    cudaGetSymbolAddress((void**)&t,     g_t);
    cudaGetSymbolAddress((void**)&r,     g_r);
    cudaGetSymbolAddress((void**)&lq,    g_lq);
    cudaGetSymbolAddress((void**)&slog,  g_slog);
    cudaGetSymbolAddress((void**)&kn,    g_kn);
    cudaGetSymbolAddress((void**)&wop,   g_Wop);

    static bool attr_set = false;
    if (!attr_set) {
        cudaFuncSetAttribute(wo_spline_tc,
                             cudaFuncAttributeMaxDynamicSharedMemorySize, 64 * 200 * 4);
        attr_set = true;
    }

    auto big_gemm = [&](const float* src, const float* bias) {
        lu_gemm_tc<<<dim3((D_ + 63) / 64, B_ / 128), 256>>>(src, ApT, bias, zn);
    };
    auto apt_gemm = [&]() {
        sgemm_pad<64, 64, 4, 4, true, false>
            <<<dim3((D_ + 63) / 64, (D_ + 63) / 64), 256>>>(
                UpT, LT, nullptr, ApT, D_, D_, LDP, LDP, LDP, LDP);
    };

    auto resnet_and_tail = [&](int i) {
        ident_knots_kernel<<<(F_ + 255) / 256, 256>>>(
            uw_u + i * F_ * 8, uh_u + i * F_ * 8, ud_u + i * F_ * 7, kn);
        ident_eval_kernel<<<dim3((F_ + 31) / 32, B_ / 8), 256>>>(
            zn, kn, ident, z, lq);
        prep_wop_kernel<<<(H_ * LDW + 255) / 256, 256>>>(Wo + i * H_ * OUT_, wop);
        gemm_k<64, 64, 16, 4, 4, false, false>
            <<<dim3(2, B_ / 64), 256>>>(ident, Wi + i * F_ * H_, bi + i * H_, nullptr,
                                        t, B_, H_, F_, LDF, H_, H_);
        gemm_k<64, 64, 16, 4, 4, true, false>
            <<<dim3(2, B_ / 64), 256>>>(t, Wb + (i * 4 + 0) * H_ * H_, bb + (i * 4 + 0) * H_,
                                        nullptr, r, B_, H_, H_, H_, H_, H_);
        gemm_k<64, 64, 16, 4, 4, true, true>
            <<<dim3(2, B_ / 64), 256>>>(r, Wb + (i * 4 + 1) * H_ * H_, bb + (i * 4 + 1) * H_,
                                        t, t, B_, H_, H_, H_, H_, H_);
        gemm_k<64, 64, 16, 4, 4, true, false>
            <<<dim3(2, B_ / 64), 256>>>(t, Wb + (i * 4 + 2) * H_ * H_, bb + (i * 4 + 2) * H_,
                                        nullptr, r, B_, H_, H_, H_, H_, H_);
        gemm_k<64, 64, 16, 4, 4, true, true>
            <<<dim3(2, B_ / 64), 256>>>(r, Wb + (i * 4 + 3) * H_ * H_, bb + (i * 4 + 3) * H_,
                                        t, t, B_, H_, H_, H_, H_, H_);
        wo_spline_tc<<<dim3((F_ + 7) / 8, B_ / 64), 256, 64 * 200 * 4>>>(
            t, wop, bo + i * OUT_, zn, z, lq);
    };

    // ---- layer 2 prelude, ordered so the TC BIG GEMM is launch index 3 (ncu) ----
    build_lt_upt_kernel<<<dim3((D_ + 255) / 256, D_, 2), 256>>>(          // 0
        lower + 2 * D_ * D_, upper + 2 * D_ * D_, lu_ud + 2 * D_, perms + 2 * D_, LT, UpT);
    apt_gemm();                                                            // 1
    copy_pad_kernel<<<(B_ * D_ + 255) / 256, 256>>>(x, z);                 // 2
    big_gemm(z, lu_b + 2 * D_);                                            // 3 <- profiled
    zero_kernel<<<(B_ + 255) / 256, 256>>>(lq, B_);                        // 4
    sumlog_kernel<<<3, 256>>>(lu_ud, slog);                                // 5
    resnet_and_tail(2);

    for (int i = 1; i >= 0; i--) {
        build_lt_upt_kernel<<<dim3((D_ + 255) / 256, D_, 2), 256>>>(
            lower + i * D_ * D_, upper + i * D_ * D_,
            lu_ud + i * D_, perms + i * D_, LT, UpT);
        apt_gemm();
        big_gemm(z, lu_b + i * D_);
        resnet_and_tail(i);
    }

    final_kernel<<<B_, 256>>>(z, loc, lsc, lq, slog, outp);
}

// round 10
// speedup vs baseline: 4.9352x; 1.2121x over previous
#include <cuda_runtime.h>
#include <math.h>

// ---------------- problem constants ----------------
namespace {
constexpr int D_   = 550;
constexpr int LDP  = 560;    // padded lead dim: 35*16, all pads guaranteed zero
constexpr int MATR = 576;    // matrix buffer rows (covers tile overreach)
constexpr int F_   = 275;
constexpr int LDF  = 288;    // padded ident stride (36*8, zero pads -> guard-free K)
constexpr int B_   = 4096;   // N*T = 8*512
constexpr int H_   = 128;
constexpr int OUT_ = 6325;   // F_*(3*8-1)
constexpr int LDW  = 6720;   // padded Wo cols: 280 features * 24
}

// ---------------- scratch (device globals; no allocs allowed) ----------------
__device__ float g_z  [B_*LDP];   // zero-init => pad cols stay 0
__device__ float g_zn [B_*LDP];
__device__ float g_LT [MATR*LDP];
__device__ float g_UpT[MATR*LDP];
__device__ float g_ApT[MATR*LDP];
__device__ float g_id [B_*LDF];   // zero-init => cols 275..287 stay 0
__device__ float g_t  [B_*H_];
__device__ float g_lq [B_];
__device__ float g_slog[3];
__device__ float g_kn [F_*27];    // per-f ident knots
__device__ float g_Wop[H_*LDW];   // per-layer padded Wo (24 cols per feature)
__device__ float g_Wip[288*H_];   // per-layer padded Wi (288 rows, zeros past 275)

// ---------------- helpers ----------------
__device__ __forceinline__ float softplus_acc(float x) {
    return (x > 20.f) ? x : log1pf(__expf(x));
}
__device__ __forceinline__ float softplus_fast(float x) {
    return (x > 15.f) ? x : __logf(1.f + __expf(x));
}

__device__ __forceinline__ unsigned f2tf32(float x) {
    unsigned r; asm("cvt.rna.tf32.f32 %0, %1;" : "=r"(r) : "f"(x)); return r;
}

__device__ __forceinline__ void mma_tf32(float* c,
    unsigned a0, unsigned a1, unsigned a2, unsigned a3,
    unsigned b0, unsigned b1)
{
    asm volatile(
        "mma.sync.aligned.m16n8k8.row.col.f32.tf32.tf32.f32 "
        "{%0,%1,%2,%3}, {%4,%5,%6,%7}, {%8,%9}, {%0,%1,%2,%3};\n"
        : "+f"(c[0]), "+f"(c[1]), "+f"(c[2]), "+f"(c[3])
        : "r"(a0), "r"(a1), "r"(a2), "r"(a3), "r"(b0), "r"(b1));
}

__device__ __forceinline__ float block_reduce_sum(float v) {
    __shared__ float sred[32];
    int tid = threadIdx.x;
    #pragma unroll
    for (int o = 16; o > 0; o >>= 1) v += __shfl_down_sync(0xffffffffu, v, o);
    if ((tid & 31) == 0) sred[tid >> 5] = v;
    __syncthreads();
    if (tid < 32) {
        int nw = (blockDim.x + 31) >> 5;
        v = (tid < nw) ? sred[tid] : 0.f;
        #pragma unroll
        for (int o = 16; o > 0; o >>= 1) v += __shfl_down_sync(0xffffffffu, v, o);
    }
    return v;
}

// Fast inverse RQS, params in registers (conditional path).
__device__ __forceinline__ void rqs_fast(float x, const float* uw, const float* uh,
                                         const float* ud7, float& out, float& ld)
{
    const float TB = 3.f;
    bool inside = (x >= -TB) && (x <= TB);
    float xi = fminf(fmaxf(x, -TB), TB);

    float cw[9], ch[9];
    {
        float m = uw[0];
        #pragma unroll
        for (int k = 1; k < 8; k++) m = fmaxf(m, uw[k]);
        float e[8]; float s = 0.f;
        #pragma unroll
        for (int k = 0; k < 8; k++) { e[k] = __expf(uw[k] - m); s += e[k]; }
        float inv = __fdividef(1.f, s);
        float cum = 0.f;
        cw[0] = -TB;
        #pragma unroll
        for (int k = 0; k < 7; k++) { cum += 0.001f + 0.992f * e[k] * inv; cw[k+1] = 6.f * cum - 3.f; }
        cw[8] = TB;
    }
    {
        float m = uh[0];
        #pragma unroll
        for (int k = 1; k < 8; k++) m = fmaxf(m, uh[k]);
        float e[8]; float s = 0.f;
        #pragma unroll
        for (int k = 0; k < 8; k++) { e[k] = __expf(uh[k] - m); s += e[k]; }
        float inv = __fdividef(1.f, s);
        float cum = 0.f;
        ch[0] = -TB;
        #pragma unroll
        for (int k = 0; k < 7; k++) { cum += 0.001f + 0.992f * e[k] * inv; ch[k+1] = 6.f * cum - 3.f; }
        ch[8] = TB;
    }

    int cnt = 0;
    #pragma unroll
    for (int k = 0; k < 9; k++) {
        float lo = ch[k] + (k == 8 ? 1e-6f : 0.f);
        cnt += (xi >= lo) ? 1 : 0;
    }
    int idx = cnt - 1; idx = idx < 0 ? 0 : (idx > 7 ? 7 : idx);

    float icw = 0.f, iw = 1.f, ich = 0.f, ih = 1.f;
    float u0 = 0.f, u1 = 0.f;
    #pragma unroll
    for (int k = 0; k < 8; k++) {
        if (k == idx) {
            icw = cw[k]; iw = cw[k+1] - cw[k];
            ich = ch[k]; ih = ch[k+1] - ch[k];
        }
    }
    #pragma unroll
    for (int k = 0; k < 7; k++) {
        if (k == idx - 1) u0 = ud7[k];
        if (k == idx)     u1 = ud7[k];
    }
    float d0 = (idx == 0) ? 1.f : 0.001f + softplus_fast(u0);
    float d1 = (idx == 7) ? 1.f : 0.001f + softplus_fast(u1);

    float delta = __fdividef(ih, iw);
    float t  = xi - ich;
    float s2 = d0 + d1 - 2.f * delta;
    float aa = t * s2 + ih * (delta - d0);
    float bb = ih * d0 - t * s2;
    float cc = -delta * t;
    float disc = bb * bb - 4.f * aa * cc;
    float sq = disc * __frsqrt_rn(fmaxf(disc, 1e-37f));
    float root = __fdividef(2.f * cc, -bb - sq);
    float o = root * iw + icw;
    float tm = root * (1.f - root);
    float den = delta + s2 * tm;
    float omr = 1.f - root;
    float dnum = delta * delta * (d1 * root * root + 2.f * delta * tm + d0 * omr * omr);
    float l = -__logf(__fdividef(dnum, den * den));

    out = inside ? o : x;
    ld  = inside ? l : 0.f;
}

// ---------------- small kernels ----------------
__global__ void zero_kernel(float* p, int n) {
    int i = blockIdx.x * blockDim.x + threadIdx.x;
    if (i < n) p[i] = 0.f;
}

__global__ void copy_pad_kernel(const float* __restrict__ x, float* __restrict__ z) {
    int i = blockIdx.x * blockDim.x + threadIdx.x;
    if (i >= B_ * D_) return;
    int b = i / D_, d = i % D_;
    z[b * LDP + d] = x[i];
}

__global__ void sumlog_kernel(const float* __restrict__ lu_ud, float* __restrict__ out) {
    int i = blockIdx.x;
    float s = 0.f;
    for (int d = threadIdx.x; d < D_; d += blockDim.x)
        s += __logf(softplus_acc(lu_ud[i * D_ + d]) + 0.001f);
    s = block_reduce_sum(s);
    if (threadIdx.x == 0) out[i] = s;
}

// Pad Wo[k, f*23+o] -> Wop[k, f*24+o]
__global__ void prep_wop_kernel(const float* __restrict__ Wo, float* __restrict__ Wop) {
    int idx = blockIdx.x * blockDim.x + threadIdx.x;
    if (idx >= H_ * LDW) return;
    int k = idx / LDW, c = idx % LDW;
    int f = c / 24, o = c % 24;
    float v = 0.f;
    if (o < 23 && f < F_) v = Wo[k * OUT_ + f * 23 + o];
    Wop[idx] = v;
}

// Pad Wi[f, h] (275 rows) -> Wip[f, h] (288 rows, zeros past 275)
__global__ void prep_wip_kernel(const float* __restrict__ Wi, float* __restrict__ Wip) {
    int idx = blockIdx.x * blockDim.x + threadIdx.x;
    if (idx >= 288 * H_) return;
    int f = idx / H_, h = idx % H_;
    Wip[idx] = (f < F_) ? Wi[f * H_ + h] : 0.f;
}

// Per-f knots for the unconditional (ident) spline
__global__ void ident_knots_kernel(const float* __restrict__ uw_u,
                                   const float* __restrict__ uh_u,
                                   const float* __restrict__ ud_u,
                                   float* __restrict__ kn)
{
    int f = blockIdx.x * blockDim.x + threadIdx.x;
    if (f >= F_) return;
    const float TB = 3.f;
    float* o = kn + f * 27;
    {
        const float* u = uw_u + f * 8;
        float m = u[0];
        #pragma unroll
        for (int k = 1; k < 8; k++) m = fmaxf(m, u[k]);
        float e[8]; float s = 0.f;
        #pragma unroll
        for (int k = 0; k < 8; k++) { e[k] = __expf(u[k] - m); s += e[k]; }
        float inv = 1.f / s;
        float cum = 0.f;
        o[0] = -TB;
        #pragma unroll
        for (int k = 0; k < 7; k++) { cum += 0.001f + 0.992f * e[k] * inv; o[k+1] = 6.f * cum - 3.f; }
        o[8] = TB;
    }
    {
        const float* u = uh_u + f * 8;
        float m = u[0];
        #pragma unroll
        for (int k = 1; k < 8; k++) m = fmaxf(m, u[k]);
        float e[8]; float s = 0.f;
        #pragma unroll
        for (int k = 0; k < 8; k++) { e[k] = __expf(u[k] - m); s += e[k]; }
        float inv = 1.f / s;
        float cum = 0.f;
        o[9] = -TB;
        #pragma unroll
        for (int k = 0; k < 7; k++) { cum += 0.001f + 0.992f * e[k] * inv; o[10+k] = 6.f * cum - 3.f; }
        o[17] = TB;
    }
    o[18] = 1.f; o[26] = 1.f;
    #pragma unroll
    for (int k = 0; k < 7; k++) o[19 + k] = 0.001f + softplus_acc(ud_u[f * 7 + k]);
}

// Table-driven ident spline eval. Block = 32 f x 8 b (256 thr).
__global__ void __launch_bounds__(256)
ident_eval_kernel(const float* __restrict__ zn, const float* __restrict__ kn,
                  float* __restrict__ ident, float* __restrict__ zout,
                  float* __restrict__ lq)
{
    __shared__ float sk[32][29];
    int tid = threadIdx.x;
    int f_local = tid & 31;
    int b_local = tid >> 5;
    int f0 = blockIdx.x * 32;
    int b  = blockIdx.y * 8 + b_local;

    for (int j = tid; j < 32 * 27; j += 256) {
        int fl = j / 27, e = j % 27;
        int f = f0 + fl;
        sk[fl][e] = (f < F_) ? kn[f * 27 + e] : 0.f;
    }
    __syncthreads();

    int f = f0 + f_local;
    float ldv = 0.f;
    if (f < F_) {
        const float TB = 3.f;
        const float* K = sk[f_local];
        float x = zn[b * LDP + 2 * f];
        bool inside = (x >= -TB) && (x <= TB);
        float xi = fminf(fmaxf(x, -TB), TB);

        int cnt = 0;
        #pragma unroll
        for (int k = 0; k < 9; k++) {
            float lo = K[9 + k] + (k == 8 ? 1e-6f : 0.f);
            cnt += (xi >= lo) ? 1 : 0;
        }
        int idx = cnt - 1; idx = idx < 0 ? 0 : (idx > 7 ? 7 : idx);

        float icw = K[idx],     iw = K[idx + 1] - icw;
        float ich = K[9 + idx], ih = K[10 + idx] - ich;
        float d0  = K[18 + idx], d1 = K[19 + idx];

        float delta = __fdividef(ih, iw);
        float t  = xi - ich;
        float s2 = d0 + d1 - 2.f * delta;
        float aa = t * s2 + ih * (delta - d0);
        float bb = ih * d0 - t * s2;
        float cc = -delta * t;
        float disc = bb * bb - 4.f * aa * cc;
        float sq = disc * __frsqrt_rn(fmaxf(disc, 1e-37f));
        float root = __fdividef(2.f * cc, -bb - sq);
        float o = root * iw + icw;
        float tm = root * (1.f - root);
        float den = delta + s2 * tm;
        float omr = 1.f - root;
        float dnum = delta * delta * (d1 * root * root + 2.f * delta * tm + d0 * omr * omr);
        float l = -__logf(__fdividef(dnum, den * den));

        float ov = inside ? o : x;
        ldv = inside ? l : 0.f;
        ident[b * LDF + f] = ov;
        zout[b * LDP + 2 * f] = ov;
    }
    #pragma unroll
    for (int o = 16; o > 0; o >>= 1) ldv += __shfl_xor_sync(0xffffffffu, ldv, o);
    if (f_local == 0) atomicAdd(&lq[b], ldv);
}

// Materialize LT[m,d] = L[d,m] (unit diag) and UpT[perm[k], m] = Udense[m,k].
__global__ void build_lt_upt_kernel(const float* __restrict__ lower,
                                    const float* __restrict__ upper,
                                    const float* __restrict__ lu_ud,
                                    const int* __restrict__ perm,
                                    float* __restrict__ LT, float* __restrict__ UpT)
{
    int c = blockIdx.x * blockDim.x + threadIdx.x;
    int rr = blockIdx.y;
    if (c >= D_) return;
    if (blockIdx.z == 0) {
        int m = rr, d = c;
        float v = (m < d) ? lower[d * D_ + m] : ((m == d) ? 1.f : 0.f);
        LT[m * LDP + d] = v;
    } else {
        int k = rr, m = c;
        float v;
        if (m < k)       v = upper[m * D_ + k];
        else if (m == k) v = softplus_acc(lu_ud[k]) + 0.001f;
        else             v = 0.f;
        UpT[perm[k] * LDP + m] = v;
    }
}

// ---------------- padded SGEMM (ApT build only) ----------------
template<int BM, int BN, int TM, int TN, bool GUARDM, bool HASB>
__global__ void __launch_bounds__((BM/TM)*(BN/TN))
sgemm_pad(const float* __restrict__ A, const float* __restrict__ Bm,
          const float* __restrict__ bias, float* __restrict__ C,
          int M, int N, int K, int lda, int ldb, int ldc)
{
    constexpr int BK = 16;
    constexpr int TX = BN / TN, TY = BM / TM;
    constexpr int NT = TX * TY;
    __shared__ __align__(16) float As[BK][BM];
    __shared__ __align__(16) float Bs[BK][BN];
    int tid = threadIdx.x;
    int tx = tid % TX, ty = tid / TX;
    int m0 = blockIdx.y * BM, n0 = blockIdx.x * BN;

    float acc[TM][TN];
    #pragma unroll
    for (int i = 0; i < TM; i++)
        #pragma unroll
        for (int j = 0; j < TN; j++) acc[i][j] = 0.f;

    for (int k0 = 0; k0 < K; k0 += BK) {
        #pragma unroll
        for (int idx = tid; idx < BM * 4; idx += NT) {
            int m = idx >> 2, k4 = (idx & 3) << 2;
            int gm = m0 + m;
            float4 v = make_float4(0.f, 0.f, 0.f, 0.f);
            if (!GUARDM || gm < M)
                v = *reinterpret_cast<const float4*>(&A[gm * lda + k0 + k4]);
            As[k4 + 0][m] = v.x; As[k4 + 1][m] = v.y;
            As[k4 + 2][m] = v.z; As[k4 + 3][m] = v.w;
        }
        #pragma unroll
        for (int idx = tid; idx < BN * 4; idx += NT) {
            int k = idx / (BN / 4), n4 = (idx % (BN / 4)) << 2;
            float4 v = *reinterpret_cast<const float4*>(&Bm[(k0 + k) * ldb + n0 + n4]);
            *reinterpret_cast<float4*>(&Bs[k][n4]) = v;
        }
        __syncthreads();
        #pragma unroll
        for (int kk = 0; kk < BK; kk++) {
            float a[TM], b[TN];
            #pragma unroll
            for (int i = 0; i < TM / 4; i++)
                *reinterpret_cast<float4*>(&a[4 * i]) =
                    *reinterpret_cast<const float4*>(&As[kk][ty * TM + 4 * i]);
            #pragma unroll
            for (int j = 0; j < TN / 4; j++)
                *reinterpret_cast<float4*>(&b[4 * j]) =
                    *reinterpret_cast<const float4*>(&Bs[kk][tx * TN + 4 * j]);
            #pragma unroll
            for (int i = 0; i < TM; i++)
                #pragma unroll
                for (int j = 0; j < TN; j++)
                    acc[i][j] = fmaf(a[i], b[j], acc[i][j]);
        }
        __syncthreads();
    }
    #pragma unroll
    for (int i = 0; i < TM; i++) {
        int gm = m0 + ty * TM + i;
        if (!GUARDM || gm < M) {
            #pragma unroll
            for (int j = 0; j < TN; j++) {
                int gn = n0 + tx * TN + j;
                if (gn < N) {
                    float bv = HASB ? bias[gn] : 0.f;
                    C[gm * ldc + gn] = acc[i][j] + bv;
                }
            }
        }
    }
}

// ---------------- tf32 tensor-core big GEMM: zn = src @ ApT + bias ----------
__global__ void __launch_bounds__(256)
lu_gemm_tc(const float* __restrict__ src, const float* __restrict__ ApT,
           const float* __restrict__ bias, float* __restrict__ C)
{
    __shared__ __align__(16) float As[128][20];
    __shared__ __align__(16) float Bs[16][72];

    int tid  = threadIdx.x;
    int warp = tid >> 5, lane = tid & 31;
    int mwarp = (warp & 3) * 32;
    int nwarp = (warp >> 2) * 32;
    int m0 = blockIdx.y * 128;
    int n0 = blockIdx.x * 64;
    int g = lane >> 2, t4 = lane & 3;

    float c[2][4][4];
    #pragma unroll
    for (int i = 0; i < 2; i++)
        #pragma unroll
        for (int j = 0; j < 4; j++)
            c[i][j][0] = c[i][j][1] = c[i][j][2] = c[i][j][3] = 0.f;

    for (int kc = 0; kc < LDP; kc += 16) {
        __syncthreads();
        #pragma unroll
        for (int i = 0; i < 2; i++) {
            int idx = tid + i * 256;
            int r = idx >> 2, c4 = (idx & 3) << 2;
            float4 v = *reinterpret_cast<const float4*>(&src[(m0 + r) * LDP + kc + c4]);
            v.x = __uint_as_float(f2tf32(v.x));
            v.y = __uint_as_float(f2tf32(v.y));
            v.z = __uint_as_float(f2tf32(v.z));
            v.w = __uint_as_float(f2tf32(v.w));
            *reinterpret_cast<float4*>(&As[r][c4]) = v;
        }
        {
            int r = tid >> 4, c4 = (tid & 15) << 2;
            float4 v = *reinterpret_cast<const float4*>(&ApT[(kc + r) * LDP + n0 + c4]);
            v.x = __uint_as_float(f2tf32(v.x));
            v.y = __uint_as_float(f2tf32(v.y));
            v.z = __uint_as_float(f2tf32(v.z));
            v.w = __uint_as_float(f2tf32(v.w));
            *reinterpret_cast<float4*>(&Bs[r][c4]) = v;
        }
        __syncthreads();
        #pragma unroll
        for (int k8 = 0; k8 < 16; k8 += 8) {
            #pragma unroll
            for (int mf = 0; mf < 2; mf++) {
                int mb = mwarp + mf * 16;
                unsigned a0 = __float_as_uint(As[mb + g][k8 + t4]);
                unsigned a1 = __float_as_uint(As[mb + g + 8][k8 + t4]);
                unsigned a2 = __float_as_uint(As[mb + g][k8 + t4 + 4]);
                unsigned a3 = __float_as_uint(As[mb + g + 8][k8 + t4 + 4]);
                #pragma unroll
                for (int nf = 0; nf < 4; nf++) {
                    unsigned b0r = __float_as_uint(Bs[k8 + t4][nwarp + nf * 8 + g]);
                    unsigned b1r = __float_as_uint(Bs[k8 + t4 + 4][nwarp + nf * 8 + g]);
                    mma_tf32(c[mf][nf], a0, a1, a2, a3, b0r, b1r);
                }
            }
        }
    }

    #pragma unroll
    for (int mf = 0; mf < 2; mf++) {
        int r0 = m0 + mwarp + mf * 16 + g;
        int r1 = r0 + 8;
        #pragma unroll
        for (int nf = 0; nf < 4; nf++) {
            int cA = n0 + nwarp + nf * 8 + t4 * 2;
            int cB = cA + 1;
            if (cA < D_) {
                C[r0 * LDP + cA] = c[mf][nf][0] + bias[cA];
                C[r1 * LDP + cA] = c[mf][nf][2] + bias[cA];
            }
            if (cB < D_) {
                C[r0 * LDP + cB] = c[mf][nf][1] + bias[cB];
                C[r1 * LDP + cB] = c[mf][nf][3] + bias[cB];
            }
        }
    }
}

// ---------------- fused tf32 resnet: t = resnet(ident) per 32-row block ------
// Block: 32 batch rows, 256 thr = 8 warps (2m x 4n), warp tile 16x32, N=128.
__global__ void __launch_bounds__(256)
resnet_fused(const float* __restrict__ ident, const float* __restrict__ Wip,
             const float* __restrict__ bi, const float* __restrict__ Wb,
             const float* __restrict__ bb, float* __restrict__ tout)
{
    extern __shared__ float smf[];
    float (*Ts)[132] = reinterpret_cast<float(*)[132]>(smf);                  // 32x132
    float (*Rs)[132] = reinterpret_cast<float(*)[132]>(smf + 32 * 132);       // 32x132
    float (*Ws)[136] = reinterpret_cast<float(*)[136]>(smf + 64 * 132);       // 32x136
    float (*As)[36]  = reinterpret_cast<float(*)[36]>(smf + 64 * 132 + 32 * 136); // 32x36

    int tid = threadIdx.x, warp = tid >> 5, lane = tid & 31;
    int mw = (warp & 1) * 16;
    int nw = (warp >> 1) * 32;
    int m0 = blockIdx.x * 32;
    int g = lane >> 2, t4 = lane & 3;

    float c[4][4];

    // ---- phase 1: t = ident @ Wip + bi, K = 288 ----
    #pragma unroll
    for (int i = 0; i < 4; i++) c[i][0] = c[i][1] = c[i][2] = c[i][3] = 0.f;

    for (int kc = 0; kc < 288; kc += 32) {
        __syncthreads();
        {   // A chunk 32x32 (8 float4 per row)
            int r = tid >> 3, c4 = (tid & 7) << 2;
            float4 v = *reinterpret_cast<const float4*>(&ident[(m0 + r) * LDF + kc + c4]);
            As[r][c4 + 0] = __uint_as_float(f2tf32(v.x));
            As[r][c4 + 1] = __uint_as_float(f2tf32(v.y));
            As[r][c4 + 2] = __uint_as_float(f2tf32(v.z));
            As[r][c4 + 3] = __uint_as_float(f2tf32(v.w));
        }
        #pragma unroll
        for (int i = 0; i < 4; i++) {   // B chunk 32x128 (32 float4 per row)
            int idx = tid + i * 256;
            int r = idx >> 5, c4 = (idx & 31) << 2;
            float4 v = *reinterpret_cast<const float4*>(&Wip[(kc + r) * H_ + c4]);
            Ws[r][c4 + 0] = __uint_as_float(f2tf32(v.x));
            Ws[r][c4 + 1] = __uint_as_float(f2tf32(v.y));
            Ws[r][c4 + 2] = __uint_as_float(f2tf32(v.z));
            Ws[r][c4 + 3] = __uint_as_float(f2tf32(v.w));
        }
        __syncthreads();
        #pragma unroll
        for (int k8 = 0; k8 < 32; k8 += 8) {
            unsigned a0 = __float_as_uint(As[mw + g][k8 + t4]);
            unsigned a1 = __float_as_uint(As[mw + g + 8][k8 + t4]);
            unsigned a2 = __float_as_uint(As[mw + g][k8 + t4 + 4]);
            unsigned a3 = __float_as_uint(As[mw + g + 8][k8 + t4 + 4]);
            #pragma unroll
            for (int nf = 0; nf < 4; nf++) {
                unsigned b0r = __float_as_uint(Ws[k8 + t4][nw + nf * 8 + g]);
                unsigned b1r = __float_as_uint(Ws[k8 + t4 + 4][nw + nf * 8 + g]);
                mma_tf32(c[nf], a0, a1, a2, a3, b0r, b1r);
            }
        }
    }
    {   // epilogue 1 -> Ts
        int r0 = mw + g, r1 = r0 + 8;
        #pragma unroll
        for (int nf = 0; nf < 4; nf++) {
            int cA = nw + nf * 8 + t4 * 2, cB = cA + 1;
            Ts[r0][cA] = c[nf][0] + bi[cA];
            Ts[r0][cB] = c[nf][1] + bi[cB];
            Ts[r1][cA] = c[nf][2] + bi[cA];
            Ts[r1][cB] = c[nf][3] + bi[cB];
        }
    }

    // ---- phases 2-5: residual blocks ----
    #pragma unroll 1
    for (int j = 0; j < 4; j++) {
        float (*S)[132] = (j & 1) ? Rs : Ts;
        const float* W  = Wb + j * H_ * H_;
        const float* bv = bb + j * H_;
        #pragma unroll
        for (int i = 0; i < 4; i++) c[i][0] = c[i][1] = c[i][2] = c[i][3] = 0.f;

        for (int kc = 0; kc < H_; kc += 32) {
            __syncthreads();
            #pragma unroll
            for (int i = 0; i < 4; i++) {
                int idx = tid + i * 256;
                int r = idx >> 5, c4 = (idx & 31) << 2;
                float4 v = *reinterpret_cast<const float4*>(&W[(kc + r) * H_ + c4]);
                Ws[r][c4 + 0] = __uint_as_float(f2tf32(v.x));
                Ws[r][c4 + 1] = __uint_as_float(f2tf32(v.y));
                Ws[r][c4 + 2] = __uint_as_float(f2tf32(v.z));
                Ws[r][c4 + 3] = __uint_as_float(f2tf32(v.w));
            }
            __syncthreads();
            #pragma unroll
            for (int k8 = 0; k8 < 32; k8 += 8) {
                int k = kc + k8;
                unsigned a0 = f2tf32(fmaxf(S[mw + g][k + t4], 0.f));
                unsigned a1 = f2tf32(fmaxf(S[mw + g + 8][k + t4], 0.f));
                unsigned a2 = f2tf32(fmaxf(S[mw + g][k + t4 + 4], 0.f));
                unsigned a3 = f2tf32(fmaxf(S[mw + g + 8][k + t4 + 4], 0.f));
                #pragma unroll
                for (int nf = 0; nf < 4; nf++) {
                    unsigned b0r = __float_as_uint(Ws[k8 + t4][nw + nf * 8 + g]);
                    unsigned b1r = __float_as_uint(Ws[k8 + t4 + 4][nw + nf * 8 + g]);
                    mma_tf32(c[nf], a0, a1, a2, a3, b0r, b1r);
                }
            }
        }
        {   // epilogue: same thread owns the same C cells across phases
            int r0 = mw + g, r1 = r0 + 8;
            #pragma unroll
            for (int nf = 0; nf < 4; nf++) {
                int cA = nw + nf * 8 + t4 * 2, cB = cA + 1;
                if (j & 1) {
                    Ts[r0][cA] += c[nf][0] + bv[cA];
                    Ts[r0][cB] += c[nf][1] + bv[cB];
                    Ts[r1][cA] += c[nf][2] + bv[cA];
                    Ts[r1][cB] += c[nf][3] + bv[cB];
                } else {
                    Rs[r0][cA] = c[nf][0] + bv[cA];
                    Rs[r0][cB] = c[nf][1] + bv[cB];
                    Rs[r1][cA] = c[nf][2] + bv[cA];
                    Rs[r1][cB] = c[nf][3] + bv[cB];
                }
            }
        }
    }
    __syncthreads();
    // FIXED writeback: 32 rows x 128 cols = 1024 float4, 32 f4/row -> >>5, &31
    #pragma unroll
    for (int i = 0; i < 4; i++) {
        int idx = tid + i * 256;
        int r = idx >> 5, c4 = (idx & 31) << 2;
        *reinterpret_cast<float4*>(&tout[(m0 + r) * H_ + c4]) =
            *reinterpret_cast<const float4*>(&Ts[r][c4]);
    }
}

// ---------------- tf32 tensor-core fused Wo GEMM + conditional spline ----------
__global__ void __launch_bounds__(256)
wo_spline_tc(const float* __restrict__ tmat, const float* __restrict__ Wop,
             const float* __restrict__ bo, const float* __restrict__ zn,
             float* __restrict__ zout, float* __restrict__ lq)
{
    extern __shared__ float sm[];
    float (*As)[36]  = reinterpret_cast<float(*)[36]>(sm);            // 64x36
    float (*Bs)[200] = reinterpret_cast<float(*)[200]>(sm + 64 * 36); // 32x200
    float (*Cs)[200] = reinterpret_cast<float(*)[200]>(sm);           // 64x200 (aliases)
    __shared__ float bos[192];

    int tid  = threadIdx.x;
    int warp = tid >> 5, lane = tid & 31;
    int mw = (warp & 3) * 16;
    int nw = (warp >> 2) * 96;
    int b0 = blockIdx.y * 64;
    int f0 = blockIdx.x * 8;
    int n0 = blockIdx.x * 192;

    for (int i = tid; i < 192; i += 256) {
        int ff = i / 24, oo = i % 24;
        int col = (f0 + ff) * 23 + oo;
        bos[i] = (oo < 23 && col < OUT_) ? bo[col] : 0.f;
    }

    float c[12][4];
    #pragma unroll
    for (int i = 0; i < 12; i++) { c[i][0] = c[i][1] = c[i][2] = c[i][3] = 0.f; }

    int g = lane >> 2, t4 = lane & 3;

    for (int kc = 0; kc < H_; kc += 32) {
        __syncthreads();
        #pragma unroll
        for (int i = 0; i < 2; i++) {
            int idx = tid + i * 256;
            int r = idx >> 3, c4 = (idx & 7) << 2;
            float4 v = *reinterpret_cast<const float4*>(&tmat[(b0 + r) * H_ + kc + c4]);
            As[r][c4 + 0] = __uint_as_float(f2tf32(v.x));
            As[r][c4 + 1] = __uint_as_float(f2tf32(v.y));
            As[r][c4 + 2] = __uint_as_float(f2tf32(v.z));
            As[r][c4 + 3] = __uint_as_float(f2tf32(v.w));
        }
        #pragma unroll
        for (int i = 0; i < 6; i++) {
            int idx = tid + i * 256;
            int r = idx / 48, c4 = (idx % 48) << 2;
            float4 v = *reinterpret_cast<const float4*>(&Wop[(kc + r) * LDW + n0 + c4]);
            Bs[r][c4 + 0] = __uint_as_float(f2tf32(v.x));
            Bs[r][c4 + 1] = __uint_as_float(f2tf32(v.y));
            Bs[r][c4 + 2] = __uint_as_float(f2tf32(v.z));
            Bs[r][c4 + 3] = __uint_as_float(f2tf32(v.w));
        }
        __syncthreads();
        #pragma unroll
        for (int k8 = 0; k8 < 32; k8 += 8) {
            unsigned a0 = __float_as_uint(As[mw + g][k8 + t4]);
            unsigned a1 = __float_as_uint(As[mw + g + 8][k8 + t4]);
            unsigned a2 = __float_as_uint(As[mw + g][k8 + t4 + 4]);
            unsigned a3 = __float_as_uint(As[mw + g + 8][k8 + t4 + 4]);
            #pragma unroll
            for (int nt = 0; nt < 12; nt++) {
                unsigned b0r = __float_as_uint(Bs[k8 + t4][nw + nt * 8 + g]);
                unsigned b1r = __float_as_uint(Bs[k8 + t4 + 4][nw + nt * 8 + g]);
                mma_tf32(c[nt], a0, a1, a2, a3, b0r, b1r);
            }
        }
    }
    __syncthreads();
    {
        int t2 = (lane & 3) * 2;
        int r0 = mw + g, r1 = r0 + 8;
        #pragma unroll
        for (int nt = 0; nt < 12; nt++) {
            int col0 = nw + nt * 8 + t2;
            int fa = col0 / 24, oa = col0 % 24;
            Cs[r0][fa * 25 + oa] = c[nt][0];
            Cs[r1][fa * 25 + oa] = c[nt][2];
            int col1 = col0 + 1;
            int fb = col1 / 24, ob = col1 % 24;
            Cs[r0][fb * 25 + ob] = c[nt][1];
            Cs[r1][fb * 25 + ob] = c[nt][3];
        }
    }
    __syncthreads();

    int f_local = tid & 7;
    int b_local = tid >> 3;
    int f = f0 + f_local;
    const float scale = 0.08838834764831845f;
    float ld0 = 0.f, ld1 = 0.f;

    if (f < F_) {
        const float* Bo = bos + f_local * 24;
        {
            const float* P = Cs[b_local] + f_local * 25;
            float uw[8], uh[8], ud7[7];
            #pragma unroll
            for (int o = 0; o < 8; o++) {
                uw[o] = (P[o] + Bo[o]) * scale;
                uh[o] = (P[8 + o] + Bo[8 + o]) * scale;
            }
            #pragma unroll
            for (int o = 0; o < 7; o++) ud7[o] = P[16 + o] + Bo[16 + o];
            int b = b0 + b_local;
            float x = zn[b * LDP + 2 * f + 1];
            float o, l;
            rqs_fast(x, uw, uh, ud7, o, l);
            zout[b * LDP + 2 * f + 1] = o;
            ld0 = l;
        }
        {
            const float* P = Cs[b_local + 32] + f_local * 25;
            float uw[8], uh[8], ud7[7];
            #pragma unroll
            for (int o = 0; o < 8; o++) {
                uw[o] = (P[o] + Bo[o]) * scale;
                uh[o] = (P[8 + o] + Bo[8 + o]) * scale;
            }
            #pragma unroll
            for (int o = 0; o < 7; o++) ud7[o] = P[16 + o] + Bo[16 + o];
            int b = b0 + b_local + 32;
            float x = zn[b * LDP + 2 * f + 1];
            float o, l;
            rqs_fast(x, uw, uh, ud7, o, l);
            zout[b * LDP + 2 * f + 1] = o;
            ld1 = l;
        }
    }
    #pragma unroll
    for (int o = 4; o > 0; o >>= 1) {
        ld0 += __shfl_xor_sync(0xffffffffu, ld0, o);
        ld1 += __shfl_xor_sync(0xffffffffu, ld1, o);
    }
    if (f_local == 0) {
        atomicAdd(&lq[b0 + b_local], ld0);
        atomicAdd(&lq[b0 + b_local + 32], ld1);
    }
}

__global__ void final_kernel(const float* __restrict__ z, const float* __restrict__ loc,
                             const float* __restrict__ lsc, const float* __restrict__ lq,
                             const float* __restrict__ slog, float* __restrict__ out)
{
    int b = blockIdx.x;
    float s = 0.f;
    for (int d = threadIdx.x; d < D_; d += blockDim.x) {
        float inv = __expf(-lsc[d]);
        float u = (z[b * LDP + d] - loc[d]) * inv;
        s += lsc[d] + 0.5f * u * u;
    }
    s = block_reduce_sum(s);
    if (threadIdx.x == 0) {
        const float c = 0.5f * 550.f * 1.8378770664093453f;
        out[b] = lq[b] + slog[0] + slog[1] + slog[2] - c - s;
    }
}

// ---------------- launch ----------------
extern "C" void kernel_launch(void* const* d_in, const int* in_sizes, int n_in,
                              void* d_out, int out_size)
{
    (void)in_sizes; (void)n_in; (void)out_size;
    const float* x      = (const float*)d_in[0];
    const float* loc    = (const float*)d_in[1];
    const float* lsc    = (const float*)d_in[2];
    const float* Wi     = (const float*)d_in[3];
    const float* bi     = (const float*)d_in[4];
    const float* Wb     = (const float*)d_in[5];
    const float* bb     = (const float*)d_in[6];
    const float* Wo     = (const float*)d_in[7];
    const float* bo     = (const float*)d_in[8];
    const float* uw_u   = (const float*)d_in[9];
    const float* uh_u   = (const float*)d_in[10];
    const float* ud_u   = (const float*)d_in[11];
    const float* lower  = (const float*)d_in[12];
    const float* upper  = (const float*)d_in[13];
    const float* lu_ud  = (const float*)d_in[14];
    const float* lu_b   = (const float*)d_in[15];
    const int*   perms  = (const int*)d_in[16];
    float* outp = (float*)d_out;

    float *z, *zn, *LT, *UpT, *ApT, *ident, *t, *lq, *slog, *kn, *wop, *wip;
    cudaGetSymbolAddress((void**)&z,     g_z);
    cudaGetSymbolAddress((void**)&zn,    g_zn);
    cudaGetSymbolAddress((void**)&LT,    g_LT);
    cudaGetSymbolAddress((void**)&UpT,   g_UpT);
    cudaGetSymbolAddress((void**)&ApT,   g_ApT);
    cudaGetSymbolAddress((void**)&ident, g_id);
    cudaGetSymbolAddress((void**)&t,     g_t);
    cudaGetSymbolAddress((void**)&lq,    g_lq);
    cudaGetSymbolAddress((void**)&slog,  g_slog);
    cudaGetSymbolAddress((void**)&kn,    g_kn);
    cudaGetSymbolAddress((void**)&wop,   g_Wop);
    cudaGetSymbolAddress((void**)&wip,   g_Wip);

    constexpr int RESNET_SMEM = (64 * 132 + 32 * 136 + 32 * 36) * 4;  // 55808 B
    static bool attr_set = false;
    if (!attr_set) {
        cudaFuncSetAttribute(wo_spline_tc,
                             cudaFuncAttributeMaxDynamicSharedMemorySize, 64 * 200 * 4);
        cudaFuncSetAttribute(resnet_fused,
                             cudaFuncAttributeMaxDynamicSharedMemorySize, RESNET_SMEM);
        attr_set = true;
    }

    auto big_gemm = [&](const float* src, const float* bias) {
        lu_gemm_tc<<<dim3((D_ + 63) / 64, B_ / 128), 256>>>(src, ApT, bias, zn);
    };
    auto apt_gemm = [&]() {
        sgemm_pad<64, 64, 4, 4, true, false>
            <<<dim3((D_ + 63) / 64, (D_ + 63) / 64), 256>>>(
                UpT, LT, nullptr, ApT, D_, D_, LDP, LDP, LDP, LDP);
    };

    auto resnet_and_tail = [&](int i) {
        ident_knots_kernel<<<(F_ + 255) / 256, 256>>>(
            uw_u + i * F_ * 8, uh_u + i * F_ * 8, ud_u + i * F_ * 7, kn);
        ident_eval_kernel<<<dim3((F_ + 31) / 32, B_ / 8), 256>>>(
            zn, kn, ident, z, lq);
        prep_wip_kernel<<<(288 * H_ + 255) / 256, 256>>>(Wi + i * F_ * H_, wip);
        prep_wop_kernel<<<(H_ * LDW + 255) / 256, 256>>>(Wo + i * H_ * OUT_, wop);
        resnet_fused<<<B_ / 32, 256, RESNET_SMEM>>>(
            ident, wip, bi + i * H_, Wb + i * 4 * H_ * H_, bb + i * 4 * H_, t);
        wo_spline_tc<<<dim3((F_ + 7) / 8, B_ / 64), 256, 64 * 200 * 4>>>(
            t, wop, bo + i * OUT_, zn, z, lq);
    };

    // ---- layer 2 prelude, ordered so the TC BIG GEMM is launch index 3 (ncu) ----
    build_lt_upt_kernel<<<dim3((D_ + 255) / 256, D_, 2), 256>>>(          // 0
        lower + 2 * D_ * D_, upper + 2 * D_ * D_, lu_ud + 2 * D_, perms + 2 * D_, LT, UpT);
    apt_gemm();                                                            // 1
    copy_pad_kernel<<<(B_ * D_ + 255) / 256, 256>>>(x, z);                 // 2
    big_gemm(z, lu_b + 2 * D_);                                            // 3 <- profiled
    zero_kernel<<<(B_ + 255) / 256, 256>>>(lq, B_);                        // 4
    sumlog_kernel<<<3, 256>>>(lu_ud, slog);                                // 5
    resnet_and_tail(2);

    for (int i = 1; i >= 0; i--) {
        build_lt_upt_kernel<<<dim3((D_ + 255) / 256, D_, 2), 256>>>(
            lower + i * D_ * D_, upper + i * D_ * D_,
            lu_ud + i * D_, perms + i * D_, LT, UpT);
        apt_gemm();
        big_gemm(z, lu_b + i * D_);
        resnet_and_tail(i);
    }

    final_kernel<<<B_, 256>>>(z, loc, lsc, lq, slog, outp);
}